// round 10
// baseline (speedup 1.0000x reference)
#include <cuda_runtime.h>
#include <cuda_bf16.h>
#include <math.h>
#include <stdint.h>

#define EPS 1e-8f
#define TR  (1.0f/1024.0f)
#define TC  (1.0f/256.0f)
#define SEG 4194304            // 16*1024*256

// ---------------- scratch (device globals; no allocation) ----------------
__device__ __align__(16) __nv_bfloat16 g_xh[8388608];   // normalized X hi
__device__ __align__(16) __nv_bfloat16 g_xl[8388608];   // normalized X lo
__device__ __align__(16) __nv_bfloat16 g_Mh[8388608];   // M = exp(sim/tau) hi
__device__ __align__(16) __nv_bfloat16 g_Ml[8388608];   // M lo
__device__ __align__(16) __nv_bfloat16 g_pbh[131072];   // proto normalized hi [2][k][d]
__device__ __align__(16) __nv_bfloat16 g_pbl[131072];
__device__ __align__(16) __nv_bfloat16 g_pth[131072];   // proto^T hi [2][d][k]
__device__ __align__(16) __nv_bfloat16 g_ptl[131072];
__device__ __align__(16) __nv_bfloat16 g_bvh[2097152];  // v-scaled proto^T hi [32][d][k]
__device__ __align__(16) __nv_bfloat16 g_bvl[2097152];
__device__ float g_u[32768];
__device__ float g_v[8192];
__device__ float g_csum2[8192];
__device__ float g_bs[32];

// exp(20*s) via 2^y, FFMA-only
__device__ __forceinline__ float exp20(float s) {
    float y  = s * 28.853900817779268f;
    float fl = floorf(y);
    float f  = y - fl;
    float p = 1.5252733804059840e-05f;
    p = fmaf(p, f, 1.5403530393381609e-04f);
    p = fmaf(p, f, 1.3333558146428443e-03f);
    p = fmaf(p, f, 9.6181291076284772e-03f);
    p = fmaf(p, f, 5.5504108664821580e-02f);
    p = fmaf(p, f, 2.4022650695910071e-01f);
    p = fmaf(p, f, 6.9314718055994531e-01f);
    p = fmaf(p, f, 1.0f);
    int e = (int)fl + 127;
    return p * __int_as_float(e << 23);
}

__device__ __forceinline__ uint32_t smem_u32(const void* p) {
    uint32_t a;
    asm("{ .reg .u64 t; cvta.to.shared.u64 t, %1; cvt.u32.u64 %0, t; }" : "=r"(a) : "l"(p));
    return a;
}
__device__ __forceinline__ void ldmx4(uint32_t* r, uint32_t addr) {
    asm volatile("ldmatrix.sync.aligned.m8n8.x4.shared.b16 {%0,%1,%2,%3}, [%4];"
                 : "=r"(r[0]), "=r"(r[1]), "=r"(r[2]), "=r"(r[3]) : "r"(addr));
}
__device__ __forceinline__ void mma16816(float* d, const uint32_t* a, const uint32_t* b) {
    asm volatile("mma.sync.aligned.m16n8k16.row.col.f32.bf16.bf16.f32 "
                 "{%0,%1,%2,%3}, {%4,%5,%6,%7}, {%8,%9}, {%0,%1,%2,%3};"
                 : "+f"(d[0]), "+f"(d[1]), "+f"(d[2]), "+f"(d[3])
                 : "r"(a[0]), "r"(a[1]), "r"(a[2]), "r"(a[3]), "r"(b[0]), "r"(b[1]));
}
__device__ __forceinline__ uint32_t pack_bf2(__nv_bfloat16 lo, __nv_bfloat16 hi) {
    __nv_bfloat162 t; t.x = lo; t.y = hi;
    uint32_t r; memcpy(&r, &t, 4); return r;
}
__device__ __forceinline__ void split_bf(float x, __nv_bfloat16& h, __nv_bfloat16& l) {
    h = __float2bfloat16_rn(x);
    l = __float2bfloat16_rn(x - __bfloat162float(h));
}
__device__ __forceinline__ void cp_async16(uint32_t smem, const void* g) {
    asm volatile("cp.async.cg.shared.global [%0], [%1], 16;" :: "r"(smem), "l"(g));
}
#define CP_COMMIT() asm volatile("cp.async.commit_group;" ::: "memory")
#define CP_WAIT0()  asm volatile("cp.async.wait_group 0;" ::: "memory")
#define CP_WAIT1()  asm volatile("cp.async.wait_group 1;" ::: "memory")
__device__ __forceinline__ uint32_t mapa_u32(uint32_t a, uint32_t r) {
    uint32_t d;
    asm("mapa.shared::cluster.u32 %0, %1, %2;" : "=r"(d) : "r"(a), "r"(r));
    return d;
}
__device__ __forceinline__ float ld_cluster_f32(uint32_t a) {
    float v;
    asm volatile("ld.shared::cluster.b32 %0, [%1];" : "=f"(v) : "r"(a));
    return v;
}
#define CLUSTER_SYNC() do { \
    asm volatile("barrier.cluster.arrive.aligned;" ::: "memory"); \
    asm volatile("barrier.cluster.wait.aligned;"   ::: "memory"); \
} while (0)

// ---------------- setup: zero + normalize/split/transpose protos ----------------
__global__ void k_proto(const float* __restrict__ p_rgb, const float* __restrict__ p_sn) {
    int gt = blockIdx.x * blockDim.x + threadIdx.x;
    if (gt < 8192) g_csum2[gt] = 0.f;
    if (gt < 32)   g_bs[gt] = 0.f;

    int warp = gt >> 5;
    int lane = threadIdx.x & 31;
    int mod = warp >> 8, row = warp & 255;
    const float* src = (mod ? p_sn : p_rgb) + row * 256;
    float v[8], s = 0.f;
#pragma unroll
    for (int j = 0; j < 8; j++) { v[j] = src[lane + 32 * j]; s += v[j] * v[j]; }
#pragma unroll
    for (int o = 16; o; o >>= 1) s += __shfl_xor_sync(0xffffffffu, s, o);
    float inv = 1.0f / (sqrtf(s) + EPS);
    int base = mod * 65536;
#pragma unroll
    for (int j = 0; j < 8; j++) {
        int col = lane + 32 * j;
        float val = v[j] * inv;
        __nv_bfloat16 h, l;
        split_bf(val, h, l);
        g_pbh[base + row * 256 + col] = h;
        g_pbl[base + row * 256 + col] = l;
        g_pth[base + col * 256 + row] = h;
        g_ptl[base + col * 256 + row] = l;
    }
}

// ---------------- normalize + split X ----------------
__global__ void k_xsplit(const float* __restrict__ f_rgb, const float* __restrict__ f_sn) {
    int warp = (blockIdx.x * blockDim.x + threadIdx.x) >> 5;
    int lane = threadIdx.x & 31;
    int mod = warp >> 14, lrow = warp & 16383;
    const float* src = (mod ? f_sn : f_rgb) + (size_t)lrow * 256;
    float v[8], s = 0.f;
#pragma unroll
    for (int j = 0; j < 8; j++) { v[j] = src[lane + 32 * j]; s += v[j] * v[j]; }
#pragma unroll
    for (int o = 16; o; o >>= 1) s += __shfl_xor_sync(0xffffffffu, s, o);
    float inv = 1.0f / (sqrtf(s) + EPS);
    size_t base = (size_t)warp * 256;
#pragma unroll
    for (int j = 0; j < 8; j++) {
        float val = v[j] * inv;
        __nv_bfloat16 h, l;
        split_bf(val, h, l);
        g_xh[base + lane + 32 * j] = h;
        g_xl[base + lane + 32 * j] = l;
    }
}

// ---------------- pure-load GEMM machinery ----------------
#define STG   40960          // per stage: Ah 10240 | Al 10240 | Bh 10240 | Bl 10240
#define GSMEM 81920

#define DO_MMA(sb) do { \
    _Pragma("unroll") \
    for (int ks = 0; ks < 2; ks++) { \
        uint32_t kb = ks * 32; \
        uint32_t aH[2][4], aL[2][4]; \
        ldmx4(aH[0], (sb) + a_off + kb); \
        ldmx4(aH[1], (sb) + a_off + 16 * 80 + kb); \
        ldmx4(aL[0], (sb) + 10240 + a_off + kb); \
        ldmx4(aL[1], (sb) + 10240 + a_off + 16 * 80 + kb); \
        _Pragma("unroll") \
        for (int np = 0; np < 4; np++) { \
            uint32_t bo = b_off + (uint32_t)np * 16 * 80 + kb; \
            uint32_t bH[4], bL[4]; \
            ldmx4(bH, (sb) + 20480 + bo); \
            ldmx4(bL, (sb) + 30720 + bo); \
            _Pragma("unroll") \
            for (int tm = 0; tm < 2; tm++) { \
                mma16816(acc[tm][2 * np],     aH[tm], bH); \
                mma16816(acc[tm][2 * np],     aH[tm], bL); \
                mma16816(acc[tm][2 * np],     aL[tm], bH); \
                mma16816(acc[tm][2 * np + 1], aH[tm], bH + 2); \
                mma16816(acc[tm][2 * np + 1], aH[tm], bL + 2); \
                mma16816(acc[tm][2 * np + 1], aL[tm], bH + 2); \
            } \
        } \
    } \
} while (0)

// load one 32-k chunk (all 4 parts) via cp.async; parts[i>>1] constant per unrolled i
#define LOAD_CHUNK(dd, stg) do { \
    _Pragma("unroll") \
    for (int i = 0; i < 8; i++) { \
        int rem = t + 256 * (i & 1); \
        int row = rem >> 2, c16 = rem & 3; \
        cp_async16(smb + (stg) + (i >> 1) * 10240 + row * 80 + c16 * 16, \
                   parts[i >> 1] + (size_t)row * 256 + (dd) + c16 * 8); \
    } \
    CP_COMMIT(); \
} while (0)

#define GEMM_PIPELINE() do { \
    LOAD_CHUNK(0, 0); \
    for (int c = 0; c < 8; c++) { \
        int buf = c & 1; \
        if (c < 7) { LOAD_CHUNK((c + 1) * 32, (buf ^ 1) * STG); CP_WAIT1(); } \
        else       { CP_WAIT0(); } \
        __syncthreads(); \
        uint32_t sb = smb + buf * STG; \
        DO_MMA(sb); \
        __syncthreads(); \
    } \
} while (0)

// ---------------- GEMM1: sim = Xn @ Pn^T ; Mh/Ml = split(exp(20*sim)) ----------------
__global__ __launch_bounds__(256, 2)
void k_gemm_sim(float* __restrict__ out) {
    extern __shared__ char dsm[];
    int t = threadIdx.x, l = t & 31, w = t >> 5;
    int wm = w >> 1, wn = w & 1;
    int bx = blockIdx.x;
    int row0 = (bx >> 1) * 128;
    int col0 = (bx & 1) * 128;
    int mod = row0 >> 14, lrow0 = row0 & 16383;

    const __nv_bfloat16* parts[4] = {
        g_xh + (size_t)row0 * 256,
        g_xl + (size_t)row0 * 256,
        g_pbh + mod * 65536 + (size_t)col0 * 256,
        g_pbl + mod * 65536 + (size_t)col0 * 256
    };
    uint32_t smb = smem_u32(dsm);
    uint32_t a_off = (uint32_t)(wm * 32 + (l & 7) + 8 * ((l >> 3) & 1)) * 80
                   + ((l >> 4) & 1) * 16;
    uint32_t b_off = (uint32_t)(wn * 64 + (l & 7) + 8 * ((l >> 4) & 1)) * 80
                   + ((l >> 3) & 1) * 16;

    float acc[2][8][4];
#pragma unroll
    for (int a = 0; a < 2; a++)
#pragma unroll
        for (int b = 0; b < 8; b++)
#pragma unroll
            for (int d = 0; d < 4; d++) acc[a][b][d] = 0.f;

    GEMM_PIPELINE();

    float* simb = out + (size_t)(4 + mod) * SEG;
    float psum = 0.f;
#pragma unroll
    for (int tm = 0; tm < 2; tm++) {
        int tr0 = wm * 32 + tm * 16 + (l >> 2);
        int r0 = row0 + tr0, r1 = r0 + 8;
        size_t lr0 = (size_t)(r0 & 16383) * 256, lr1 = (size_t)(r1 & 16383) * 256;
        size_t gr0 = (size_t)r0 * 256, gr1 = (size_t)r1 * 256;
#pragma unroll
        for (int nt = 0; nt < 8; nt++) {
            int col = col0 + wn * 64 + nt * 8 + 2 * (l & 3);
            float* d = acc[tm][nt];
            float2 s0 = {d[0], d[1]};
            float2 s1 = {d[2], d[3]};
            *(float2*)(simb + lr0 + col) = s0;
            *(float2*)(simb + lr1 + col) = s1;
            float2 e0 = {exp20(s0.x), exp20(s0.y)};
            float2 e1 = {exp20(s1.x), exp20(s1.y)};
            __nv_bfloat16 h0x, l0x, h0y, l0y, h1x, l1x, h1y, l1y;
            split_bf(e0.x, h0x, l0x); split_bf(e0.y, h0y, l0y);
            split_bf(e1.x, h1x, l1x); split_bf(e1.y, h1y, l1y);
            *(uint32_t*)(g_Mh + gr0 + col) = pack_bf2(h0x, h0y);
            *(uint32_t*)(g_Ml + gr0 + col) = pack_bf2(l0x, l0y);
            *(uint32_t*)(g_Mh + gr1 + col) = pack_bf2(h1x, h1y);
            *(uint32_t*)(g_Ml + gr1 + col) = pack_bf2(l1x, l1y);
            psum += (e0.x + e0.y) + (e1.x + e1.y);
        }
    }
#pragma unroll
    for (int o = 16; o; o >>= 1) psum += __shfl_xor_sync(0xffffffffu, psum, o);
    if (l == 0) atomicAdd(&g_bs[row0 >> 10], psum);
}

// ---------------- sinkhorn: cluster of 4 CTAs per slice; B' epilogue ----------------
#define SINK_SMEM 134144

__global__ void __launch_bounds__(256, 1) __cluster_dims__(4, 1, 1)
k_sinkhorn() {
    extern __shared__ char smraw[];
    __nv_bfloat16* sM = (__nv_bfloat16*)smraw;
    float* su   = (float*)(smraw + 131072);
    float* sv   = (float*)(smraw + 132096);
    float* scol = (float*)(smraw + 133120);
    int t = threadIdx.x, lane = t & 31, w = t >> 5;
    uint32_t rank;
    asm("mov.u32 %0, %%cluster_ctarank;" : "=r"(rank));
    int bm = blockIdx.x >> 2;
    uint32_t scol_a = smem_u32(scol);

    const uint4* src = (const uint4*)(g_Mh + (size_t)bm * 262144 + (size_t)rank * 65536);
    uint4* dstM = (uint4*)sM;
    for (int i = t; i < 8192; i += 256) dstM[i] = src[i];

    float u0 = 1.0f / (g_bs[bm] + EPS);
    if (t < 256) { su[t] = u0; sv[t] = 1.0f; scol[t] = 0.f; }
    __syncthreads();

    for (int it = 0; it < 5; it++) {
        float vr[8];
#pragma unroll
        for (int j = 0; j < 8; j++) vr[j] = sv[8 * lane + j];
        float c[8] = {0, 0, 0, 0, 0, 0, 0, 0};
        for (int rr = 0; rr < 32; rr += 2) {
            int row = w * 32 + rr;
            uint4 mv0 = *(const uint4*)(sM + row * 256 + 8 * lane);
            uint4 mv1 = *(const uint4*)(sM + (row + 1) * 256 + 8 * lane);
            float m0[8], m1[8];
            {
                float2 f;
                f = __bfloat1622float2(*(__nv_bfloat162*)&mv0.x); m0[0]=f.x; m0[1]=f.y;
                f = __bfloat1622float2(*(__nv_bfloat162*)&mv0.y); m0[2]=f.x; m0[3]=f.y;
                f = __bfloat1622float2(*(__nv_bfloat162*)&mv0.z); m0[4]=f.x; m0[5]=f.y;
                f = __bfloat1622float2(*(__nv_bfloat162*)&mv0.w); m0[6]=f.x; m0[7]=f.y;
                f = __bfloat1622float2(*(__nv_bfloat162*)&mv1.x); m1[0]=f.x; m1[1]=f.y;
                f = __bfloat1622float2(*(__nv_bfloat162*)&mv1.y); m1[2]=f.x; m1[3]=f.y;
                f = __bfloat1622float2(*(__nv_bfloat162*)&mv1.z); m1[4]=f.x; m1[5]=f.y;
                f = __bfloat1622float2(*(__nv_bfloat162*)&mv1.w); m1[6]=f.x; m1[7]=f.y;
            }
            float d0 = 0.f, d1 = 0.f;
#pragma unroll
            for (int j = 0; j < 8; j++) { d0 = fmaf(m0[j], vr[j], d0); d1 = fmaf(m1[j], vr[j], d1); }
#pragma unroll
            for (int o = 16; o; o >>= 1) {
                d0 += __shfl_xor_sync(0xffffffffu, d0, o);
                d1 += __shfl_xor_sync(0xffffffffu, d1, o);
            }
            float uu0 = su[row], uu1 = su[row + 1];
            float un0 = uu0 * TR / (uu0 * d0 + EPS);
            float un1 = uu1 * TR / (uu1 * d1 + EPS);
            if (lane == 0) { su[row] = un0; su[row + 1] = un1; }
#pragma unroll
            for (int j = 0; j < 8; j++)
                c[j] = fmaf(m0[j], un0, fmaf(m1[j], un1, c[j]));
        }
#pragma unroll
        for (int j = 0; j < 8; j++) atomicAdd(&scol[8 * lane + j], c[j]);
        CLUSTER_SYNC();
        float tot = 0.f;
        if (t < 256) {
#pragma unroll
            for (uint32_t r = 0; r < 4; r++)
                tot += ld_cluster_f32(mapa_u32(scol_a + 4 * t, r));
        }
        CLUSTER_SYNC();
        if (t < 256) {
            float v = sv[t];
            sv[t] = v * TC / (v * tot + EPS);
            scol[t] = 0.f;
        }
        __syncthreads();
    }
    if (rank == 0 && t < 256) g_v[bm * 256 + t] = sv[t];
    if (t < 256) g_u[bm * 1024 + rank * 256 + t] = su[t];

    // B' = diag(v) @ Pn, transposed layout [d][k], split to bf16 hi/lo
    {
        int mod = bm >> 4;
        const __nv_bfloat16* pth = g_pth + mod * 65536;
        const __nv_bfloat16* ptl = g_ptl + mod * 65536;
        __nv_bfloat16* bvh = g_bvh + (size_t)bm * 65536;
        __nv_bfloat16* bvl = g_bvl + (size_t)bm * 65536;
        int k = t;
        float vk = sv[k];
        for (int n = 0; n < 64; n++) {
            int d = (rank << 6) + n;
            float pv = __bfloat162float(pth[d * 256 + k]) + __bfloat162float(ptl[d * 256 + k]);
            float val = vk * pv;
            __nv_bfloat16 h, l;
            split_bf(val, h, l);
            bvh[d * 256 + k] = h;
            bvl[d * 256 + k] = l;
        }
    }
}

// ---------------- fused final+z: phase1 from Mh+Ml; phase2 pure-load GEMM ----------------
__global__ __launch_bounds__(256, 2)
void k_finalz(float* __restrict__ out) {
    extern __shared__ char dsm[];
    __shared__ float sv[256];
    __shared__ float sun[128];
    __shared__ float scol[256];

    int t = threadIdx.x, l = t & 31, w = t >> 5;
    int bx = blockIdx.x;
    int row0 = (bx >> 1) * 128;
    int col0 = (bx & 1) * 128;
    int primary = (bx & 1) == 0;
    int bm = row0 >> 10;
    int mod = row0 >> 14, lrow0 = row0 & 16383;
    float* ab = out + (size_t)(2 + mod) * SEG + (size_t)lrow0 * 256;

    if (t < 256) { sv[t] = g_v[bm * 256 + t]; scol[t] = 0.f; }
    __syncthreads();

    // ---- phase 1: un per row from (Mh+Ml); assign write + colsums (primary) ----
    {
        float vr[8];
#pragma unroll
        for (int j = 0; j < 8; j++) vr[j] = sv[8 * l + j];
        float c[8] = {0, 0, 0, 0, 0, 0, 0, 0};
        for (int rr = 0; rr < 16; rr += 2) {
            int lr = w * 16 + rr;
            size_t gr0 = (size_t)(row0 + lr) * 256 + 8 * l;
            size_t gr1 = gr0 + 256;
            uint4 h0 = *(const uint4*)(g_Mh + gr0), lo0 = *(const uint4*)(g_Ml + gr0);
            uint4 h1 = *(const uint4*)(g_Mh + gr1), lo1 = *(const uint4*)(g_Ml + gr1);
            float m0[8], m1[8];
            {
                float2 fh, fl;
                fh = __bfloat1622float2(*(__nv_bfloat162*)&h0.x);
                fl = __bfloat1622float2(*(__nv_bfloat162*)&lo0.x);
                m0[0] = fh.x + fl.x; m0[1] = fh.y + fl.y;
                fh = __bfloat1622float2(*(__nv_bfloat162*)&h0.y);
                fl = __bfloat1622float2(*(__nv_bfloat162*)&lo0.y);
                m0[2] = fh.x + fl.x; m0[3] = fh.y + fl.y;
                fh = __bfloat1622float2(*(__nv_bfloat162*)&h0.z);
                fl = __bfloat1622float2(*(__nv_bfloat162*)&lo0.z);
                m0[4] = fh.x + fl.x; m0[5] = fh.y + fl.y;
                fh = __bfloat1622float2(*(__nv_bfloat162*)&h0.w);
                fl = __bfloat1622float2(*(__nv_bfloat162*)&lo0.w);
                m0[6] = fh.x + fl.x; m0[7] = fh.y + fl.y;
                fh = __bfloat1622float2(*(__nv_bfloat162*)&h1.x);
                fl = __bfloat1622float2(*(__nv_bfloat162*)&lo1.x);
                m1[0] = fh.x + fl.x; m1[1] = fh.y + fl.y;
                fh = __bfloat1622float2(*(__nv_bfloat162*)&h1.y);
                fl = __bfloat1622float2(*(__nv_bfloat162*)&lo1.y);
                m1[2] = fh.x + fl.x; m1[3] = fh.y + fl.y;
                fh = __bfloat1622float2(*(__nv_bfloat162*)&h1.z);
                fl = __bfloat1622float2(*(__nv_bfloat162*)&lo1.z);
                m1[4] = fh.x + fl.x; m1[5] = fh.y + fl.y;
                fh = __bfloat1622float2(*(__nv_bfloat162*)&h1.w);
                fl = __bfloat1622float2(*(__nv_bfloat162*)&lo1.w);
                m1[6] = fh.x + fl.x; m1[7] = fh.y + fl.y;
            }
            float d0 = 0.f, d1 = 0.f;
#pragma unroll
            for (int j = 0; j < 8; j++) { d0 = fmaf(m0[j], vr[j], d0); d1 = fmaf(m1[j], vr[j], d1); }
#pragma unroll
            for (int o = 16; o; o >>= 1) {
                d0 += __shfl_xor_sync(0xffffffffu, d0, o);
                d1 += __shfl_xor_sync(0xffffffffu, d1, o);
            }
            float uu0 = g_u[row0 + lr], uu1 = g_u[row0 + lr + 1];
            float un0 = uu0 / (uu0 * d0 + EPS);
            float un1 = uu1 / (uu1 * d1 + EPS);
            if (l == 0) { sun[lr] = un0; sun[lr + 1] = un1; }
            if (primary) {
                float a0[8], a1[8];
#pragma unroll
                for (int j = 0; j < 8; j++) {
                    a0[j] = m0[j] * un0 * vr[j];
                    a1[j] = m1[j] * un1 * vr[j];
                    c[j] += a0[j] + a1[j];
                }
                *(float4*)(ab + (size_t)lr * 256 + 8 * l)           = *(float4*)&a0[0];
                *(float4*)(ab + (size_t)lr * 256 + 8 * l + 4)       = *(float4*)&a0[4];
                *(float4*)(ab + (size_t)(lr + 1) * 256 + 8 * l)     = *(float4*)&a1[0];
                *(float4*)(ab + (size_t)(lr + 1) * 256 + 8 * l + 4) = *(float4*)&a1[4];
            }
        }
        if (primary) {
#pragma unroll
            for (int j = 0; j < 8; j++) atomicAdd(&scol[8 * l + j], c[j]);
            __syncthreads();
            if (t < 256) atomicAdd(&g_csum2[bm * 256 + t], scol[t]);
        }
    }
    __syncthreads();

    // ---- phase 2: z tile = diag(un) · M @ B' ----
    const __nv_bfloat16* parts[4] = {
        g_Mh + (size_t)row0 * 256,
        g_Ml + (size_t)row0 * 256,
        g_bvh + (size_t)bm * 65536 + (size_t)col0 * 256,
        g_bvl + (size_t)bm * 65536 + (size_t)col0 * 256
    };
    uint32_t smb = smem_u32(dsm);
    int wm = w >> 1, wn = w & 1;
    uint32_t a_off = (uint32_t)(wm * 32 + (l & 7) + 8 * ((l >> 3) & 1)) * 80
                   + ((l >> 4) & 1) * 16;
    uint32_t b_off = (uint32_t)(wn * 64 + (l & 7) + 8 * ((l >> 4) & 1)) * 80
                   + ((l >> 3) & 1) * 16;

    float acc[2][8][4];
#pragma unroll
    for (int a = 0; a < 2; a++)
#pragma unroll
        for (int b = 0; b < 8; b++)
#pragma unroll
            for (int d = 0; d < 4; d++) acc[a][b][d] = 0.f;

    GEMM_PIPELINE();

    float* zb = out + (size_t)mod * SEG;
#pragma unroll
    for (int tm = 0; tm < 2; tm++) {
        int tr0 = wm * 32 + tm * 16 + (l >> 2);
        int r0 = row0 + tr0;
        float un0 = sun[tr0], un1 = sun[tr0 + 8];
        size_t lr0 = (size_t)(r0 & 16383) * 256, lr1 = lr0 + 8 * 256;
#pragma unroll
        for (int nt = 0; nt < 8; nt++) {
            int col = col0 + wn * 64 + nt * 8 + 2 * (l & 3);
            float* d = acc[tm][nt];
            float2 v0 = {d[0] * un0, d[1] * un0};
            float2 v1 = {d[2] * un1, d[3] * un1};
            *(float2*)(zb + lr0 + col) = v0;
            *(float2*)(zb + lr1 + col) = v1;
        }
    }
}

// ---------------- consistency scalar ----------------
__global__ void k_consist(float* __restrict__ out) {
    __shared__ float red[8];
    int t = threadIdx.x;
    float acc = 0.f;
#pragma unroll
    for (int b = 0; b < 16; b++)
        acc += g_csum2[b * 256 + t] * g_csum2[4096 + b * 256 + t];
#pragma unroll
    for (int o = 16; o; o >>= 1) acc += __shfl_xor_sync(0xffffffffu, acc, o);
    if ((t & 31) == 0) red[t >> 5] = acc;
    __syncthreads();
    if (t == 0) {
        float tot = 0.f;
        for (int i = 0; i < 8; i++) tot += red[i];
        float m = tot * (1.0f / 16777216.0f);
        m = fminf(fmaxf(m, 0.f), 1.f);
        out[(size_t)6 * SEG] = 1.0f - m;
    }
}

// ---------------- launch ----------------
extern "C" void kernel_launch(void* const* d_in, const int* in_sizes, int n_in,
                              void* d_out, int out_size) {
    const float* f_rgb = (const float*)d_in[0];
    const float* f_sn  = (const float*)d_in[1];
    const float* p_rgb = (const float*)d_in[2];
    const float* p_sn  = (const float*)d_in[3];
    float* out = (float*)d_out;

    cudaFuncSetAttribute(k_sinkhorn, cudaFuncAttributeMaxDynamicSharedMemorySize, SINK_SMEM);
    cudaFuncSetAttribute(k_gemm_sim, cudaFuncAttributeMaxDynamicSharedMemorySize, GSMEM);
    cudaFuncSetAttribute(k_finalz,   cudaFuncAttributeMaxDynamicSharedMemorySize, GSMEM);

    k_proto<<<64, 256>>>(p_rgb, p_sn);
    k_xsplit<<<4096, 256>>>(f_rgb, f_sn);
    k_gemm_sim<<<512, 256, GSMEM>>>(out);
    k_sinkhorn<<<128, 256, SINK_SMEM>>>();
    k_finalz<<<512, 256, GSMEM>>>(out);
    k_consist<<<1, 256>>>(out);
}

// round 11
// speedup vs baseline: 1.2526x; 1.2526x over previous
#include <cuda_runtime.h>
#include <cuda_bf16.h>
#include <math.h>
#include <stdint.h>

#define EPS 1e-8f
#define TR  (1.0f/1024.0f)
#define TC  (1.0f/256.0f)
#define SEG 4194304            // 16*1024*256

// ---------------- scratch (device globals; no allocation) ----------------
__device__ __align__(16) __nv_bfloat16 g_Mh[8388608];   // M = exp(sim/tau) hi
__device__ __align__(16) __nv_bfloat16 g_Ml[8388608];   // M lo
__device__ __align__(16) __nv_bfloat16 g_Ah[8388608];   // assign hi
__device__ __align__(16) __nv_bfloat16 g_Al[8388608];   // assign lo
__device__ __align__(16) __nv_bfloat16 g_pbh[131072];   // proto normalized hi [2][k][d]
__device__ __align__(16) __nv_bfloat16 g_pbl[131072];
__device__ __align__(16) __nv_bfloat16 g_pth[131072];   // proto^T hi [2][d][k]
__device__ __align__(16) __nv_bfloat16 g_ptl[131072];
__device__ float g_u[32768];
__device__ float g_v[8192];
__device__ float g_csum2[8192];
__device__ float g_bs[32];

// exp(20*s) via 2^y, FFMA-only
__device__ __forceinline__ float exp20(float s) {
    float y  = s * 28.853900817779268f;
    float fl = floorf(y);
    float f  = y - fl;
    float p = 1.5252733804059840e-05f;
    p = fmaf(p, f, 1.5403530393381609e-04f);
    p = fmaf(p, f, 1.3333558146428443e-03f);
    p = fmaf(p, f, 9.6181291076284772e-03f);
    p = fmaf(p, f, 5.5504108664821580e-02f);
    p = fmaf(p, f, 2.4022650695910071e-01f);
    p = fmaf(p, f, 6.9314718055994531e-01f);
    p = fmaf(p, f, 1.0f);
    int e = (int)fl + 127;
    return p * __int_as_float(e << 23);
}

__device__ __forceinline__ uint32_t smem_u32(const void* p) {
    uint32_t a;
    asm("{ .reg .u64 t; cvta.to.shared.u64 t, %1; cvt.u32.u64 %0, t; }" : "=r"(a) : "l"(p));
    return a;
}
__device__ __forceinline__ void ldmx4(uint32_t* r, uint32_t addr) {
    asm volatile("ldmatrix.sync.aligned.m8n8.x4.shared.b16 {%0,%1,%2,%3}, [%4];"
                 : "=r"(r[0]), "=r"(r[1]), "=r"(r[2]), "=r"(r[3]) : "r"(addr));
}
__device__ __forceinline__ void mma16816(float* d, const uint32_t* a, const uint32_t* b) {
    asm volatile("mma.sync.aligned.m16n8k16.row.col.f32.bf16.bf16.f32 "
                 "{%0,%1,%2,%3}, {%4,%5,%6,%7}, {%8,%9}, {%0,%1,%2,%3};"
                 : "+f"(d[0]), "+f"(d[1]), "+f"(d[2]), "+f"(d[3])
                 : "r"(a[0]), "r"(a[1]), "r"(a[2]), "r"(a[3]), "r"(b[0]), "r"(b[1]));
}
__device__ __forceinline__ uint32_t pack_bf2(__nv_bfloat16 lo, __nv_bfloat16 hi) {
    __nv_bfloat162 t; t.x = lo; t.y = hi;
    uint32_t r; memcpy(&r, &t, 4); return r;
}
__device__ __forceinline__ void split_bf(float x, __nv_bfloat16& h, __nv_bfloat16& l) {
    h = __float2bfloat16_rn(x);
    l = __float2bfloat16_rn(x - __bfloat162float(h));
}
__device__ __forceinline__ void cp_async16(uint32_t smem, const void* g) {
    asm volatile("cp.async.cg.shared.global [%0], [%1], 16;" :: "r"(smem), "l"(g));
}
#define CP_COMMIT() asm volatile("cp.async.commit_group;" ::: "memory")
#define CP_WAIT0()  asm volatile("cp.async.wait_group 0;" ::: "memory")
#define CP_WAIT1()  asm volatile("cp.async.wait_group 1;" ::: "memory")
__device__ __forceinline__ uint32_t mapa_u32(uint32_t a, uint32_t r) {
    uint32_t d;
    asm("mapa.shared::cluster.u32 %0, %1, %2;" : "=r"(d) : "r"(a), "r"(r));
    return d;
}
__device__ __forceinline__ float ld_cluster_f32(uint32_t a) {
    float v;
    asm volatile("ld.shared::cluster.b32 %0, [%1];" : "=f"(v) : "r"(a));
    return v;
}
#define CLUSTER_SYNC() do { \
    asm volatile("barrier.cluster.arrive.aligned;" ::: "memory"); \
    asm volatile("barrier.cluster.wait.aligned;"   ::: "memory"); \
} while (0)

// ---------------- setup ----------------
__global__ void k_proto(const float* __restrict__ p_rgb, const float* __restrict__ p_sn) {
    int gt = blockIdx.x * blockDim.x + threadIdx.x;
    if (gt < 8192) g_csum2[gt] = 0.f;
    if (gt < 32)   g_bs[gt] = 0.f;

    int warp = gt >> 5;
    int lane = threadIdx.x & 31;
    int mod = warp >> 8, row = warp & 255;
    const float* src = (mod ? p_sn : p_rgb) + row * 256;
    float v[8], s = 0.f;
#pragma unroll
    for (int j = 0; j < 8; j++) { v[j] = src[lane + 32 * j]; s += v[j] * v[j]; }
#pragma unroll
    for (int o = 16; o; o >>= 1) s += __shfl_xor_sync(0xffffffffu, s, o);
    float inv = 1.0f / (sqrtf(s) + EPS);
    int base = mod * 65536;
#pragma unroll
    for (int j = 0; j < 8; j++) {
        int col = lane + 32 * j;
        float val = v[j] * inv;
        __nv_bfloat16 h, l;
        split_bf(val, h, l);
        g_pbh[base + row * 256 + col] = h;
        g_pbl[base + row * 256 + col] = l;
        g_pth[base + col * 256 + row] = h;
        g_ptl[base + col * 256 + row] = l;
    }
}

// ---------------- GEMM1 (round-9 proven): sim + split M, xnorm fused ----------------
#define STG   40960
#define GSMEM 81920

#define DO_MMA(sb) do { \
    _Pragma("unroll") \
    for (int ks = 0; ks < 2; ks++) { \
        uint32_t kb = ks * 32; \
        uint32_t aH[2][4], aL[2][4]; \
        ldmx4(aH[0], (sb) + a_off + kb); \
        ldmx4(aH[1], (sb) + a_off + 16 * 80 + kb); \
        ldmx4(aL[0], (sb) + 10240 + a_off + kb); \
        ldmx4(aL[1], (sb) + 10240 + a_off + 16 * 80 + kb); \
        _Pragma("unroll") \
        for (int np = 0; np < 4; np++) { \
            uint32_t bo = b_off + (uint32_t)np * 16 * 80 + kb; \
            uint32_t bH[4], bL[4]; \
            ldmx4(bH, (sb) + 20480 + bo); \
            ldmx4(bL, (sb) + 30720 + bo); \
            _Pragma("unroll") \
            for (int tm = 0; tm < 2; tm++) { \
                mma16816(acc[tm][2 * np],     aH[tm], bH); \
                mma16816(acc[tm][2 * np],     aH[tm], bL); \
                mma16816(acc[tm][2 * np],     aL[tm], bH); \
                mma16816(acc[tm][2 * np + 1], aH[tm], bH + 2); \
                mma16816(acc[tm][2 * np + 1], aH[tm], bL + 2); \
                mma16816(acc[tm][2 * np + 1], aL[tm], bH + 2); \
            } \
        } \
    } \
} while (0)

#define B_CPASYNC(dd, stg_off) do { \
    _Pragma("unroll") \
    for (int i = 0; i < 4; i++) { \
        int idx = t + 256 * i; \
        int part = idx >> 9, row = (idx >> 2) & 127, c8 = idx & 3; \
        const __nv_bfloat16* srcp = (part ? Blp : Bhp) + (size_t)row * 256 + (dd) + 8 * c8; \
        cp_async16(smb + (stg_off) + (part ? 30720 : 20480) + row * 80 + c8 * 16, srcp); \
    } \
    CP_COMMIT(); \
} while (0)

__global__ __launch_bounds__(256, 2)
void k_gemm_sim(const float* __restrict__ f_rgb, const float* __restrict__ f_sn,
                float* __restrict__ out) {
    extern __shared__ char dsm[];
    __shared__ float sSq[128];
    int t = threadIdx.x, l = t & 31, w = t >> 5;
    int wm = w >> 1, wn = w & 1;
    int bx = blockIdx.x;
    int row0 = (bx >> 1) * 128;
    int col0 = (bx & 1) * 128;
    int mod = row0 >> 14, lrow0 = row0 & 16383;
    const float* X = (mod ? f_sn : f_rgb) + (size_t)lrow0 * 256;
    const __nv_bfloat16* Bhp = g_pbh + mod * 65536 + (size_t)col0 * 256;
    const __nv_bfloat16* Blp = g_pbl + mod * 65536 + (size_t)col0 * 256;

    uint32_t smb = smem_u32(dsm);
    uint32_t a_off = (uint32_t)(wm * 32 + (l & 7) + 8 * ((l >> 3) & 1)) * 80
                   + ((l >> 4) & 1) * 16;
    uint32_t b_off = (uint32_t)(wn * 64 + (l & 7) + 8 * ((l >> 4) & 1)) * 80
                   + ((l >> 3) & 1) * 16;

    float acc[2][8][4];
#pragma unroll
    for (int a = 0; a < 2; a++)
#pragma unroll
        for (int b = 0; b < 8; b++)
#pragma unroll
            for (int d = 0; d < 4; d++) acc[a][b][d] = 0.f;
    float ss[4] = {0.f, 0.f, 0.f, 0.f};
    float4 aReg[4];

#pragma unroll
    for (int i = 0; i < 4; i++) {
        int idx = t + 256 * i;
        aReg[i] = *(const float4*)(X + (size_t)(idx >> 3) * 256 + 4 * (idx & 7));
    }
    B_CPASYNC(0, 0);
#pragma unroll
    for (int i = 0; i < 4; i++) {
        int idx = t + 256 * i;
        int row = idx >> 3, c4 = idx & 7;
        float4 v = aReg[i];
        ss[i] += v.x * v.x + v.y * v.y + v.z * v.z + v.w * v.w;
        __nv_bfloat16 hx, lx, hy, ly, hz, lz, hw, lw;
        split_bf(v.x, hx, lx); split_bf(v.y, hy, ly);
        split_bf(v.z, hz, lz); split_bf(v.w, hw, lw);
        uint2 ph, pl;
        ph.x = pack_bf2(hx, hy); ph.y = pack_bf2(hz, hw);
        pl.x = pack_bf2(lx, ly); pl.y = pack_bf2(lz, lw);
        int sob = row * 80 + c4 * 8;
        *(uint2*)(dsm + sob) = ph;
        *(uint2*)(dsm + 10240 + sob) = pl;
    }
    CP_WAIT0();
    __syncthreads();

#pragma unroll 2
    for (int c = 0; c < 8; c++) {
        int buf = c & 1, nbuf = buf ^ 1;
        if (c < 7) {
            int dd = (c + 1) * 32;
#pragma unroll
            for (int i = 0; i < 4; i++) {
                int idx = t + 256 * i;
                aReg[i] = *(const float4*)(X + (size_t)(idx >> 3) * 256 + dd + 4 * (idx & 7));
            }
            B_CPASYNC(dd, nbuf * STG);
        }
        uint32_t sb = smb + buf * STG;
        DO_MMA(sb);
        if (c < 7) {
            char* stg = dsm + nbuf * STG;
#pragma unroll
            for (int i = 0; i < 4; i++) {
                int idx = t + 256 * i;
                int row = idx >> 3, c4 = idx & 7;
                float4 v = aReg[i];
                ss[i] += v.x * v.x + v.y * v.y + v.z * v.z + v.w * v.w;
                __nv_bfloat16 hx, lx, hy, ly, hz, lz, hw, lw;
                split_bf(v.x, hx, lx); split_bf(v.y, hy, ly);
                split_bf(v.z, hz, lz); split_bf(v.w, hw, lw);
                uint2 ph, pl;
                ph.x = pack_bf2(hx, hy); ph.y = pack_bf2(hz, hw);
                pl.x = pack_bf2(lx, ly); pl.y = pack_bf2(lz, lw);
                int sob = row * 80 + c4 * 8;
                *(uint2*)(stg + sob) = ph;
                *(uint2*)(stg + 10240 + sob) = pl;
            }
            CP_WAIT0();
        }
        __syncthreads();
    }

#pragma unroll
    for (int i = 0; i < 4; i++) {
        ss[i] += __shfl_xor_sync(0xffffffffu, ss[i], 1);
        ss[i] += __shfl_xor_sync(0xffffffffu, ss[i], 2);
        ss[i] += __shfl_xor_sync(0xffffffffu, ss[i], 4);
    }
    if ((t & 7) == 0) {
#pragma unroll
        for (int i = 0; i < 4; i++)
            sSq[(t >> 3) + 32 * i] = ss[i];
    }
    __syncthreads();

    float* simb = out + (size_t)(4 + mod) * SEG;
    float psum = 0.f;
#pragma unroll
    for (int tm = 0; tm < 2; tm++) {
        int tr0 = wm * 32 + tm * 16 + (l >> 2);
        int r0 = row0 + tr0, r1 = r0 + 8;
        float xi0 = 1.0f / (sqrtf(sSq[tr0]) + EPS);
        float xi1 = 1.0f / (sqrtf(sSq[tr0 + 8]) + EPS);
        size_t lr0 = (size_t)(r0 & 16383) * 256, lr1 = (size_t)(r1 & 16383) * 256;
        size_t gr0 = (size_t)r0 * 256, gr1 = (size_t)r1 * 256;
#pragma unroll
        for (int nt = 0; nt < 8; nt++) {
            int col = col0 + wn * 64 + nt * 8 + 2 * (l & 3);
            float* d = acc[tm][nt];
            float2 s0 = {d[0] * xi0, d[1] * xi0};
            float2 s1 = {d[2] * xi1, d[3] * xi1};
            *(float2*)(simb + lr0 + col) = s0;
            *(float2*)(simb + lr1 + col) = s1;
            float2 e0 = {exp20(s0.x), exp20(s0.y)};
            float2 e1 = {exp20(s1.x), exp20(s1.y)};
            __nv_bfloat16 h0x, l0x, h0y, l0y, h1x, l1x, h1y, l1y;
            split_bf(e0.x, h0x, l0x); split_bf(e0.y, h0y, l0y);
            split_bf(e1.x, h1x, l1x); split_bf(e1.y, h1y, l1y);
            *(uint32_t*)(g_Mh + gr0 + col) = pack_bf2(h0x, h0y);
            *(uint32_t*)(g_Ml + gr0 + col) = pack_bf2(l0x, l0y);
            *(uint32_t*)(g_Mh + gr1 + col) = pack_bf2(h1x, h1y);
            *(uint32_t*)(g_Ml + gr1 + col) = pack_bf2(l1x, l1y);
            psum += (e0.x + e0.y) + (e1.x + e1.y);
        }
    }
#pragma unroll
    for (int o = 16; o; o >>= 1) psum += __shfl_xor_sync(0xffffffffu, psum, o);
    if (l == 0) atomicAdd(&g_bs[row0 >> 10], psum);
}

// ---------------- sinkhorn: cluster of 4 CTAs per slice, cp.async M fill ----------------
#define SINK_SMEM 134144

__global__ void __launch_bounds__(256, 1) __cluster_dims__(4, 1, 1)
k_sinkhorn() {
    extern __shared__ char smraw[];
    __nv_bfloat16* sM = (__nv_bfloat16*)smraw;
    float* su   = (float*)(smraw + 131072);
    float* sv   = (float*)(smraw + 132096);
    float* scol = (float*)(smraw + 133120);
    int t = threadIdx.x, lane = t & 31, w = t >> 5;
    uint32_t rank;
    asm("mov.u32 %0, %%cluster_ctarank;" : "=r"(rank));
    int bm = blockIdx.x >> 2;
    uint32_t smb = smem_u32(smraw);
    uint32_t scol_a = smem_u32(scol);

    // async fill of this CTA's 256-row quarter (128 KB)
    const uint4* src = (const uint4*)(g_Mh + (size_t)bm * 262144 + (size_t)rank * 65536);
#pragma unroll
    for (int i = 0; i < 32; i++)
        cp_async16(smb + (t + 256 * i) * 16, src + t + 256 * i);
    CP_COMMIT();

    float u0 = 1.0f / (g_bs[bm] + EPS);
    if (t < 256) { su[t] = u0; sv[t] = 1.0f; scol[t] = 0.f; }
    CP_WAIT0();
    __syncthreads();

    for (int it = 0; it < 5; it++) {
        float vr[8];
#pragma unroll
        for (int j = 0; j < 8; j++) vr[j] = sv[8 * lane + j];
        float c[8] = {0, 0, 0, 0, 0, 0, 0, 0};
        for (int rr = 0; rr < 32; rr += 2) {
            int row = w * 32 + rr;
            uint4 mv0 = *(const uint4*)(sM + row * 256 + 8 * lane);
            uint4 mv1 = *(const uint4*)(sM + (row + 1) * 256 + 8 * lane);
            float m0[8], m1[8];
            {
                float2 f;
                f = __bfloat1622float2(*(__nv_bfloat162*)&mv0.x); m0[0]=f.x; m0[1]=f.y;
                f = __bfloat1622float2(*(__nv_bfloat162*)&mv0.y); m0[2]=f.x; m0[3]=f.y;
                f = __bfloat1622float2(*(__nv_bfloat162*)&mv0.z); m0[4]=f.x; m0[5]=f.y;
                f = __bfloat1622float2(*(__nv_bfloat162*)&mv0.w); m0[6]=f.x; m0[7]=f.y;
                f = __bfloat1622float2(*(__nv_bfloat162*)&mv1.x); m1[0]=f.x; m1[1]=f.y;
                f = __bfloat1622float2(*(__nv_bfloat162*)&mv1.y); m1[2]=f.x; m1[3]=f.y;
                f = __bfloat1622float2(*(__nv_bfloat162*)&mv1.z); m1[4]=f.x; m1[5]=f.y;
                f = __bfloat1622float2(*(__nv_bfloat162*)&mv1.w); m1[6]=f.x; m1[7]=f.y;
            }
            float d0 = 0.f, d1 = 0.f;
#pragma unroll
            for (int j = 0; j < 8; j++) { d0 = fmaf(m0[j], vr[j], d0); d1 = fmaf(m1[j], vr[j], d1); }
#pragma unroll
            for (int o = 16; o; o >>= 1) {
                d0 += __shfl_xor_sync(0xffffffffu, d0, o);
                d1 += __shfl_xor_sync(0xffffffffu, d1, o);
            }
            float uu0 = su[row], uu1 = su[row + 1];
            float un0 = uu0 * TR / (uu0 * d0 + EPS);
            float un1 = uu1 * TR / (uu1 * d1 + EPS);
            if (lane == 0) { su[row] = un0; su[row + 1] = un1; }
#pragma unroll
            for (int j = 0; j < 8; j++)
                c[j] = fmaf(m0[j], un0, fmaf(m1[j], un1, c[j]));
        }
#pragma unroll
        for (int j = 0; j < 8; j++) atomicAdd(&scol[8 * lane + j], c[j]);
        CLUSTER_SYNC();
        float tot = 0.f;
        if (t < 256) {
#pragma unroll
            for (uint32_t r = 0; r < 4; r++)
                tot += ld_cluster_f32(mapa_u32(scol_a + 4 * t, r));
        }
        CLUSTER_SYNC();
        if (t < 256) {
            float v = sv[t];
            sv[t] = v * TC / (v * tot + EPS);
            scol[t] = 0.f;
        }
        __syncthreads();
    }
    if (rank == 0 && t < 256) g_v[bm * 256 + t] = sv[t];
    if (t < 256) g_u[bm * 1024 + rank * 256 + t] = su[t];
}

// ---------------- k_final: un + assign (fp32 out, bf16 split) + colsums ----------------
__global__ __launch_bounds__(256)
void k_final(float* __restrict__ out) {
    __shared__ float vs[256];
    __shared__ float colacc[256];
    int t = threadIdx.x, lane = t & 31, w = t >> 5;
    int row0 = blockIdx.x * 64;
    int bm = row0 >> 10;
    int mod = row0 >> 14;
    vs[t] = g_v[bm * 256 + t];
    colacc[t] = 0.f;
    __syncthreads();
    float vr[8];
#pragma unroll
    for (int j = 0; j < 8; j++) vr[j] = vs[8 * lane + j];
    float c[8] = {0, 0, 0, 0, 0, 0, 0, 0};
    float* aout = out + (size_t)(2 + mod) * SEG;
#pragma unroll
    for (int r = 0; r < 8; r++) {
        int n = row0 + w * 8 + r;
        int lrow = n & 16383;
        size_t g = (size_t)n * 256 + 8 * lane;
        uint4 hv = *(const uint4*)(g_Mh + g);
        uint4 lv = *(const uint4*)(g_Ml + g);
        float m[8];
        {
            float2 fh, fl;
            fh = __bfloat1622float2(*(__nv_bfloat162*)&hv.x);
            fl = __bfloat1622float2(*(__nv_bfloat162*)&lv.x);
            m[0] = fh.x + fl.x; m[1] = fh.y + fl.y;
            fh = __bfloat1622float2(*(__nv_bfloat162*)&hv.y);
            fl = __bfloat1622float2(*(__nv_bfloat162*)&lv.y);
            m[2] = fh.x + fl.x; m[3] = fh.y + fl.y;
            fh = __bfloat1622float2(*(__nv_bfloat162*)&hv.z);
            fl = __bfloat1622float2(*(__nv_bfloat162*)&lv.z);
            m[4] = fh.x + fl.x; m[5] = fh.y + fl.y;
            fh = __bfloat1622float2(*(__nv_bfloat162*)&hv.w);
            fl = __bfloat1622float2(*(__nv_bfloat162*)&lv.w);
            m[6] = fh.x + fl.x; m[7] = fh.y + fl.y;
        }
        float dot = 0.f;
#pragma unroll
        for (int j = 0; j < 8; j++) dot = fmaf(m[j], vr[j], dot);
#pragma unroll
        for (int o = 16; o; o >>= 1) dot += __shfl_xor_sync(0xffffffffu, dot, o);
        float u = g_u[n];
        float un = u / (u * dot + EPS);
        float a[8];
        uint4 ah, al;
        uint32_t* ahp = (uint32_t*)&ah;
        uint32_t* alp = (uint32_t*)&al;
#pragma unroll
        for (int j = 0; j < 8; j += 2) {
            a[j] = m[j] * un * vr[j];
            a[j + 1] = m[j + 1] * un * vr[j + 1];
            c[j] += a[j]; c[j + 1] += a[j + 1];
            __nv_bfloat16 h0, l0, h1, l1;
            split_bf(a[j], h0, l0);
            split_bf(a[j + 1], h1, l1);
            ahp[j >> 1] = pack_bf2(h0, h1);
            alp[j >> 1] = pack_bf2(l0, l1);
        }
        *(float4*)(aout + (size_t)lrow * 256 + 8 * lane) = *(float4*)&a[0];
        *(float4*)(aout + (size_t)lrow * 256 + 8 * lane + 4) = *(float4*)&a[4];
        *(uint4*)(g_Ah + g) = ah;
        *(uint4*)(g_Al + g) = al;
    }
#pragma unroll
    for (int j = 0; j < 8; j++) atomicAdd(&colacc[8 * lane + j], c[j]);
    __syncthreads();
    atomicAdd(&g_csum2[bm * 256 + t], colacc[t]);
}

// ---------------- k_z: z = assign @ Phat, pure-load double-buffered ----------------
#define LOAD_CHUNK(dd, stg) do { \
    _Pragma("unroll") \
    for (int i = 0; i < 8; i++) { \
        int rem = t + 256 * (i & 1); \
        int row = rem >> 2, c16 = rem & 3; \
        cp_async16(smb + (stg) + (i >> 1) * 10240 + row * 80 + c16 * 16, \
                   parts[i >> 1] + (size_t)row * 256 + (dd) + c16 * 8); \
    } \
    CP_COMMIT(); \
} while (0)

__global__ __launch_bounds__(256, 2)
void k_z(float* __restrict__ out) {
    extern __shared__ char dsm[];
    int t = threadIdx.x, l = t & 31, w = t >> 5;
    int wm = w >> 1, wn = w & 1;
    int bx = blockIdx.x;
    int row0 = (bx >> 1) * 128;
    int col0 = (bx & 1) * 128;
    int mod = row0 >> 14;

    const __nv_bfloat16* parts[4] = {
        g_Ah + (size_t)row0 * 256,
        g_Al + (size_t)row0 * 256,
        g_pth + mod * 65536 + (size_t)col0 * 256,
        g_ptl + mod * 65536 + (size_t)col0 * 256
    };
    uint32_t smb = smem_u32(dsm);
    uint32_t a_off = (uint32_t)(wm * 32 + (l & 7) + 8 * ((l >> 3) & 1)) * 80
                   + ((l >> 4) & 1) * 16;
    uint32_t b_off = (uint32_t)(wn * 64 + (l & 7) + 8 * ((l >> 4) & 1)) * 80
                   + ((l >> 3) & 1) * 16;

    float acc[2][8][4];
#pragma unroll
    for (int a = 0; a < 2; a++)
#pragma unroll
        for (int b = 0; b < 8; b++)
#pragma unroll
            for (int d = 0; d < 4; d++) acc[a][b][d] = 0.f;

    LOAD_CHUNK(0, 0);
    for (int c = 0; c < 8; c++) {
        int buf = c & 1;
        if (c < 7) { LOAD_CHUNK((c + 1) * 32, (buf ^ 1) * STG); CP_WAIT1(); }
        else       { CP_WAIT0(); }
        __syncthreads();
        uint32_t sb = smb + buf * STG;
        DO_MMA(sb);
        __syncthreads();
    }

    float* zb = out + (size_t)mod * SEG;
#pragma unroll
    for (int tm = 0; tm < 2; tm++) {
        int r0 = row0 + wm * 32 + tm * 16 + (l >> 2);
        size_t lr0 = (size_t)(r0 & 16383) * 256, lr1 = lr0 + 8 * 256;
#pragma unroll
        for (int nt = 0; nt < 8; nt++) {
            int col = col0 + wn * 64 + nt * 8 + 2 * (l & 3);
            float* d = acc[tm][nt];
            float2 v0 = {d[0], d[1]}, v1 = {d[2], d[3]};
            *(float2*)(zb + lr0 + col) = v0;
            *(float2*)(zb + lr1 + col) = v1;
        }
    }

    // sem_consistency once (csum2 complete from k_final)
    if (bx == 0) {
        __shared__ float red[8];
        float accs = 0.f;
#pragma unroll
        for (int b = 0; b < 16; b++)
            accs += g_csum2[b * 256 + t] * g_csum2[4096 + b * 256 + t];
#pragma unroll
        for (int o = 16; o; o >>= 1) accs += __shfl_xor_sync(0xffffffffu, accs, o);
        if (l == 0) red[w] = accs;
        __syncthreads();
        if (t == 0) {
            float tot = 0.f;
            for (int i = 0; i < 8; i++) tot += red[i];
            float m = tot * (1.0f / 16777216.0f);
            m = fminf(fmaxf(m, 0.f), 1.f);
            out[(size_t)6 * SEG] = 1.0f - m;
        }
    }
}

// ---------------- launch ----------------
extern "C" void kernel_launch(void* const* d_in, const int* in_sizes, int n_in,
                              void* d_out, int out_size) {
    const float* f_rgb = (const float*)d_in[0];
    const float* f_sn  = (const float*)d_in[1];
    const float* p_rgb = (const float*)d_in[2];
    const float* p_sn  = (const float*)d_in[3];
    float* out = (float*)d_out;

    cudaFuncSetAttribute(k_sinkhorn, cudaFuncAttributeMaxDynamicSharedMemorySize, SINK_SMEM);
    cudaFuncSetAttribute(k_gemm_sim, cudaFuncAttributeMaxDynamicSharedMemorySize, GSMEM);
    cudaFuncSetAttribute(k_z,        cudaFuncAttributeMaxDynamicSharedMemorySize, GSMEM);

    k_proto<<<64, 256>>>(p_rgb, p_sn);
    k_gemm_sim<<<512, 256, GSMEM>>>(f_rgb, f_sn, out);
    k_sinkhorn<<<128, 256, SINK_SMEM>>>();
    k_final<<<512, 256>>>(out);
    k_z<<<512, 256, GSMEM>>>(out);
}

// round 12
// speedup vs baseline: 1.2561x; 1.0028x over previous
#include <cuda_runtime.h>
#include <cuda_bf16.h>
#include <math.h>
#include <stdint.h>

#define EPS 1e-8f
#define TR  (1.0f/1024.0f)
#define TC  (1.0f/256.0f)
#define SEG 4194304            // 16*1024*256

// ---------------- scratch (device globals; no allocation) ----------------
__device__ __align__(16) __nv_bfloat16 g_Mh[8388608];   // M = exp(sim/tau) hi
__device__ __align__(16) __nv_bfloat16 g_Ml[8388608];   // M lo
__device__ __align__(16) __nv_bfloat16 g_Ah[8388608];   // assign hi
__device__ __align__(16) __nv_bfloat16 g_Al[8388608];   // assign lo
__device__ __align__(16) __nv_bfloat16 g_pbh[131072];   // proto normalized hi [2][k][d]
__device__ __align__(16) __nv_bfloat16 g_pbl[131072];
__device__ __align__(16) __nv_bfloat16 g_pth[131072];   // proto^T hi [2][d][k]
__device__ __align__(16) __nv_bfloat16 g_ptl[131072];
__device__ float g_csum2[8192];
__device__ float g_bs[32];

// exp(20*s) via 2^y, FFMA-only
__device__ __forceinline__ float exp20(float s) {
    float y  = s * 28.853900817779268f;
    float fl = floorf(y);
    float f  = y - fl;
    float p = 1.5252733804059840e-05f;
    p = fmaf(p, f, 1.5403530393381609e-04f);
    p = fmaf(p, f, 1.3333558146428443e-03f);
    p = fmaf(p, f, 9.6181291076284772e-03f);
    p = fmaf(p, f, 5.5504108664821580e-02f);
    p = fmaf(p, f, 2.4022650695910071e-01f);
    p = fmaf(p, f, 6.9314718055994531e-01f);
    p = fmaf(p, f, 1.0f);
    int e = (int)fl + 127;
    return p * __int_as_float(e << 23);
}

__device__ __forceinline__ uint32_t smem_u32(const void* p) {
    uint32_t a;
    asm("{ .reg .u64 t; cvta.to.shared.u64 t, %1; cvt.u32.u64 %0, t; }" : "=r"(a) : "l"(p));
    return a;
}
__device__ __forceinline__ void ldmx4(uint32_t* r, uint32_t addr) {
    asm volatile("ldmatrix.sync.aligned.m8n8.x4.shared.b16 {%0,%1,%2,%3}, [%4];"
                 : "=r"(r[0]), "=r"(r[1]), "=r"(r[2]), "=r"(r[3]) : "r"(addr));
}
__device__ __forceinline__ void mma16816(float* d, const uint32_t* a, const uint32_t* b) {
    asm volatile("mma.sync.aligned.m16n8k16.row.col.f32.bf16.bf16.f32 "
                 "{%0,%1,%2,%3}, {%4,%5,%6,%7}, {%8,%9}, {%0,%1,%2,%3};"
                 : "+f"(d[0]), "+f"(d[1]), "+f"(d[2]), "+f"(d[3])
                 : "r"(a[0]), "r"(a[1]), "r"(a[2]), "r"(a[3]), "r"(b[0]), "r"(b[1]));
}
__device__ __forceinline__ uint32_t pack_bf2(__nv_bfloat16 lo, __nv_bfloat16 hi) {
    __nv_bfloat162 t; t.x = lo; t.y = hi;
    uint32_t r; memcpy(&r, &t, 4); return r;
}
__device__ __forceinline__ void split_bf(float x, __nv_bfloat16& h, __nv_bfloat16& l) {
    h = __float2bfloat16_rn(x);
    l = __float2bfloat16_rn(x - __bfloat162float(h));
}
__device__ __forceinline__ void cp_async16(uint32_t smem, const void* g) {
    asm volatile("cp.async.cg.shared.global [%0], [%1], 16;" :: "r"(smem), "l"(g));
}
#define CP_COMMIT() asm volatile("cp.async.commit_group;" ::: "memory")
#define CP_WAIT0()  asm volatile("cp.async.wait_group 0;" ::: "memory")
#define CP_WAIT1()  asm volatile("cp.async.wait_group 1;" ::: "memory")
__device__ __forceinline__ uint32_t mapa_u32(uint32_t a, uint32_t r) {
    uint32_t d;
    asm("mapa.shared::cluster.u32 %0, %1, %2;" : "=r"(d) : "r"(a), "r"(r));
    return d;
}
__device__ __forceinline__ float ld_cluster_f32(uint32_t a) {
    float v;
    asm volatile("ld.shared::cluster.b32 %0, [%1];" : "=f"(v) : "r"(a));
    return v;
}
#define CLUSTER_SYNC() do { \
    asm volatile("barrier.cluster.arrive.aligned;" ::: "memory"); \
    asm volatile("barrier.cluster.wait.aligned;"   ::: "memory"); \
} while (0)

// ---------------- setup ----------------
__global__ void k_proto(const float* __restrict__ p_rgb, const float* __restrict__ p_sn) {
    int gt = blockIdx.x * blockDim.x + threadIdx.x;
    if (gt < 8192) g_csum2[gt] = 0.f;
    if (gt < 32)   g_bs[gt] = 0.f;

    int warp = gt >> 5;
    int lane = threadIdx.x & 31;
    int mod = warp >> 8, row = warp & 255;
    const float* src = (mod ? p_sn : p_rgb) + row * 256;
    float v[8], s = 0.f;
#pragma unroll
    for (int j = 0; j < 8; j++) { v[j] = src[lane + 32 * j]; s += v[j] * v[j]; }
#pragma unroll
    for (int o = 16; o; o >>= 1) s += __shfl_xor_sync(0xffffffffu, s, o);
    float inv = 1.0f / (sqrtf(s) + EPS);
    int base = mod * 65536;
#pragma unroll
    for (int j = 0; j < 8; j++) {
        int col = lane + 32 * j;
        float val = v[j] * inv;
        __nv_bfloat16 h, l;
        split_bf(val, h, l);
        g_pbh[base + row * 256 + col] = h;
        g_pbl[base + row * 256 + col] = l;
        g_pth[base + col * 256 + row] = h;
        g_ptl[base + col * 256 + row] = l;
    }
}

// ---------------- GEMM machinery (round-9/11 proven) ----------------
#define STG   40960
#define GSMEM 81920

#define DO_MMA(sb) do { \
    _Pragma("unroll") \
    for (int ks = 0; ks < 2; ks++) { \
        uint32_t kb = ks * 32; \
        uint32_t aH[2][4], aL[2][4]; \
        ldmx4(aH[0], (sb) + a_off + kb); \
        ldmx4(aH[1], (sb) + a_off + 16 * 80 + kb); \
        ldmx4(aL[0], (sb) + 10240 + a_off + kb); \
        ldmx4(aL[1], (sb) + 10240 + a_off + 16 * 80 + kb); \
        _Pragma("unroll") \
        for (int np = 0; np < 4; np++) { \
            uint32_t bo = b_off + (uint32_t)np * 16 * 80 + kb; \
            uint32_t bH[4], bL[4]; \
            ldmx4(bH, (sb) + 20480 + bo); \
            ldmx4(bL, (sb) + 30720 + bo); \
            _Pragma("unroll") \
            for (int tm = 0; tm < 2; tm++) { \
                mma16816(acc[tm][2 * np],     aH[tm], bH); \
                mma16816(acc[tm][2 * np],     aH[tm], bL); \
                mma16816(acc[tm][2 * np],     aL[tm], bH); \
                mma16816(acc[tm][2 * np + 1], aH[tm], bH + 2); \
                mma16816(acc[tm][2 * np + 1], aH[tm], bL + 2); \
                mma16816(acc[tm][2 * np + 1], aL[tm], bH + 2); \
            } \
        } \
    } \
} while (0)

#define B_CPASYNC(dd, stg_off) do { \
    _Pragma("unroll") \
    for (int i = 0; i < 4; i++) { \
        int idx = t + 256 * i; \
        int part = idx >> 9, row = (idx >> 2) & 127, c8 = idx & 3; \
        const __nv_bfloat16* srcp = (part ? Blp : Bhp) + (size_t)row * 256 + (dd) + 8 * c8; \
        cp_async16(smb + (stg_off) + (part ? 30720 : 20480) + row * 80 + c8 * 16, srcp); \
    } \
    CP_COMMIT(); \
} while (0)

__global__ __launch_bounds__(256, 2)
void k_gemm_sim(const float* __restrict__ f_rgb, const float* __restrict__ f_sn,
                float* __restrict__ out) {
    extern __shared__ char dsm[];
    __shared__ float sSq[128];
    int t = threadIdx.x, l = t & 31, w = t >> 5;
    int wm = w >> 1, wn = w & 1;
    int bx = blockIdx.x;
    int row0 = (bx >> 1) * 128;
    int col0 = (bx & 1) * 128;
    int mod = row0 >> 14, lrow0 = row0 & 16383;
    const float* X = (mod ? f_sn : f_rgb) + (size_t)lrow0 * 256;
    const __nv_bfloat16* Bhp = g_pbh + mod * 65536 + (size_t)col0 * 256;
    const __nv_bfloat16* Blp = g_pbl + mod * 65536 + (size_t)col0 * 256;

    uint32_t smb = smem_u32(dsm);
    uint32_t a_off = (uint32_t)(wm * 32 + (l & 7) + 8 * ((l >> 3) & 1)) * 80
                   + ((l >> 4) & 1) * 16;
    uint32_t b_off = (uint32_t)(wn * 64 + (l & 7) + 8 * ((l >> 4) & 1)) * 80
                   + ((l >> 3) & 1) * 16;

    float acc[2][8][4];
#pragma unroll
    for (int a = 0; a < 2; a++)
#pragma unroll
        for (int b = 0; b < 8; b++)
#pragma unroll
            for (int d = 0; d < 4; d++) acc[a][b][d] = 0.f;
    float ss[4] = {0.f, 0.f, 0.f, 0.f};
    float4 aReg[4];

#pragma unroll
    for (int i = 0; i < 4; i++) {
        int idx = t + 256 * i;
        aReg[i] = *(const float4*)(X + (size_t)(idx >> 3) * 256 + 4 * (idx & 7));
    }
    B_CPASYNC(0, 0);
#pragma unroll
    for (int i = 0; i < 4; i++) {
        int idx = t + 256 * i;
        int row = idx >> 3, c4 = idx & 7;
        float4 v = aReg[i];
        ss[i] += v.x * v.x + v.y * v.y + v.z * v.z + v.w * v.w;
        __nv_bfloat16 hx, lx, hy, ly, hz, lz, hw, lw;
        split_bf(v.x, hx, lx); split_bf(v.y, hy, ly);
        split_bf(v.z, hz, lz); split_bf(v.w, hw, lw);
        uint2 ph, pl;
        ph.x = pack_bf2(hx, hy); ph.y = pack_bf2(hz, hw);
        pl.x = pack_bf2(lx, ly); pl.y = pack_bf2(lz, lw);
        int sob = row * 80 + c4 * 8;
        *(uint2*)(dsm + sob) = ph;
        *(uint2*)(dsm + 10240 + sob) = pl;
    }
    CP_WAIT0();
    __syncthreads();

#pragma unroll 2
    for (int c = 0; c < 8; c++) {
        int buf = c & 1, nbuf = buf ^ 1;
        if (c < 7) {
            int dd = (c + 1) * 32;
#pragma unroll
            for (int i = 0; i < 4; i++) {
                int idx = t + 256 * i;
                aReg[i] = *(const float4*)(X + (size_t)(idx >> 3) * 256 + dd + 4 * (idx & 7));
            }
            B_CPASYNC(dd, nbuf * STG);
        }
        uint32_t sb = smb + buf * STG;
        DO_MMA(sb);
        if (c < 7) {
            char* stg = dsm + nbuf * STG;
#pragma unroll
            for (int i = 0; i < 4; i++) {
                int idx = t + 256 * i;
                int row = idx >> 3, c4 = idx & 7;
                float4 v = aReg[i];
                ss[i] += v.x * v.x + v.y * v.y + v.z * v.z + v.w * v.w;
                __nv_bfloat16 hx, lx, hy, ly, hz, lz, hw, lw;
                split_bf(v.x, hx, lx); split_bf(v.y, hy, ly);
                split_bf(v.z, hz, lz); split_bf(v.w, hw, lw);
                uint2 ph, pl;
                ph.x = pack_bf2(hx, hy); ph.y = pack_bf2(hz, hw);
                pl.x = pack_bf2(lx, ly); pl.y = pack_bf2(lz, lw);
                int sob = row * 80 + c4 * 8;
                *(uint2*)(stg + sob) = ph;
                *(uint2*)(stg + 10240 + sob) = pl;
            }
            CP_WAIT0();
        }
        __syncthreads();
    }

#pragma unroll
    for (int i = 0; i < 4; i++) {
        ss[i] += __shfl_xor_sync(0xffffffffu, ss[i], 1);
        ss[i] += __shfl_xor_sync(0xffffffffu, ss[i], 2);
        ss[i] += __shfl_xor_sync(0xffffffffu, ss[i], 4);
    }
    if ((t & 7) == 0) {
#pragma unroll
        for (int i = 0; i < 4; i++)
            sSq[(t >> 3) + 32 * i] = ss[i];
    }
    __syncthreads();

    float* simb = out + (size_t)(4 + mod) * SEG;
    float psum = 0.f;
#pragma unroll
    for (int tm = 0; tm < 2; tm++) {
        int tr0 = wm * 32 + tm * 16 + (l >> 2);
        int r0 = row0 + tr0, r1 = r0 + 8;
        float xi0 = 1.0f / (sqrtf(sSq[tr0]) + EPS);
        float xi1 = 1.0f / (sqrtf(sSq[tr0 + 8]) + EPS);
        size_t lr0 = (size_t)(r0 & 16383) * 256, lr1 = (size_t)(r1 & 16383) * 256;
        size_t gr0 = (size_t)r0 * 256, gr1 = (size_t)r1 * 256;
#pragma unroll
        for (int nt = 0; nt < 8; nt++) {
            int col = col0 + wn * 64 + nt * 8 + 2 * (l & 3);
            float* d = acc[tm][nt];
            float2 s0 = {d[0] * xi0, d[1] * xi0};
            float2 s1 = {d[2] * xi1, d[3] * xi1};
            *(float2*)(simb + lr0 + col) = s0;
            *(float2*)(simb + lr1 + col) = s1;
            float2 e0 = {exp20(s0.x), exp20(s0.y)};
            float2 e1 = {exp20(s1.x), exp20(s1.y)};
            __nv_bfloat16 h0x, l0x, h0y, l0y, h1x, l1x, h1y, l1y;
            split_bf(e0.x, h0x, l0x); split_bf(e0.y, h0y, l0y);
            split_bf(e1.x, h1x, l1x); split_bf(e1.y, h1y, l1y);
            *(uint32_t*)(g_Mh + gr0 + col) = pack_bf2(h0x, h0y);
            *(uint32_t*)(g_Ml + gr0 + col) = pack_bf2(l0x, l0y);
            *(uint32_t*)(g_Mh + gr1 + col) = pack_bf2(h1x, h1y);
            *(uint32_t*)(g_Ml + gr1 + col) = pack_bf2(l1x, l1y);
            psum += (e0.x + e0.y) + (e1.x + e1.y);
        }
    }
#pragma unroll
    for (int o = 16; o; o >>= 1) psum += __shfl_xor_sync(0xffffffffu, psum, o);
    if (l == 0) atomicAdd(&g_bs[row0 >> 10], psum);
}

// ---------------- fused sinkhorn + final: cluster 4 CTAs/slice, 512 threads ----------------
#define SINK_SMEM 134144

__global__ void __launch_bounds__(512, 1) __cluster_dims__(4, 1, 1)
k_sinkfinal(float* __restrict__ out) {
    extern __shared__ char smraw[];
    __nv_bfloat16* sM = (__nv_bfloat16*)smraw;          // 256 rows x 256 cols (hi)
    float* su   = (float*)(smraw + 131072);             // 256
    float* sv   = (float*)(smraw + 132096);             // 256
    float* scol = (float*)(smraw + 133120);             // 256
    int t = threadIdx.x, lane = t & 31, w = t >> 5;     // 16 warps
    uint32_t rank;
    asm("mov.u32 %0, %%cluster_ctarank;" : "=r"(rank));
    int bm = blockIdx.x >> 2;
    int mod = bm >> 4;
    uint32_t smb = smem_u32(smraw);
    uint32_t scol_a = smem_u32(scol);
    size_t gbase = ((size_t)bm * 1024 + (size_t)rank * 256) * 256;  // global elem offset of quarter

    // async fill of this CTA's 256-row quarter of Mh (128 KB)
    const uint4* src = (const uint4*)(g_Mh + gbase);
#pragma unroll
    for (int i = 0; i < 16; i++)
        cp_async16(smb + (t + 512 * i) * 16, src + t + 512 * i);
    CP_COMMIT();

    float u0 = 1.0f / (g_bs[bm] + EPS);
    if (t < 256) { su[t] = u0; sv[t] = 1.0f; scol[t] = 0.f; }
    CP_WAIT0();
    __syncthreads();

    // ---- 5 sinkhorn iterations on smem Mh ----
    for (int it = 0; it < 5; it++) {
        float vr[8];
#pragma unroll
        for (int j = 0; j < 8; j++) vr[j] = sv[8 * lane + j];
        float c[8] = {0, 0, 0, 0, 0, 0, 0, 0};
        for (int rr = 0; rr < 16; rr += 2) {
            int row = w * 16 + rr;
            uint4 mv0 = *(const uint4*)(sM + row * 256 + 8 * lane);
            uint4 mv1 = *(const uint4*)(sM + (row + 1) * 256 + 8 * lane);
            float m0[8], m1[8];
            {
                float2 f;
                f = __bfloat1622float2(*(__nv_bfloat162*)&mv0.x); m0[0]=f.x; m0[1]=f.y;
                f = __bfloat1622float2(*(__nv_bfloat162*)&mv0.y); m0[2]=f.x; m0[3]=f.y;
                f = __bfloat1622float2(*(__nv_bfloat162*)&mv0.z); m0[4]=f.x; m0[5]=f.y;
                f = __bfloat1622float2(*(__nv_bfloat162*)&mv0.w); m0[6]=f.x; m0[7]=f.y;
                f = __bfloat1622float2(*(__nv_bfloat162*)&mv1.x); m1[0]=f.x; m1[1]=f.y;
                f = __bfloat1622float2(*(__nv_bfloat162*)&mv1.y); m1[2]=f.x; m1[3]=f.y;
                f = __bfloat1622float2(*(__nv_bfloat162*)&mv1.z); m1[4]=f.x; m1[5]=f.y;
                f = __bfloat1622float2(*(__nv_bfloat162*)&mv1.w); m1[6]=f.x; m1[7]=f.y;
            }
            float d0 = 0.f, d1 = 0.f;
#pragma unroll
            for (int j = 0; j < 8; j++) { d0 = fmaf(m0[j], vr[j], d0); d1 = fmaf(m1[j], vr[j], d1); }
#pragma unroll
            for (int o = 16; o; o >>= 1) {
                d0 += __shfl_xor_sync(0xffffffffu, d0, o);
                d1 += __shfl_xor_sync(0xffffffffu, d1, o);
            }
            float uu0 = su[row], uu1 = su[row + 1];
            float un0 = uu0 * TR / (uu0 * d0 + EPS);
            float un1 = uu1 * TR / (uu1 * d1 + EPS);
            if (lane == 0) { su[row] = un0; su[row + 1] = un1; }
#pragma unroll
            for (int j = 0; j < 8; j++)
                c[j] = fmaf(m0[j], un0, fmaf(m1[j], un1, c[j]));
        }
#pragma unroll
        for (int j = 0; j < 8; j++) atomicAdd(&scol[8 * lane + j], c[j]);
        CLUSTER_SYNC();
        float tot = 0.f;
        if (t < 256) {
#pragma unroll
            for (uint32_t r = 0; r < 4; r++)
                tot += ld_cluster_f32(mapa_u32(scol_a + 4 * t, r));
        }
        CLUSTER_SYNC();
        if (t < 256) {
            float v = sv[t];
            sv[t] = v * TC / (v * tot + EPS);
            scol[t] = 0.f;
        }
        __syncthreads();
    }

    // ---- fused final pass: un, assign (fp32 + bf16 split), colsums ----
    {
        float vr[8];
#pragma unroll
        for (int j = 0; j < 8; j++) vr[j] = sv[8 * lane + j];
        float c[8] = {0, 0, 0, 0, 0, 0, 0, 0};
        int lrow0 = (bm & 15) * 1024 + rank * 256;      // local row within modality
        float* aout = out + (size_t)(2 + mod) * SEG + (size_t)lrow0 * 256;
        for (int rr = 0; rr < 16; rr += 2) {
            int row = w * 16 + rr;
            size_t g0 = gbase + (size_t)row * 256 + 8 * lane;
            size_t g1 = g0 + 256;
            uint4 mv0 = *(const uint4*)(sM + row * 256 + 8 * lane);
            uint4 mv1 = *(const uint4*)(sM + (row + 1) * 256 + 8 * lane);
            uint4 lv0 = *(const uint4*)(g_Ml + g0);
            uint4 lv1 = *(const uint4*)(g_Ml + g1);
            float m0[8], m1[8];
            {
                float2 fh, fl;
                fh = __bfloat1622float2(*(__nv_bfloat162*)&mv0.x);
                fl = __bfloat1622float2(*(__nv_bfloat162*)&lv0.x);
                m0[0] = fh.x + fl.x; m0[1] = fh.y + fl.y;
                fh = __bfloat1622float2(*(__nv_bfloat162*)&mv0.y);
                fl = __bfloat1622float2(*(__nv_bfloat162*)&lv0.y);
                m0[2] = fh.x + fl.x; m0[3] = fh.y + fl.y;
                fh = __bfloat1622float2(*(__nv_bfloat162*)&mv0.z);
                fl = __bfloat1622float2(*(__nv_bfloat162*)&lv0.z);
                m0[4] = fh.x + fl.x; m0[5] = fh.y + fl.y;
                fh = __bfloat1622float2(*(__nv_bfloat162*)&mv0.w);
                fl = __bfloat1622float2(*(__nv_bfloat162*)&lv0.w);
                m0[6] = fh.x + fl.x; m0[7] = fh.y + fl.y;
                fh = __bfloat1622float2(*(__nv_bfloat162*)&mv1.x);
                fl = __bfloat1622float2(*(__nv_bfloat162*)&lv1.x);
                m1[0] = fh.x + fl.x; m1[1] = fh.y + fl.y;
                fh = __bfloat1622float2(*(__nv_bfloat162*)&mv1.y);
                fl = __bfloat1622float2(*(__nv_bfloat162*)&lv1.y);
                m1[2] = fh.x + fl.x; m1[3] = fh.y + fl.y;
                fh = __bfloat1622float2(*(__nv_bfloat162*)&mv1.z);
                fl = __bfloat1622float2(*(__nv_bfloat162*)&lv1.z);
                m1[4] = fh.x + fl.x; m1[5] = fh.y + fl.y;
                fh = __bfloat1622float2(*(__nv_bfloat162*)&mv1.w);
                fl = __bfloat1622float2(*(__nv_bfloat162*)&lv1.w);
                m1[6] = fh.x + fl.x; m1[7] = fh.y + fl.y;
            }
            float d0 = 0.f, d1 = 0.f;
#pragma unroll
            for (int j = 0; j < 8; j++) { d0 = fmaf(m0[j], vr[j], d0); d1 = fmaf(m1[j], vr[j], d1); }
#pragma unroll
            for (int o = 16; o; o >>= 1) {
                d0 += __shfl_xor_sync(0xffffffffu, d0, o);
                d1 += __shfl_xor_sync(0xffffffffu, d1, o);
            }
            float uu0 = su[row], uu1 = su[row + 1];
            float un0 = uu0 / (uu0 * d0 + EPS);
            float un1 = uu1 / (uu1 * d1 + EPS);
            float a0[8], a1[8];
            uint4 ah0, al0, ah1, al1;
            uint32_t* ah0p = (uint32_t*)&ah0; uint32_t* al0p = (uint32_t*)&al0;
            uint32_t* ah1p = (uint32_t*)&ah1; uint32_t* al1p = (uint32_t*)&al1;
#pragma unroll
            for (int j = 0; j < 8; j += 2) {
                a0[j] = m0[j] * un0 * vr[j];
                a0[j + 1] = m0[j + 1] * un0 * vr[j + 1];
                a1[j] = m1[j] * un1 * vr[j];
                a1[j + 1] = m1[j + 1] * un1 * vr[j + 1];
                c[j] += a0[j] + a1[j];
                c[j + 1] += a0[j + 1] + a1[j + 1];
                __nv_bfloat16 h0, l0, h1, l1;
                split_bf(a0[j], h0, l0); split_bf(a0[j + 1], h1, l1);
                ah0p[j >> 1] = pack_bf2(h0, h1);
                al0p[j >> 1] = pack_bf2(l0, l1);
                split_bf(a1[j], h0, l0); split_bf(a1[j + 1], h1, l1);
                ah1p[j >> 1] = pack_bf2(h0, h1);
                al1p[j >> 1] = pack_bf2(l0, l1);
            }
            *(float4*)(aout + (size_t)row * 256 + 8 * lane)           = *(float4*)&a0[0];
            *(float4*)(aout + (size_t)row * 256 + 8 * lane + 4)       = *(float4*)&a0[4];
            *(float4*)(aout + (size_t)(row + 1) * 256 + 8 * lane)     = *(float4*)&a1[0];
            *(float4*)(aout + (size_t)(row + 1) * 256 + 8 * lane + 4) = *(float4*)&a1[4];
            *(uint4*)(g_Ah + g0) = ah0;
            *(uint4*)(g_Al + g0) = al0;
            *(uint4*)(g_Ah + g1) = ah1;
            *(uint4*)(g_Al + g1) = al1;
        }
#pragma unroll
        for (int j = 0; j < 8; j++) atomicAdd(&scol[8 * lane + j], c[j]);
        __syncthreads();
        if (t < 256) atomicAdd(&g_csum2[bm * 256 + t], scol[t]);
    }
}

// ---------------- k_z: z = assign @ Phat, pure-load double-buffered ----------------
#define LOAD_CHUNK(dd, stg) do { \
    _Pragma("unroll") \
    for (int i = 0; i < 8; i++) { \
        int rem = t + 256 * (i & 1); \
        int row = rem >> 2, c16 = rem & 3; \
        cp_async16(smb + (stg) + (i >> 1) * 10240 + row * 80 + c16 * 16, \
                   parts[i >> 1] + (size_t)row * 256 + (dd) + c16 * 8); \
    } \
    CP_COMMIT(); \
} while (0)

__global__ __launch_bounds__(256, 2)
void k_z(float* __restrict__ out) {
    extern __shared__ char dsm[];
    int t = threadIdx.x, l = t & 31, w = t >> 5;
    int wm = w >> 1, wn = w & 1;
    int bx = blockIdx.x;
    int row0 = (bx >> 1) * 128;
    int col0 = (bx & 1) * 128;
    int mod = row0 >> 14;

    const __nv_bfloat16* parts[4] = {
        g_Ah + (size_t)row0 * 256,
        g_Al + (size_t)row0 * 256,
        g_pth + mod * 65536 + (size_t)col0 * 256,
        g_ptl + mod * 65536 + (size_t)col0 * 256
    };
    uint32_t smb = smem_u32(dsm);
    uint32_t a_off = (uint32_t)(wm * 32 + (l & 7) + 8 * ((l >> 3) & 1)) * 80
                   + ((l >> 4) & 1) * 16;
    uint32_t b_off = (uint32_t)(wn * 64 + (l & 7) + 8 * ((l >> 4) & 1)) * 80
                   + ((l >> 3) & 1) * 16;

    float acc[2][8][4];
#pragma unroll
    for (int a = 0; a < 2; a++)
#pragma unroll
        for (int b = 0; b < 8; b++)
#pragma unroll
            for (int d = 0; d < 4; d++) acc[a][b][d] = 0.f;

    LOAD_CHUNK(0, 0);
    for (int c = 0; c < 8; c++) {
        int buf = c & 1;
        if (c < 7) { LOAD_CHUNK((c + 1) * 32, (buf ^ 1) * STG); CP_WAIT1(); }
        else       { CP_WAIT0(); }
        __syncthreads();
        uint32_t sb = smb + buf * STG;
        DO_MMA(sb);
        __syncthreads();
    }

    float* zb = out + (size_t)mod * SEG;
#pragma unroll
    for (int tm = 0; tm < 2; tm++) {
        int r0 = row0 + wm * 32 + tm * 16 + (l >> 2);
        size_t lr0 = (size_t)(r0 & 16383) * 256, lr1 = lr0 + 8 * 256;
#pragma unroll
        for (int nt = 0; nt < 8; nt++) {
            int col = col0 + wn * 64 + nt * 8 + 2 * (l & 3);
            float* d = acc[tm][nt];
            float2 v0 = {d[0], d[1]}, v1 = {d[2], d[3]};
            *(float2*)(zb + lr0 + col) = v0;
            *(float2*)(zb + lr1 + col) = v1;
        }
    }

    // sem_consistency once (csum2 complete from k_sinkfinal)
    if (bx == 0) {
        __shared__ float red[8];
        float accs = 0.f;
#pragma unroll
        for (int b = 0; b < 16; b++)
            accs += g_csum2[b * 256 + t] * g_csum2[4096 + b * 256 + t];
#pragma unroll
        for (int o = 16; o; o >>= 1) accs += __shfl_xor_sync(0xffffffffu, accs, o);
        if (l == 0) red[w] = accs;
        __syncthreads();
        if (t == 0) {
            float tot = 0.f;
            for (int i = 0; i < 8; i++) tot += red[i];
            float m = tot * (1.0f / 16777216.0f);
            m = fminf(fmaxf(m, 0.f), 1.f);
            out[(size_t)6 * SEG] = 1.0f - m;
        }
    }
}

// ---------------- launch ----------------
extern "C" void kernel_launch(void* const* d_in, const int* in_sizes, int n_in,
                              void* d_out, int out_size) {
    const float* f_rgb = (const float*)d_in[0];
    const float* f_sn  = (const float*)d_in[1];
    const float* p_rgb = (const float*)d_in[2];
    const float* p_sn  = (const float*)d_in[3];
    float* out = (float*)d_out;

    cudaFuncSetAttribute(k_sinkfinal, cudaFuncAttributeMaxDynamicSharedMemorySize, SINK_SMEM);
    cudaFuncSetAttribute(k_gemm_sim,  cudaFuncAttributeMaxDynamicSharedMemorySize, GSMEM);
    cudaFuncSetAttribute(k_z,         cudaFuncAttributeMaxDynamicSharedMemorySize, GSMEM);

    k_proto<<<64, 256>>>(p_rgb, p_sn);
    k_gemm_sim<<<512, 256, GSMEM>>>(f_rgb, f_sn, out);
    k_sinkfinal<<<128, 512, SINK_SMEM>>>(out);
    k_z<<<512, 256, GSMEM>>>(out);
}

// round 13
// speedup vs baseline: 1.3758x; 1.0953x over previous
#include <cuda_runtime.h>
#include <cuda_bf16.h>
#include <math.h>
#include <stdint.h>

#define EPS 1e-8f
#define TR  (1.0f/1024.0f)
#define TC  (1.0f/256.0f)
#define SEG 4194304            // 16*1024*256

// ---------------- scratch (device globals; no allocation) ----------------
__device__ __align__(16) __nv_bfloat16 g_Mh[8388608];   // M = exp(sim/tau) hi
__device__ __align__(16) __nv_bfloat16 g_Ml[8388608];   // M lo
__device__ __align__(16) __nv_bfloat16 g_Ah[8388608];   // assign hi
__device__ __align__(16) __nv_bfloat16 g_Al[8388608];   // assign lo
__device__ __align__(16) __nv_bfloat16 g_pbh[131072];   // proto normalized hi [2][k][d]
__device__ __align__(16) __nv_bfloat16 g_pbl[131072];
__device__ __align__(16) __nv_bfloat16 g_pth[131072];   // proto^T hi [2][d][k]
__device__ __align__(16) __nv_bfloat16 g_ptl[131072];
__device__ float g_csum2[8192];
__device__ float g_bs[32];

// exp(20*s) via 2^y, FFMA-only
__device__ __forceinline__ float exp20(float s) {
    float y  = s * 28.853900817779268f;
    float fl = floorf(y);
    float f  = y - fl;
    float p = 1.5252733804059840e-05f;
    p = fmaf(p, f, 1.5403530393381609e-04f);
    p = fmaf(p, f, 1.3333558146428443e-03f);
    p = fmaf(p, f, 9.6181291076284772e-03f);
    p = fmaf(p, f, 5.5504108664821580e-02f);
    p = fmaf(p, f, 2.4022650695910071e-01f);
    p = fmaf(p, f, 6.9314718055994531e-01f);
    p = fmaf(p, f, 1.0f);
    int e = (int)fl + 127;
    return p * __int_as_float(e << 23);
}

__device__ __forceinline__ uint32_t smem_u32(const void* p) {
    uint32_t a;
    asm("{ .reg .u64 t; cvta.to.shared.u64 t, %1; cvt.u32.u64 %0, t; }" : "=r"(a) : "l"(p));
    return a;
}
__device__ __forceinline__ void ldmx4(uint32_t* r, uint32_t addr) {
    asm volatile("ldmatrix.sync.aligned.m8n8.x4.shared.b16 {%0,%1,%2,%3}, [%4];"
                 : "=r"(r[0]), "=r"(r[1]), "=r"(r[2]), "=r"(r[3]) : "r"(addr));
}
__device__ __forceinline__ void mma16816(float* d, const uint32_t* a, const uint32_t* b) {
    asm volatile("mma.sync.aligned.m16n8k16.row.col.f32.bf16.bf16.f32 "
                 "{%0,%1,%2,%3}, {%4,%5,%6,%7}, {%8,%9}, {%0,%1,%2,%3};"
                 : "+f"(d[0]), "+f"(d[1]), "+f"(d[2]), "+f"(d[3])
                 : "r"(a[0]), "r"(a[1]), "r"(a[2]), "r"(a[3]), "r"(b[0]), "r"(b[1]));
}
__device__ __forceinline__ uint32_t pack_bf2(__nv_bfloat16 lo, __nv_bfloat16 hi) {
    __nv_bfloat162 t; t.x = lo; t.y = hi;
    uint32_t r; memcpy(&r, &t, 4); return r;
}
__device__ __forceinline__ void split_bf(float x, __nv_bfloat16& h, __nv_bfloat16& l) {
    h = __float2bfloat16_rn(x);
    l = __float2bfloat16_rn(x - __bfloat162float(h));
}
__device__ __forceinline__ void cp_async16(uint32_t smem, const void* g) {
    asm volatile("cp.async.cg.shared.global [%0], [%1], 16;" :: "r"(smem), "l"(g));
}
#define CP_COMMIT() asm volatile("cp.async.commit_group;" ::: "memory")
#define CP_WAIT0()  asm volatile("cp.async.wait_group 0;" ::: "memory")
#define CP_WAIT1()  asm volatile("cp.async.wait_group 1;" ::: "memory")
__device__ __forceinline__ uint32_t mapa_u32(uint32_t a, uint32_t r) {
    uint32_t d;
    asm("mapa.shared::cluster.u32 %0, %1, %2;" : "=r"(d) : "r"(a), "r"(r));
    return d;
}
__device__ __forceinline__ float ld_cluster_f32(uint32_t a) {
    float v;
    asm volatile("ld.shared::cluster.b32 %0, [%1];" : "=f"(v) : "r"(a));
    return v;
}
#define CLUSTER_SYNC() do { \
    asm volatile("barrier.cluster.arrive.aligned;" ::: "memory"); \
    asm volatile("barrier.cluster.wait.aligned;"   ::: "memory"); \
} while (0)

// ---------------- setup ----------------
__global__ void k_proto(const float* __restrict__ p_rgb, const float* __restrict__ p_sn) {
    int gt = blockIdx.x * blockDim.x + threadIdx.x;
    if (gt < 8192) g_csum2[gt] = 0.f;
    if (gt < 32)   g_bs[gt] = 0.f;

    int warp = gt >> 5;
    int lane = threadIdx.x & 31;
    int mod = warp >> 8, row = warp & 255;
    const float* src = (mod ? p_sn : p_rgb) + row * 256;
    float v[8], s = 0.f;
#pragma unroll
    for (int j = 0; j < 8; j++) { v[j] = src[lane + 32 * j]; s += v[j] * v[j]; }
#pragma unroll
    for (int o = 16; o; o >>= 1) s += __shfl_xor_sync(0xffffffffu, s, o);
    float inv = 1.0f / (sqrtf(s) + EPS);
    int base = mod * 65536;
#pragma unroll
    for (int j = 0; j < 8; j++) {
        int col = lane + 32 * j;
        float val = v[j] * inv;
        __nv_bfloat16 h, l;
        split_bf(val, h, l);
        g_pbh[base + row * 256 + col] = h;
        g_pbl[base + row * 256 + col] = l;
        g_pth[base + col * 256 + row] = h;
        g_ptl[base + col * 256 + row] = l;
    }
}

// ---------------- GEMM machinery (round-9/11 proven) ----------------
#define STG   40960
#define GSMEM 81920

#define DO_MMA(sb) do { \
    _Pragma("unroll") \
    for (int ks = 0; ks < 2; ks++) { \
        uint32_t kb = ks * 32; \
        uint32_t aH[2][4], aL[2][4]; \
        ldmx4(aH[0], (sb) + a_off + kb); \
        ldmx4(aH[1], (sb) + a_off + 16 * 80 + kb); \
        ldmx4(aL[0], (sb) + 10240 + a_off + kb); \
        ldmx4(aL[1], (sb) + 10240 + a_off + 16 * 80 + kb); \
        _Pragma("unroll") \
        for (int np = 0; np < 4; np++) { \
            uint32_t bo = b_off + (uint32_t)np * 16 * 80 + kb; \
            uint32_t bH[4], bL[4]; \
            ldmx4(bH, (sb) + 20480 + bo); \
            ldmx4(bL, (sb) + 30720 + bo); \
            _Pragma("unroll") \
            for (int tm = 0; tm < 2; tm++) { \
                mma16816(acc[tm][2 * np],     aH[tm], bH); \
                mma16816(acc[tm][2 * np],     aH[tm], bL); \
                mma16816(acc[tm][2 * np],     aL[tm], bH); \
                mma16816(acc[tm][2 * np + 1], aH[tm], bH + 2); \
                mma16816(acc[tm][2 * np + 1], aH[tm], bL + 2); \
                mma16816(acc[tm][2 * np + 1], aL[tm], bH + 2); \
            } \
        } \
    } \
} while (0)

#define B_CPASYNC(dd, stg_off) do { \
    _Pragma("unroll") \
    for (int i = 0; i < 4; i++) { \
        int idx = t + 256 * i; \
        int part = idx >> 9, row = (idx >> 2) & 127, c8 = idx & 3; \
        const __nv_bfloat16* srcp = (part ? Blp : Bhp) + (size_t)row * 256 + (dd) + 8 * c8; \
        cp_async16(smb + (stg_off) + (part ? 30720 : 20480) + row * 80 + c8 * 16, srcp); \
    } \
    CP_COMMIT(); \
} while (0)

__global__ __launch_bounds__(256, 2)
void k_gemm_sim(const float* __restrict__ f_rgb, const float* __restrict__ f_sn,
                float* __restrict__ out) {
    extern __shared__ char dsm[];
    __shared__ float sSq[128];
    int t = threadIdx.x, l = t & 31, w = t >> 5;
    int wm = w >> 1, wn = w & 1;
    int bx = blockIdx.x;
    int row0 = (bx >> 1) * 128;
    int col0 = (bx & 1) * 128;
    int mod = row0 >> 14, lrow0 = row0 & 16383;
    const float* X = (mod ? f_sn : f_rgb) + (size_t)lrow0 * 256;
    const __nv_bfloat16* Bhp = g_pbh + mod * 65536 + (size_t)col0 * 256;
    const __nv_bfloat16* Blp = g_pbl + mod * 65536 + (size_t)col0 * 256;

    uint32_t smb = smem_u32(dsm);
    uint32_t a_off = (uint32_t)(wm * 32 + (l & 7) + 8 * ((l >> 3) & 1)) * 80
                   + ((l >> 4) & 1) * 16;
    uint32_t b_off = (uint32_t)(wn * 64 + (l & 7) + 8 * ((l >> 4) & 1)) * 80
                   + ((l >> 3) & 1) * 16;

    float acc[2][8][4];
#pragma unroll
    for (int a = 0; a < 2; a++)
#pragma unroll
        for (int b = 0; b < 8; b++)
#pragma unroll
            for (int d = 0; d < 4; d++) acc[a][b][d] = 0.f;
    float ss[4] = {0.f, 0.f, 0.f, 0.f};
    float4 aReg[4];

#pragma unroll
    for (int i = 0; i < 4; i++) {
        int idx = t + 256 * i;
        aReg[i] = *(const float4*)(X + (size_t)(idx >> 3) * 256 + 4 * (idx & 7));
    }
    B_CPASYNC(0, 0);
#pragma unroll
    for (int i = 0; i < 4; i++) {
        int idx = t + 256 * i;
        int row = idx >> 3, c4 = idx & 7;
        float4 v = aReg[i];
        ss[i] += v.x * v.x + v.y * v.y + v.z * v.z + v.w * v.w;
        __nv_bfloat16 hx, lx, hy, ly, hz, lz, hw, lw;
        split_bf(v.x, hx, lx); split_bf(v.y, hy, ly);
        split_bf(v.z, hz, lz); split_bf(v.w, hw, lw);
        uint2 ph, pl;
        ph.x = pack_bf2(hx, hy); ph.y = pack_bf2(hz, hw);
        pl.x = pack_bf2(lx, ly); pl.y = pack_bf2(lz, lw);
        int sob = row * 80 + c4 * 8;
        *(uint2*)(dsm + sob) = ph;
        *(uint2*)(dsm + 10240 + sob) = pl;
    }
    CP_WAIT0();
    __syncthreads();

#pragma unroll 2
    for (int c = 0; c < 8; c++) {
        int buf = c & 1, nbuf = buf ^ 1;
        if (c < 7) {
            int dd = (c + 1) * 32;
#pragma unroll
            for (int i = 0; i < 4; i++) {
                int idx = t + 256 * i;
                aReg[i] = *(const float4*)(X + (size_t)(idx >> 3) * 256 + dd + 4 * (idx & 7));
            }
            B_CPASYNC(dd, nbuf * STG);
        }
        uint32_t sb = smb + buf * STG;
        DO_MMA(sb);
        if (c < 7) {
            char* stg = dsm + nbuf * STG;
#pragma unroll
            for (int i = 0; i < 4; i++) {
                int idx = t + 256 * i;
                int row = idx >> 3, c4 = idx & 7;
                float4 v = aReg[i];
                ss[i] += v.x * v.x + v.y * v.y + v.z * v.z + v.w * v.w;
                __nv_bfloat16 hx, lx, hy, ly, hz, lz, hw, lw;
                split_bf(v.x, hx, lx); split_bf(v.y, hy, ly);
                split_bf(v.z, hz, lz); split_bf(v.w, hw, lw);
                uint2 ph, pl;
                ph.x = pack_bf2(hx, hy); ph.y = pack_bf2(hz, hw);
                pl.x = pack_bf2(lx, ly); pl.y = pack_bf2(lz, lw);
                int sob = row * 80 + c4 * 8;
                *(uint2*)(stg + sob) = ph;
                *(uint2*)(stg + 10240 + sob) = pl;
            }
            CP_WAIT0();
        }
        __syncthreads();
    }

#pragma unroll
    for (int i = 0; i < 4; i++) {
        ss[i] += __shfl_xor_sync(0xffffffffu, ss[i], 1);
        ss[i] += __shfl_xor_sync(0xffffffffu, ss[i], 2);
        ss[i] += __shfl_xor_sync(0xffffffffu, ss[i], 4);
    }
    if ((t & 7) == 0) {
#pragma unroll
        for (int i = 0; i < 4; i++)
            sSq[(t >> 3) + 32 * i] = ss[i];
    }
    __syncthreads();

    float* simb = out + (size_t)(4 + mod) * SEG;
    float psum = 0.f;
#pragma unroll
    for (int tm = 0; tm < 2; tm++) {
        int tr0 = wm * 32 + tm * 16 + (l >> 2);
        int r0 = row0 + tr0, r1 = r0 + 8;
        float xi0 = 1.0f / (sqrtf(sSq[tr0]) + EPS);
        float xi1 = 1.0f / (sqrtf(sSq[tr0 + 8]) + EPS);
        size_t lr0 = (size_t)(r0 & 16383) * 256, lr1 = (size_t)(r1 & 16383) * 256;
        size_t gr0 = (size_t)r0 * 256, gr1 = (size_t)r1 * 256;
#pragma unroll
        for (int nt = 0; nt < 8; nt++) {
            int col = col0 + wn * 64 + nt * 8 + 2 * (l & 3);
            float* d = acc[tm][nt];
            float2 s0 = {d[0] * xi0, d[1] * xi0};
            float2 s1 = {d[2] * xi1, d[3] * xi1};
            *(float2*)(simb + lr0 + col) = s0;
            *(float2*)(simb + lr1 + col) = s1;
            float2 e0 = {exp20(s0.x), exp20(s0.y)};
            float2 e1 = {exp20(s1.x), exp20(s1.y)};
            __nv_bfloat16 h0x, l0x, h0y, l0y, h1x, l1x, h1y, l1y;
            split_bf(e0.x, h0x, l0x); split_bf(e0.y, h0y, l0y);
            split_bf(e1.x, h1x, l1x); split_bf(e1.y, h1y, l1y);
            *(uint32_t*)(g_Mh + gr0 + col) = pack_bf2(h0x, h0y);
            *(uint32_t*)(g_Ml + gr0 + col) = pack_bf2(l0x, l0y);
            *(uint32_t*)(g_Mh + gr1 + col) = pack_bf2(h1x, h1y);
            *(uint32_t*)(g_Ml + gr1 + col) = pack_bf2(l1x, l1y);
            psum += (e0.x + e0.y) + (e1.x + e1.y);
        }
    }
#pragma unroll
    for (int o = 16; o; o >>= 1) psum += __shfl_xor_sync(0xffffffffu, psum, o);
    if (l == 0) atomicAdd(&g_bs[row0 >> 10], psum);
}

// ---------------- fused sinkhorn + final: cluster 4 CTAs/slice, 512 threads ----------------
// smem: sM 131072 | su 1024 | sv 1024 | scol[2] 2048 | wbuf 16384 = 151552
#define SINK_SMEM 151552

__global__ void __launch_bounds__(512, 1) __cluster_dims__(4, 1, 1)
k_sinkfinal(float* __restrict__ out) {
    extern __shared__ char smraw[];
    __nv_bfloat16* sM = (__nv_bfloat16*)smraw;          // 256 rows x 256 cols (hi)
    float* su    = (float*)(smraw + 131072);            // 256
    float* sv    = (float*)(smraw + 132096);            // 256
    float* scolb = (float*)(smraw + 133120);            // 2 x 256
    float* wbuf  = (float*)(smraw + 135168);            // 16 x 256
    int t = threadIdx.x, lane = t & 31, w = t >> 5;     // 16 warps
    uint32_t rank;
    asm("mov.u32 %0, %%cluster_ctarank;" : "=r"(rank));
    int bm = blockIdx.x >> 2;
    int mod = bm >> 4;
    uint32_t smb = smem_u32(smraw);
    size_t gbase = ((size_t)bm * 1024 + (size_t)rank * 256) * 256;

    // async fill of this CTA's 256-row quarter of Mh (128 KB)
    const uint4* src = (const uint4*)(g_Mh + gbase);
#pragma unroll
    for (int i = 0; i < 16; i++)
        cp_async16(smb + (t + 512 * i) * 16, src + t + 512 * i);
    CP_COMMIT();

    float u0 = 1.0f / (g_bs[bm] + EPS);
    if (t < 256) { su[t] = u0; sv[t] = 1.0f; }
    CP_WAIT0();
    __syncthreads();

    // ---- 5 sinkhorn iterations on smem Mh ----
    for (int it = 0; it < 5; it++) {
        float* scol = scolb + (it & 1) * 256;
        uint32_t scol_a = smem_u32(scol);
        float vr[8];
#pragma unroll
        for (int j = 0; j < 8; j++) vr[j] = sv[8 * lane + j];
        float c[8] = {0, 0, 0, 0, 0, 0, 0, 0};
        for (int rr = 0; rr < 16; rr += 2) {
            int row = w * 16 + rr;
            uint4 mv0 = *(const uint4*)(sM + row * 256 + 8 * lane);
            uint4 mv1 = *(const uint4*)(sM + (row + 1) * 256 + 8 * lane);
            float m0[8], m1[8];
            {
                float2 f;
                f = __bfloat1622float2(*(__nv_bfloat162*)&mv0.x); m0[0]=f.x; m0[1]=f.y;
                f = __bfloat1622float2(*(__nv_bfloat162*)&mv0.y); m0[2]=f.x; m0[3]=f.y;
                f = __bfloat1622float2(*(__nv_bfloat162*)&mv0.z); m0[4]=f.x; m0[5]=f.y;
                f = __bfloat1622float2(*(__nv_bfloat162*)&mv0.w); m0[6]=f.x; m0[7]=f.y;
                f = __bfloat1622float2(*(__nv_bfloat162*)&mv1.x); m1[0]=f.x; m1[1]=f.y;
                f = __bfloat1622float2(*(__nv_bfloat162*)&mv1.y); m1[2]=f.x; m1[3]=f.y;
                f = __bfloat1622float2(*(__nv_bfloat162*)&mv1.z); m1[4]=f.x; m1[5]=f.y;
                f = __bfloat1622float2(*(__nv_bfloat162*)&mv1.w); m1[6]=f.x; m1[7]=f.y;
            }
            float d0 = 0.f, d1 = 0.f;
#pragma unroll
            for (int j = 0; j < 8; j++) { d0 = fmaf(m0[j], vr[j], d0); d1 = fmaf(m1[j], vr[j], d1); }
#pragma unroll
            for (int o = 16; o; o >>= 1) {
                d0 += __shfl_xor_sync(0xffffffffu, d0, o);
                d1 += __shfl_xor_sync(0xffffffffu, d1, o);
            }
            float uu0 = su[row], uu1 = su[row + 1];
            float un0 = uu0 * TR / (uu0 * d0 + EPS);
            float un1 = uu1 * TR / (uu1 * d1 + EPS);
            if (lane == 0) { su[row] = un0; su[row + 1] = un1; }
#pragma unroll
            for (int j = 0; j < 8; j++)
                c[j] = fmaf(m0[j], un0, fmaf(m1[j], un1, c[j]));
        }
        // conflict-free per-warp staging (2x STS.128 per lane)
        *(float4*)&wbuf[w * 256 + 8 * lane]     = *(float4*)&c[0];
        *(float4*)&wbuf[w * 256 + 8 * lane + 4] = *(float4*)&c[4];
        __syncthreads();
        if (t < 256) {
            float tot = 0.f;
#pragma unroll
            for (int ww = 0; ww < 16; ww++) tot += wbuf[ww * 256 + t];
            scol[t] = tot;
        }
        CLUSTER_SYNC();                   // scol (this parity) complete across cluster
        if (t < 256) {
            float tot = 0.f;
#pragma unroll
            for (uint32_t r = 0; r < 4; r++)
                tot += ld_cluster_f32(mapa_u32(scol_a + 4 * t, r));
            float v = sv[t];
            sv[t] = v * TC / (v * tot + EPS);
        }
        __syncthreads();
    }

    // ---- fused final pass: un, assign (fp32 + bf16 split), colsums ----
    {
        float vr[8];
#pragma unroll
        for (int j = 0; j < 8; j++) vr[j] = sv[8 * lane + j];
        float c[8] = {0, 0, 0, 0, 0, 0, 0, 0};
        int lrow0 = (bm & 15) * 1024 + rank * 256;
        float* aout = out + (size_t)(2 + mod) * SEG + (size_t)lrow0 * 256;
        for (int rr = 0; rr < 16; rr += 2) {
            int row = w * 16 + rr;
            size_t g0 = gbase + (size_t)row * 256 + 8 * lane;
            size_t g1 = g0 + 256;
            uint4 mv0 = *(const uint4*)(sM + row * 256 + 8 * lane);
            uint4 mv1 = *(const uint4*)(sM + (row + 1) * 256 + 8 * lane);
            uint4 lv0 = *(const uint4*)(g_Ml + g0);
            uint4 lv1 = *(const uint4*)(g_Ml + g1);
            float m0[8], m1[8];
            {
                float2 fh, fl;
                fh = __bfloat1622float2(*(__nv_bfloat162*)&mv0.x);
                fl = __bfloat1622float2(*(__nv_bfloat162*)&lv0.x);
                m0[0] = fh.x + fl.x; m0[1] = fh.y + fl.y;
                fh = __bfloat1622float2(*(__nv_bfloat162*)&mv0.y);
                fl = __bfloat1622float2(*(__nv_bfloat162*)&lv0.y);
                m0[2] = fh.x + fl.x; m0[3] = fh.y + fl.y;
                fh = __bfloat1622float2(*(__nv_bfloat162*)&mv0.z);
                fl = __bfloat1622float2(*(__nv_bfloat162*)&lv0.z);
                m0[4] = fh.x + fl.x; m0[5] = fh.y + fl.y;
                fh = __bfloat1622float2(*(__nv_bfloat162*)&mv0.w);
                fl = __bfloat1622float2(*(__nv_bfloat162*)&lv0.w);
                m0[6] = fh.x + fl.x; m0[7] = fh.y + fl.y;
                fh = __bfloat1622float2(*(__nv_bfloat162*)&mv1.x);
                fl = __bfloat1622float2(*(__nv_bfloat162*)&lv1.x);
                m1[0] = fh.x + fl.x; m1[1] = fh.y + fl.y;
                fh = __bfloat1622float2(*(__nv_bfloat162*)&mv1.y);
                fl = __bfloat1622float2(*(__nv_bfloat162*)&lv1.y);
                m1[2] = fh.x + fl.x; m1[3] = fh.y + fl.y;
                fh = __bfloat1622float2(*(__nv_bfloat162*)&mv1.z);
                fl = __bfloat1622float2(*(__nv_bfloat162*)&lv1.z);
                m1[4] = fh.x + fl.x; m1[5] = fh.y + fl.y;
                fh = __bfloat1622float2(*(__nv_bfloat162*)&mv1.w);
                fl = __bfloat1622float2(*(__nv_bfloat162*)&lv1.w);
                m1[6] = fh.x + fl.x; m1[7] = fh.y + fl.y;
            }
            float d0 = 0.f, d1 = 0.f;
#pragma unroll
            for (int j = 0; j < 8; j++) { d0 = fmaf(m0[j], vr[j], d0); d1 = fmaf(m1[j], vr[j], d1); }
#pragma unroll
            for (int o = 16; o; o >>= 1) {
                d0 += __shfl_xor_sync(0xffffffffu, d0, o);
                d1 += __shfl_xor_sync(0xffffffffu, d1, o);
            }
            float uu0 = su[row], uu1 = su[row + 1];
            float un0 = uu0 / (uu0 * d0 + EPS);
            float un1 = uu1 / (uu1 * d1 + EPS);
            float a0[8], a1[8];
            uint4 ah0, al0, ah1, al1;
            uint32_t* ah0p = (uint32_t*)&ah0; uint32_t* al0p = (uint32_t*)&al0;
            uint32_t* ah1p = (uint32_t*)&ah1; uint32_t* al1p = (uint32_t*)&al1;
#pragma unroll
            for (int j = 0; j < 8; j += 2) {
                a0[j] = m0[j] * un0 * vr[j];
                a0[j + 1] = m0[j + 1] * un0 * vr[j + 1];
                a1[j] = m1[j] * un1 * vr[j];
                a1[j + 1] = m1[j + 1] * un1 * vr[j + 1];
                c[j] += a0[j] + a1[j];
                c[j + 1] += a0[j + 1] + a1[j + 1];
                __nv_bfloat16 h0, l0, h1, l1;
                split_bf(a0[j], h0, l0); split_bf(a0[j + 1], h1, l1);
                ah0p[j >> 1] = pack_bf2(h0, h1);
                al0p[j >> 1] = pack_bf2(l0, l1);
                split_bf(a1[j], h0, l0); split_bf(a1[j + 1], h1, l1);
                ah1p[j >> 1] = pack_bf2(h0, h1);
                al1p[j >> 1] = pack_bf2(l0, l1);
            }
            *(float4*)(aout + (size_t)row * 256 + 8 * lane)           = *(float4*)&a0[0];
            *(float4*)(aout + (size_t)row * 256 + 8 * lane + 4)       = *(float4*)&a0[4];
            *(float4*)(aout + (size_t)(row + 1) * 256 + 8 * lane)     = *(float4*)&a1[0];
            *(float4*)(aout + (size_t)(row + 1) * 256 + 8 * lane + 4) = *(float4*)&a1[4];
            *(uint4*)(g_Ah + g0) = ah0;
            *(uint4*)(g_Al + g0) = al0;
            *(uint4*)(g_Ah + g1) = ah1;
            *(uint4*)(g_Al + g1) = al1;
        }
        // staged colsum reduction, then one global atomic per column
        *(float4*)&wbuf[w * 256 + 8 * lane]     = *(float4*)&c[0];
        *(float4*)&wbuf[w * 256 + 8 * lane + 4] = *(float4*)&c[4];
        __syncthreads();
        if (t < 256) {
            float tot = 0.f;
#pragma unroll
            for (int ww = 0; ww < 16; ww++) tot += wbuf[ww * 256 + t];
            atomicAdd(&g_csum2[bm * 256 + t], tot);
        }
    }
}

// ---------------- k_z: z = assign @ Phat, pure-load double-buffered ----------------
#define LOAD_CHUNK(dd, stg) do { \
    _Pragma("unroll") \
    for (int i = 0; i < 8; i++) { \
        int rem = t + 256 * (i & 1); \
        int row = rem >> 2, c16 = rem & 3; \
        cp_async16(smb + (stg) + (i >> 1) * 10240 + row * 80 + c16 * 16, \
                   parts[i >> 1] + (size_t)row * 256 + (dd) + c16 * 8); \
    } \
    CP_COMMIT(); \
} while (0)

__global__ __launch_bounds__(256, 2)
void k_z(float* __restrict__ out) {
    extern __shared__ char dsm[];
    int t = threadIdx.x, l = t & 31, w = t >> 5;
    int wm = w >> 1, wn = w & 1;
    int bx = blockIdx.x;
    int row0 = (bx >> 1) * 128;
    int col0 = (bx & 1) * 128;
    int mod = row0 >> 14;

    const __nv_bfloat16* parts[4] = {
        g_Ah + (size_t)row0 * 256,
        g_Al + (size_t)row0 * 256,
        g_pth + mod * 65536 + (size_t)col0 * 256,
        g_ptl + mod * 65536 + (size_t)col0 * 256
    };
    uint32_t smb = smem_u32(dsm);
    uint32_t a_off = (uint32_t)(wm * 32 + (l & 7) + 8 * ((l >> 3) & 1)) * 80
                   + ((l >> 4) & 1) * 16;
    uint32_t b_off = (uint32_t)(wn * 64 + (l & 7) + 8 * ((l >> 4) & 1)) * 80
                   + ((l >> 3) & 1) * 16;

    float acc[2][8][4];
#pragma unroll
    for (int a = 0; a < 2; a++)
#pragma unroll
        for (int b = 0; b < 8; b++)
#pragma unroll
            for (int d = 0; d < 4; d++) acc[a][b][d] = 0.f;

    LOAD_CHUNK(0, 0);
    for (int c = 0; c < 8; c++) {
        int buf = c & 1;
        if (c < 7) { LOAD_CHUNK((c + 1) * 32, (buf ^ 1) * STG); CP_WAIT1(); }
        else       { CP_WAIT0(); }
        __syncthreads();
        uint32_t sb = smb + buf * STG;
        DO_MMA(sb);
        __syncthreads();
    }

    float* zb = out + (size_t)mod * SEG;
#pragma unroll
    for (int tm = 0; tm < 2; tm++) {
        int r0 = row0 + wm * 32 + tm * 16 + (l >> 2);
        size_t lr0 = (size_t)(r0 & 16383) * 256, lr1 = lr0 + 8 * 256;
#pragma unroll
        for (int nt = 0; nt < 8; nt++) {
            int col = col0 + wn * 64 + nt * 8 + 2 * (l & 3);
            float* d = acc[tm][nt];
            float2 v0 = {d[0], d[1]}, v1 = {d[2], d[3]};
            *(float2*)(zb + lr0 + col) = v0;
            *(float2*)(zb + lr1 + col) = v1;
        }
    }

    if (bx == 0) {
        __shared__ float red[8];
        float accs = 0.f;
#pragma unroll
        for (int b = 0; b < 16; b++)
            accs += g_csum2[b * 256 + t] * g_csum2[4096 + b * 256 + t];
#pragma unroll
        for (int o = 16; o; o >>= 1) accs += __shfl_xor_sync(0xffffffffu, accs, o);
        if (l == 0) red[w] = accs;
        __syncthreads();
        if (t == 0) {
            float tot = 0.f;
            for (int i = 0; i < 8; i++) tot += red[i];
            float m = tot * (1.0f / 16777216.0f);
            m = fminf(fmaxf(m, 0.f), 1.f);
            out[(size_t)6 * SEG] = 1.0f - m;
        }
    }
}

// ---------------- launch ----------------
extern "C" void kernel_launch(void* const* d_in, const int* in_sizes, int n_in,
                              void* d_out, int out_size) {
    const float* f_rgb = (const float*)d_in[0];
    const float* f_sn  = (const float*)d_in[1];
    const float* p_rgb = (const float*)d_in[2];
    const float* p_sn  = (const float*)d_in[3];
    float* out = (float*)d_out;

    cudaFuncSetAttribute(k_sinkfinal, cudaFuncAttributeMaxDynamicSharedMemorySize, SINK_SMEM);
    cudaFuncSetAttribute(k_gemm_sim,  cudaFuncAttributeMaxDynamicSharedMemorySize, GSMEM);
    cudaFuncSetAttribute(k_z,         cudaFuncAttributeMaxDynamicSharedMemorySize, GSMEM);

    k_proto<<<64, 256>>>(p_rgb, p_sn);
    k_gemm_sim<<<512, 256, GSMEM>>>(f_rgb, f_sn, out);
    k_sinkfinal<<<128, 512, SINK_SMEM>>>(out);
    k_z<<<512, 256, GSMEM>>>(out);
}

// round 14
// speedup vs baseline: 1.3779x; 1.0015x over previous
#include <cuda_runtime.h>
#include <cuda_bf16.h>
#include <math.h>
#include <stdint.h>

#define EPS 1e-8f
#define TR  (1.0f/1024.0f)
#define TC  (1.0f/256.0f)
#define SEG 4194304            // 16*1024*256

// ---------------- scratch (device globals; no allocation) ----------------
__device__ __align__(16) __nv_bfloat16 g_Mh[8388608];   // M = exp(sim/tau) hi
__device__ __align__(16) __nv_bfloat16 g_Ml[8388608];   // M lo
__device__ __align__(16) __nv_bfloat16 g_Ah[8388608];   // assign hi
__device__ __align__(16) __nv_bfloat16 g_Al[8388608];   // assign lo
__device__ __align__(16) __nv_bfloat16 g_pbh[131072];   // proto normalized hi [2][k][d]
__device__ __align__(16) __nv_bfloat16 g_pbl[131072];
__device__ __align__(16) __nv_bfloat16 g_pth[131072];   // proto^T hi [2][d][k]
__device__ __align__(16) __nv_bfloat16 g_ptl[131072];
__device__ float g_csum2[8192];
__device__ float g_bs[32];

// exp(20*s) via 2^y, FFMA-only
__device__ __forceinline__ float exp20(float s) {
    float y  = s * 28.853900817779268f;
    float fl = floorf(y);
    float f  = y - fl;
    float p = 1.5252733804059840e-05f;
    p = fmaf(p, f, 1.5403530393381609e-04f);
    p = fmaf(p, f, 1.3333558146428443e-03f);
    p = fmaf(p, f, 9.6181291076284772e-03f);
    p = fmaf(p, f, 5.5504108664821580e-02f);
    p = fmaf(p, f, 2.4022650695910071e-01f);
    p = fmaf(p, f, 6.9314718055994531e-01f);
    p = fmaf(p, f, 1.0f);
    int e = (int)fl + 127;
    return p * __int_as_float(e << 23);
}

__device__ __forceinline__ uint32_t smem_u32(const void* p) {
    uint32_t a;
    asm("{ .reg .u64 t; cvta.to.shared.u64 t, %1; cvt.u32.u64 %0, t; }" : "=r"(a) : "l"(p));
    return a;
}
__device__ __forceinline__ void ldmx4(uint32_t* r, uint32_t addr) {
    asm volatile("ldmatrix.sync.aligned.m8n8.x4.shared.b16 {%0,%1,%2,%3}, [%4];"
                 : "=r"(r[0]), "=r"(r[1]), "=r"(r[2]), "=r"(r[3]) : "r"(addr));
}
__device__ __forceinline__ void mma16816(float* d, const uint32_t* a, const uint32_t* b) {
    asm volatile("mma.sync.aligned.m16n8k16.row.col.f32.bf16.bf16.f32 "
                 "{%0,%1,%2,%3}, {%4,%5,%6,%7}, {%8,%9}, {%0,%1,%2,%3};"
                 : "+f"(d[0]), "+f"(d[1]), "+f"(d[2]), "+f"(d[3])
                 : "r"(a[0]), "r"(a[1]), "r"(a[2]), "r"(a[3]), "r"(b[0]), "r"(b[1]));
}
__device__ __forceinline__ uint32_t pack_bf2(__nv_bfloat16 lo, __nv_bfloat16 hi) {
    __nv_bfloat162 t; t.x = lo; t.y = hi;
    uint32_t r; memcpy(&r, &t, 4); return r;
}
__device__ __forceinline__ void split_bf(float x, __nv_bfloat16& h, __nv_bfloat16& l) {
    h = __float2bfloat16_rn(x);
    l = __float2bfloat16_rn(x - __bfloat162float(h));
}
__device__ __forceinline__ void cp_async16(uint32_t smem, const void* g) {
    asm volatile("cp.async.cg.shared.global [%0], [%1], 16;" :: "r"(smem), "l"(g));
}
#define CP_COMMIT() asm volatile("cp.async.commit_group;" ::: "memory")
#define CP_WAIT0()  asm volatile("cp.async.wait_group 0;" ::: "memory")
#define CP_WAIT1()  asm volatile("cp.async.wait_group 1;" ::: "memory")
__device__ __forceinline__ uint32_t mapa_u32(uint32_t a, uint32_t r) {
    uint32_t d;
    asm("mapa.shared::cluster.u32 %0, %1, %2;" : "=r"(d) : "r"(a), "r"(r));
    return d;
}
__device__ __forceinline__ float ld_cluster_f32(uint32_t a) {
    float v;
    asm volatile("ld.shared::cluster.b32 %0, [%1];" : "=f"(v) : "r"(a));
    return v;
}
#define CLUSTER_SYNC() do { \
    asm volatile("barrier.cluster.arrive.aligned;" ::: "memory"); \
    asm volatile("barrier.cluster.wait.aligned;"   ::: "memory"); \
} while (0)

// ---------------- setup ----------------
__global__ void k_proto(const float* __restrict__ p_rgb, const float* __restrict__ p_sn) {
    int gt = blockIdx.x * blockDim.x + threadIdx.x;
    if (gt < 8192) g_csum2[gt] = 0.f;
    if (gt < 32)   g_bs[gt] = 0.f;

    int warp = gt >> 5;
    int lane = threadIdx.x & 31;
    int mod = warp >> 8, row = warp & 255;
    const float* src = (mod ? p_sn : p_rgb) + row * 256;
    float v[8], s = 0.f;
#pragma unroll
    for (int j = 0; j < 8; j++) { v[j] = src[lane + 32 * j]; s += v[j] * v[j]; }
#pragma unroll
    for (int o = 16; o; o >>= 1) s += __shfl_xor_sync(0xffffffffu, s, o);
    float inv = 1.0f / (sqrtf(s) + EPS);
    int base = mod * 65536;
#pragma unroll
    for (int j = 0; j < 8; j++) {
        int col = lane + 32 * j;
        float val = v[j] * inv;
        __nv_bfloat16 h, l;
        split_bf(val, h, l);
        g_pbh[base + row * 256 + col] = h;
        g_pbl[base + row * 256 + col] = l;
        g_pth[base + col * 256 + row] = h;
        g_ptl[base + col * 256 + row] = l;
    }
}

// ---------------- GEMM machinery (round-9/11 proven; N=128 version) ----------------
#define STG   40960
#define GSMEM 81920

#define DO_MMA(sb) do { \
    _Pragma("unroll") \
    for (int ks = 0; ks < 2; ks++) { \
        uint32_t kb = ks * 32; \
        uint32_t aH[2][4], aL[2][4]; \
        ldmx4(aH[0], (sb) + a_off + kb); \
        ldmx4(aH[1], (sb) + a_off + 16 * 80 + kb); \
        ldmx4(aL[0], (sb) + 10240 + a_off + kb); \
        ldmx4(aL[1], (sb) + 10240 + a_off + 16 * 80 + kb); \
        _Pragma("unroll") \
        for (int np = 0; np < 4; np++) { \
            uint32_t bo = b_off + (uint32_t)np * 16 * 80 + kb; \
            uint32_t bH[4], bL[4]; \
            ldmx4(bH, (sb) + 20480 + bo); \
            ldmx4(bL, (sb) + 30720 + bo); \
            _Pragma("unroll") \
            for (int tm = 0; tm < 2; tm++) { \
                mma16816(acc[tm][2 * np],     aH[tm], bH); \
                mma16816(acc[tm][2 * np],     aH[tm], bL); \
                mma16816(acc[tm][2 * np],     aL[tm], bH); \
                mma16816(acc[tm][2 * np + 1], aH[tm], bH + 2); \
                mma16816(acc[tm][2 * np + 1], aH[tm], bL + 2); \
                mma16816(acc[tm][2 * np + 1], aL[tm], bH + 2); \
            } \
        } \
    } \
} while (0)

#define B_CPASYNC(dd, stg_off) do { \
    _Pragma("unroll") \
    for (int i = 0; i < 4; i++) { \
        int idx = t + 256 * i; \
        int part = idx >> 9, row = (idx >> 2) & 127, c8 = idx & 3; \
        const __nv_bfloat16* srcp = (part ? Blp : Bhp) + (size_t)row * 256 + (dd) + 8 * c8; \
        cp_async16(smb + (stg_off) + (part ? 30720 : 20480) + row * 80 + c8 * 16, srcp); \
    } \
    CP_COMMIT(); \
} while (0)

__global__ __launch_bounds__(256, 2)
void k_gemm_sim(const float* __restrict__ f_rgb, const float* __restrict__ f_sn,
                float* __restrict__ out) {
    extern __shared__ char dsm[];
    __shared__ float sSq[128];
    int t = threadIdx.x, l = t & 31, w = t >> 5;
    int wm = w >> 1, wn = w & 1;
    int bx = blockIdx.x;
    int row0 = (bx >> 1) * 128;
    int col0 = (bx & 1) * 128;
    int mod = row0 >> 14, lrow0 = row0 & 16383;
    const float* X = (mod ? f_sn : f_rgb) + (size_t)lrow0 * 256;
    const __nv_bfloat16* Bhp = g_pbh + mod * 65536 + (size_t)col0 * 256;
    const __nv_bfloat16* Blp = g_pbl + mod * 65536 + (size_t)col0 * 256;

    uint32_t smb = smem_u32(dsm);
    uint32_t a_off = (uint32_t)(wm * 32 + (l & 7) + 8 * ((l >> 3) & 1)) * 80
                   + ((l >> 4) & 1) * 16;
    uint32_t b_off = (uint32_t)(wn * 64 + (l & 7) + 8 * ((l >> 4) & 1)) * 80
                   + ((l >> 3) & 1) * 16;

    float acc[2][8][4];
#pragma unroll
    for (int a = 0; a < 2; a++)
#pragma unroll
        for (int b = 0; b < 8; b++)
#pragma unroll
            for (int d = 0; d < 4; d++) acc[a][b][d] = 0.f;
    float ss[4] = {0.f, 0.f, 0.f, 0.f};
    float4 aReg[4];

#pragma unroll
    for (int i = 0; i < 4; i++) {
        int idx = t + 256 * i;
        aReg[i] = *(const float4*)(X + (size_t)(idx >> 3) * 256 + 4 * (idx & 7));
    }
    B_CPASYNC(0, 0);
#pragma unroll
    for (int i = 0; i < 4; i++) {
        int idx = t + 256 * i;
        int row = idx >> 3, c4 = idx & 7;
        float4 v = aReg[i];
        ss[i] += v.x * v.x + v.y * v.y + v.z * v.z + v.w * v.w;
        __nv_bfloat16 hx, lx, hy, ly, hz, lz, hw, lw;
        split_bf(v.x, hx, lx); split_bf(v.y, hy, ly);
        split_bf(v.z, hz, lz); split_bf(v.w, hw, lw);
        uint2 ph, pl;
        ph.x = pack_bf2(hx, hy); ph.y = pack_bf2(hz, hw);
        pl.x = pack_bf2(lx, ly); pl.y = pack_bf2(lz, lw);
        int sob = row * 80 + c4 * 8;
        *(uint2*)(dsm + sob) = ph;
        *(uint2*)(dsm + 10240 + sob) = pl;
    }
    CP_WAIT0();
    __syncthreads();

#pragma unroll 2
    for (int c = 0; c < 8; c++) {
        int buf = c & 1, nbuf = buf ^ 1;
        if (c < 7) {
            int dd = (c + 1) * 32;
#pragma unroll
            for (int i = 0; i < 4; i++) {
                int idx = t + 256 * i;
                aReg[i] = *(const float4*)(X + (size_t)(idx >> 3) * 256 + dd + 4 * (idx & 7));
            }
            B_CPASYNC(dd, nbuf * STG);
        }
        uint32_t sb = smb + buf * STG;
        DO_MMA(sb);
        if (c < 7) {
            char* stg = dsm + nbuf * STG;
#pragma unroll
            for (int i = 0; i < 4; i++) {
                int idx = t + 256 * i;
                int row = idx >> 3, c4 = idx & 7;
                float4 v = aReg[i];
                ss[i] += v.x * v.x + v.y * v.y + v.z * v.z + v.w * v.w;
                __nv_bfloat16 hx, lx, hy, ly, hz, lz, hw, lw;
                split_bf(v.x, hx, lx); split_bf(v.y, hy, ly);
                split_bf(v.z, hz, lz); split_bf(v.w, hw, lw);
                uint2 ph, pl;
                ph.x = pack_bf2(hx, hy); ph.y = pack_bf2(hz, hw);
                pl.x = pack_bf2(lx, ly); pl.y = pack_bf2(lz, lw);
                int sob = row * 80 + c4 * 8;
                *(uint2*)(stg + sob) = ph;
                *(uint2*)(stg + 10240 + sob) = pl;
            }
            CP_WAIT0();
        }
        __syncthreads();
    }

#pragma unroll
    for (int i = 0; i < 4; i++) {
        ss[i] += __shfl_xor_sync(0xffffffffu, ss[i], 1);
        ss[i] += __shfl_xor_sync(0xffffffffu, ss[i], 2);
        ss[i] += __shfl_xor_sync(0xffffffffu, ss[i], 4);
    }
    if ((t & 7) == 0) {
#pragma unroll
        for (int i = 0; i < 4; i++)
            sSq[(t >> 3) + 32 * i] = ss[i];
    }
    __syncthreads();

    float* simb = out + (size_t)(4 + mod) * SEG;
    float psum = 0.f;
#pragma unroll
    for (int tm = 0; tm < 2; tm++) {
        int tr0 = wm * 32 + tm * 16 + (l >> 2);
        int r0 = row0 + tr0, r1 = r0 + 8;
        float xi0 = 1.0f / (sqrtf(sSq[tr0]) + EPS);
        float xi1 = 1.0f / (sqrtf(sSq[tr0 + 8]) + EPS);
        size_t lr0 = (size_t)(r0 & 16383) * 256, lr1 = (size_t)(r1 & 16383) * 256;
        size_t gr0 = (size_t)r0 * 256, gr1 = (size_t)r1 * 256;
#pragma unroll
        for (int nt = 0; nt < 8; nt++) {
            int col = col0 + wn * 64 + nt * 8 + 2 * (l & 3);
            float* d = acc[tm][nt];
            float2 s0 = {d[0] * xi0, d[1] * xi0};
            float2 s1 = {d[2] * xi1, d[3] * xi1};
            *(float2*)(simb + lr0 + col) = s0;
            *(float2*)(simb + lr1 + col) = s1;
            float2 e0 = {exp20(s0.x), exp20(s0.y)};
            float2 e1 = {exp20(s1.x), exp20(s1.y)};
            __nv_bfloat16 h0x, l0x, h0y, l0y, h1x, l1x, h1y, l1y;
            split_bf(e0.x, h0x, l0x); split_bf(e0.y, h0y, l0y);
            split_bf(e1.x, h1x, l1x); split_bf(e1.y, h1y, l1y);
            *(uint32_t*)(g_Mh + gr0 + col) = pack_bf2(h0x, h0y);
            *(uint32_t*)(g_Ml + gr0 + col) = pack_bf2(l0x, l0y);
            *(uint32_t*)(g_Mh + gr1 + col) = pack_bf2(h1x, h1y);
            *(uint32_t*)(g_Ml + gr1 + col) = pack_bf2(l1x, l1y);
            psum += (e0.x + e0.y) + (e1.x + e1.y);
        }
    }
#pragma unroll
    for (int o = 16; o; o >>= 1) psum += __shfl_xor_sync(0xffffffffu, psum, o);
    if (l == 0) atomicAdd(&g_bs[row0 >> 10], psum);
}

// ---------------- fused sinkhorn + final (round-13 proven) ----------------
#define SINK_SMEM 151552

__global__ void __launch_bounds__(512, 1) __cluster_dims__(4, 1, 1)
k_sinkfinal(float* __restrict__ out) {
    extern __shared__ char smraw[];
    __nv_bfloat16* sM = (__nv_bfloat16*)smraw;
    float* su    = (float*)(smraw + 131072);
    float* sv    = (float*)(smraw + 132096);
    float* scolb = (float*)(smraw + 133120);
    float* wbuf  = (float*)(smraw + 135168);
    int t = threadIdx.x, lane = t & 31, w = t >> 5;
    uint32_t rank;
    asm("mov.u32 %0, %%cluster_ctarank;" : "=r"(rank));
    int bm = blockIdx.x >> 2;
    int mod = bm >> 4;
    uint32_t smb = smem_u32(smraw);
    size_t gbase = ((size_t)bm * 1024 + (size_t)rank * 256) * 256;

    const uint4* src = (const uint4*)(g_Mh + gbase);
#pragma unroll
    for (int i = 0; i < 16; i++)
        cp_async16(smb + (t + 512 * i) * 16, src + t + 512 * i);
    CP_COMMIT();

    float u0 = 1.0f / (g_bs[bm] + EPS);
    if (t < 256) { su[t] = u0; sv[t] = 1.0f; }
    CP_WAIT0();
    __syncthreads();

    for (int it = 0; it < 5; it++) {
        float* scol = scolb + (it & 1) * 256;
        uint32_t scol_a = smem_u32(scol);
        float vr[8];
#pragma unroll
        for (int j = 0; j < 8; j++) vr[j] = sv[8 * lane + j];
        float c[8] = {0, 0, 0, 0, 0, 0, 0, 0};
        for (int rr = 0; rr < 16; rr += 2) {
            int row = w * 16 + rr;
            uint4 mv0 = *(const uint4*)(sM + row * 256 + 8 * lane);
            uint4 mv1 = *(const uint4*)(sM + (row + 1) * 256 + 8 * lane);
            float m0[8], m1[8];
            {
                float2 f;
                f = __bfloat1622float2(*(__nv_bfloat162*)&mv0.x); m0[0]=f.x; m0[1]=f.y;
                f = __bfloat1622float2(*(__nv_bfloat162*)&mv0.y); m0[2]=f.x; m0[3]=f.y;
                f = __bfloat1622float2(*(__nv_bfloat162*)&mv0.z); m0[4]=f.x; m0[5]=f.y;
                f = __bfloat1622float2(*(__nv_bfloat162*)&mv0.w); m0[6]=f.x; m0[7]=f.y;
                f = __bfloat1622float2(*(__nv_bfloat162*)&mv1.x); m1[0]=f.x; m1[1]=f.y;
                f = __bfloat1622float2(*(__nv_bfloat162*)&mv1.y); m1[2]=f.x; m1[3]=f.y;
                f = __bfloat1622float2(*(__nv_bfloat162*)&mv1.z); m1[4]=f.x; m1[5]=f.y;
                f = __bfloat1622float2(*(__nv_bfloat162*)&mv1.w); m1[6]=f.x; m1[7]=f.y;
            }
            float d0 = 0.f, d1 = 0.f;
#pragma unroll
            for (int j = 0; j < 8; j++) { d0 = fmaf(m0[j], vr[j], d0); d1 = fmaf(m1[j], vr[j], d1); }
#pragma unroll
            for (int o = 16; o; o >>= 1) {
                d0 += __shfl_xor_sync(0xffffffffu, d0, o);
                d1 += __shfl_xor_sync(0xffffffffu, d1, o);
            }
            float uu0 = su[row], uu1 = su[row + 1];
            float un0 = uu0 * TR / (uu0 * d0 + EPS);
            float un1 = uu1 * TR / (uu1 * d1 + EPS);
            if (lane == 0) { su[row] = un0; su[row + 1] = un1; }
#pragma unroll
            for (int j = 0; j < 8; j++)
                c[j] = fmaf(m0[j], un0, fmaf(m1[j], un1, c[j]));
        }
        *(float4*)&wbuf[w * 256 + 8 * lane]     = *(float4*)&c[0];
        *(float4*)&wbuf[w * 256 + 8 * lane + 4] = *(float4*)&c[4];
        __syncthreads();
        if (t < 256) {
            float tot = 0.f;
#pragma unroll
            for (int ww = 0; ww < 16; ww++) tot += wbuf[ww * 256 + t];
            scol[t] = tot;
        }
        CLUSTER_SYNC();
        if (t < 256) {
            float tot = 0.f;
#pragma unroll
            for (uint32_t r = 0; r < 4; r++)
                tot += ld_cluster_f32(mapa_u32(smem_u32(scol) + 4 * t, r));
            float v = sv[t];
            sv[t] = v * TC / (v * tot + EPS);
        }
        __syncthreads();
    }

    {
        float vr[8];
#pragma unroll
        for (int j = 0; j < 8; j++) vr[j] = sv[8 * lane + j];
        float c[8] = {0, 0, 0, 0, 0, 0, 0, 0};
        int lrow0 = (bm & 15) * 1024 + rank * 256;
        float* aout = out + (size_t)(2 + mod) * SEG + (size_t)lrow0 * 256;
        for (int rr = 0; rr < 16; rr += 2) {
            int row = w * 16 + rr;
            size_t g0 = gbase + (size_t)row * 256 + 8 * lane;
            size_t g1 = g0 + 256;
            uint4 mv0 = *(const uint4*)(sM + row * 256 + 8 * lane);
            uint4 mv1 = *(const uint4*)(sM + (row + 1) * 256 + 8 * lane);
            uint4 lv0 = *(const uint4*)(g_Ml + g0);
            uint4 lv1 = *(const uint4*)(g_Ml + g1);
            float m0[8], m1[8];
            {
                float2 fh, fl;
                fh = __bfloat1622float2(*(__nv_bfloat162*)&mv0.x);
                fl = __bfloat1622float2(*(__nv_bfloat162*)&lv0.x);
                m0[0] = fh.x + fl.x; m0[1] = fh.y + fl.y;
                fh = __bfloat1622float2(*(__nv_bfloat162*)&mv0.y);
                fl = __bfloat1622float2(*(__nv_bfloat162*)&lv0.y);
                m0[2] = fh.x + fl.x; m0[3] = fh.y + fl.y;
                fh = __bfloat1622float2(*(__nv_bfloat162*)&mv0.z);
                fl = __bfloat1622float2(*(__nv_bfloat162*)&lv0.z);
                m0[4] = fh.x + fl.x; m0[5] = fh.y + fl.y;
                fh = __bfloat1622float2(*(__nv_bfloat162*)&mv0.w);
                fl = __bfloat1622float2(*(__nv_bfloat162*)&lv0.w);
                m0[6] = fh.x + fl.x; m0[7] = fh.y + fl.y;
                fh = __bfloat1622float2(*(__nv_bfloat162*)&mv1.x);
                fl = __bfloat1622float2(*(__nv_bfloat162*)&lv1.x);
                m1[0] = fh.x + fl.x; m1[1] = fh.y + fl.y;
                fh = __bfloat1622float2(*(__nv_bfloat162*)&mv1.y);
                fl = __bfloat1622float2(*(__nv_bfloat162*)&lv1.y);
                m1[2] = fh.x + fl.x; m1[3] = fh.y + fl.y;
                fh = __bfloat1622float2(*(__nv_bfloat162*)&mv1.z);
                fl = __bfloat1622float2(*(__nv_bfloat162*)&lv1.z);
                m1[4] = fh.x + fl.x; m1[5] = fh.y + fl.y;
                fh = __bfloat1622float2(*(__nv_bfloat162*)&mv1.w);
                fl = __bfloat1622float2(*(__nv_bfloat162*)&lv1.w);
                m1[6] = fh.x + fl.x; m1[7] = fh.y + fl.y;
            }
            float d0 = 0.f, d1 = 0.f;
#pragma unroll
            for (int j = 0; j < 8; j++) { d0 = fmaf(m0[j], vr[j], d0); d1 = fmaf(m1[j], vr[j], d1); }
#pragma unroll
            for (int o = 16; o; o >>= 1) {
                d0 += __shfl_xor_sync(0xffffffffu, d0, o);
                d1 += __shfl_xor_sync(0xffffffffu, d1, o);
            }
            float uu0 = su[row], uu1 = su[row + 1];
            float un0 = uu0 / (uu0 * d0 + EPS);
            float un1 = uu1 / (uu1 * d1 + EPS);
            float a0[8], a1[8];
            uint4 ah0, al0, ah1, al1;
            uint32_t* ah0p = (uint32_t*)&ah0; uint32_t* al0p = (uint32_t*)&al0;
            uint32_t* ah1p = (uint32_t*)&ah1; uint32_t* al1p = (uint32_t*)&al1;
#pragma unroll
            for (int j = 0; j < 8; j += 2) {
                a0[j] = m0[j] * un0 * vr[j];
                a0[j + 1] = m0[j + 1] * un0 * vr[j + 1];
                a1[j] = m1[j] * un1 * vr[j];
                a1[j + 1] = m1[j + 1] * un1 * vr[j + 1];
                c[j] += a0[j] + a1[j];
                c[j + 1] += a0[j + 1] + a1[j + 1];
                __nv_bfloat16 h0, l0, h1, l1;
                split_bf(a0[j], h0, l0); split_bf(a0[j + 1], h1, l1);
                ah0p[j >> 1] = pack_bf2(h0, h1);
                al0p[j >> 1] = pack_bf2(l0, l1);
                split_bf(a1[j], h0, l0); split_bf(a1[j + 1], h1, l1);
                ah1p[j >> 1] = pack_bf2(h0, h1);
                al1p[j >> 1] = pack_bf2(l0, l1);
            }
            *(float4*)(aout + (size_t)row * 256 + 8 * lane)           = *(float4*)&a0[0];
            *(float4*)(aout + (size_t)row * 256 + 8 * lane + 4)       = *(float4*)&a0[4];
            *(float4*)(aout + (size_t)(row + 1) * 256 + 8 * lane)     = *(float4*)&a1[0];
            *(float4*)(aout + (size_t)(row + 1) * 256 + 8 * lane + 4) = *(float4*)&a1[4];
            *(uint4*)(g_Ah + g0) = ah0;
            *(uint4*)(g_Al + g0) = al0;
            *(uint4*)(g_Ah + g1) = ah1;
            *(uint4*)(g_Al + g1) = al1;
        }
        *(float4*)&wbuf[w * 256 + 8 * lane]     = *(float4*)&c[0];
        *(float4*)&wbuf[w * 256 + 8 * lane + 4] = *(float4*)&c[4];
        __syncthreads();
        if (t < 256) {
            float tot = 0.f;
#pragma unroll
            for (int ww = 0; ww < 16; ww++) tot += wbuf[ww * 256 + t];
            atomicAdd(&g_csum2[bm * 256 + t], tot);
        }
    }
}

// ---------------- k_z: 128x64 tiles, occ 3, pure-load double-buffered ----------------
#define STGZ   30720           // Ah 10240 | Al 10240 | Bh 5120 | Bl 5120
#define GSMEMZ 61440

#define DO_MMA_Z(sb) do { \
    _Pragma("unroll") \
    for (int ks = 0; ks < 2; ks++) { \
        uint32_t kb = ks * 32; \
        uint32_t aH[2][4], aL[2][4]; \
        ldmx4(aH[0], (sb) + a_off + kb); \
        ldmx4(aH[1], (sb) + a_off + 16 * 80 + kb); \
        ldmx4(aL[0], (sb) + 10240 + a_off + kb); \
        ldmx4(aL[1], (sb) + 10240 + a_off + 16 * 80 + kb); \
        _Pragma("unroll") \
        for (int np = 0; np < 2; np++) { \
            uint32_t bo = b_off + (uint32_t)np * 16 * 80 + kb; \
            uint32_t bH[4], bL[4]; \
            ldmx4(bH, (sb) + 20480 + bo); \
            ldmx4(bL, (sb) + 25600 + bo); \
            _Pragma("unroll") \
            for (int tm = 0; tm < 2; tm++) { \
                mma16816(acc[tm][2 * np],     aH[tm], bH); \
                mma16816(acc[tm][2 * np],     aH[tm], bL); \
                mma16816(acc[tm][2 * np],     aL[tm], bH); \
                mma16816(acc[tm][2 * np + 1], aH[tm], bH + 2); \
                mma16816(acc[tm][2 * np + 1], aH[tm], bL + 2); \
                mma16816(acc[tm][2 * np + 1], aL[tm], bH + 2); \
            } \
        } \
    } \
} while (0)

#define LOAD_CHUNK_Z(dd, stg) do { \
    _Pragma("unroll") \
    for (int i = 0; i < 4; i++) { \
        int rem = t + 256 * (i & 1); \
        int row = rem >> 2, c16 = rem & 3; \
        cp_async16(smb + (stg) + (i >> 1) * 10240 + row * 80 + c16 * 16, \
                   partsA[i >> 1] + (size_t)row * 256 + (dd) + c16 * 8); \
    } \
    { \
        int row = t >> 2, c16 = t & 3; \
        cp_async16(smb + (stg) + 20480 + row * 80 + c16 * 16, \
                   partsB[0] + (size_t)row * 256 + (dd) + c16 * 8); \
        cp_async16(smb + (stg) + 25600 + row * 80 + c16 * 16, \
                   partsB[1] + (size_t)row * 256 + (dd) + c16 * 8); \
    } \
    CP_COMMIT(); \
} while (0)

__global__ __launch_bounds__(256, 3)
void k_z(float* __restrict__ out) {
    extern __shared__ char dsm[];
    int t = threadIdx.x, l = t & 31, w = t >> 5;
    int wm = w >> 1, wn = w & 1;
    int bx = blockIdx.x;
    int row0 = (bx >> 2) * 128;
    int col0 = (bx & 3) * 64;
    int mod = row0 >> 14;

    const __nv_bfloat16* partsA[2] = {
        g_Ah + (size_t)row0 * 256,
        g_Al + (size_t)row0 * 256
    };
    const __nv_bfloat16* partsB[2] = {
        g_pth + mod * 65536 + (size_t)col0 * 256,
        g_ptl + mod * 65536 + (size_t)col0 * 256
    };
    uint32_t smb = smem_u32(dsm);
    uint32_t a_off = (uint32_t)(wm * 32 + (l & 7) + 8 * ((l >> 3) & 1)) * 80
                   + ((l >> 4) & 1) * 16;
    uint32_t b_off = (uint32_t)(wn * 32 + (l & 7) + 8 * ((l >> 4) & 1)) * 80
                   + ((l >> 3) & 1) * 16;

    float acc[2][4][4];
#pragma unroll
    for (int a = 0; a < 2; a++)
#pragma unroll
        for (int b = 0; b < 4; b++)
#pragma unroll
            for (int d = 0; d < 4; d++) acc[a][b][d] = 0.f;

    LOAD_CHUNK_Z(0, 0);
    for (int c = 0; c < 8; c++) {
        int buf = c & 1;
        if (c < 7) { LOAD_CHUNK_Z((c + 1) * 32, (buf ^ 1) * STGZ); CP_WAIT1(); }
        else       { CP_WAIT0(); }
        __syncthreads();
        uint32_t sb = smb + buf * STGZ;
        DO_MMA_Z(sb);
        __syncthreads();
    }

    float* zb = out + (size_t)mod * SEG;
#pragma unroll
    for (int tm = 0; tm < 2; tm++) {
        int r0 = row0 + wm * 32 + tm * 16 + (l >> 2);
        size_t lr0 = (size_t)(r0 & 16383) * 256, lr1 = lr0 + 8 * 256;
#pragma unroll
        for (int nt = 0; nt < 4; nt++) {
            int col = col0 + wn * 32 + nt * 8 + 2 * (l & 3);
            float* d = acc[tm][nt];
            float2 v0 = {d[0], d[1]}, v1 = {d[2], d[3]};
            *(float2*)(zb + lr0 + col) = v0;
            *(float2*)(zb + lr1 + col) = v1;
        }
    }

    if (bx == 0) {
        __shared__ float red[8];
        float accs = 0.f;
#pragma unroll
        for (int b = 0; b < 16; b++)
            accs += g_csum2[b * 256 + t] * g_csum2[4096 + b * 256 + t];
#pragma unroll
        for (int o = 16; o; o >>= 1) accs += __shfl_xor_sync(0xffffffffu, accs, o);
        if (l == 0) red[w] = accs;
        __syncthreads();
        if (t == 0) {
            float tot = 0.f;
            for (int i = 0; i < 8; i++) tot += red[i];
            float m = tot * (1.0f / 16777216.0f);
            m = fminf(fmaxf(m, 0.f), 1.f);
            out[(size_t)6 * SEG] = 1.0f - m;
        }
    }
}

// ---------------- launch ----------------
extern "C" void kernel_launch(void* const* d_in, const int* in_sizes, int n_in,
                              void* d_out, int out_size) {
    const float* f_rgb = (const float*)d_in[0];
    const float* f_sn  = (const float*)d_in[1];
    const float* p_rgb = (const float*)d_in[2];
    const float* p_sn  = (const float*)d_in[3];
    float* out = (float*)d_out;

    cudaFuncSetAttribute(k_sinkfinal, cudaFuncAttributeMaxDynamicSharedMemorySize, SINK_SMEM);
    cudaFuncSetAttribute(k_gemm_sim,  cudaFuncAttributeMaxDynamicSharedMemorySize, GSMEM);
    cudaFuncSetAttribute(k_z,         cudaFuncAttributeMaxDynamicSharedMemorySize, GSMEMZ);

    k_proto<<<64, 256>>>(p_rgb, p_sn);
    k_gemm_sim<<<512, 256, GSMEM>>>(f_rgb, f_sn, out);
    k_sinkfinal<<<128, 512, SINK_SMEM>>>(out);
    k_z<<<1024, 256, GSMEMZ>>>(out);
}

// round 15
// speedup vs baseline: 1.6822x; 1.2209x over previous
#include <cuda_runtime.h>
#include <cuda_bf16.h>
#include <cuda_fp16.h>
#include <math.h>
#include <stdint.h>

#define EPS 1e-8f
#define TR  (1.0f/1024.0f)
#define TC  (1.0f/256.0f)
#define SEG 4194304            // 16*1024*256

// ---------------- scratch (device globals; no allocation) ----------------
__device__ __align__(16) __nv_bfloat16 g_Mh[8388608];   // M = exp(sim/tau) hi (bf16: range)
__device__ __align__(16) __nv_bfloat16 g_Ml[8388608];   // M lo
__device__ __align__(16) __half g_Ah[8388608];          // assign hi (fp16)
__device__ __align__(16) __half g_Al[8388608];          // assign lo
__device__ __align__(16) __half g_pb[131072];           // proto normalized fp16 [2][k][d]
__device__ __align__(16) __half g_pt[131072];           // proto^T fp16 [2][d][k]
__device__ float g_csum2[8192];
__device__ float g_bs[32];

// exp(20*s) via 2^y, FFMA-only
__device__ __forceinline__ float exp20(float s) {
    float y  = s * 28.853900817779268f;
    float fl = floorf(y);
    float f  = y - fl;
    float p = 1.5252733804059840e-05f;
    p = fmaf(p, f, 1.5403530393381609e-04f);
    p = fmaf(p, f, 1.3333558146428443e-03f);
    p = fmaf(p, f, 9.6181291076284772e-03f);
    p = fmaf(p, f, 5.5504108664821580e-02f);
    p = fmaf(p, f, 2.4022650695910071e-01f);
    p = fmaf(p, f, 6.9314718055994531e-01f);
    p = fmaf(p, f, 1.0f);
    int e = (int)fl + 127;
    return p * __int_as_float(e << 23);
}

__device__ __forceinline__ uint32_t smem_u32(const void* p) {
    uint32_t a;
    asm("{ .reg .u64 t; cvta.to.shared.u64 t, %1; cvt.u32.u64 %0, t; }" : "=r"(a) : "l"(p));
    return a;
}
__device__ __forceinline__ void ldmx4(uint32_t* r, uint32_t addr) {
    asm volatile("ldmatrix.sync.aligned.m8n8.x4.shared.b16 {%0,%1,%2,%3}, [%4];"
                 : "=r"(r[0]), "=r"(r[1]), "=r"(r[2]), "=r"(r[3]) : "r"(addr));
}
// fp16 MMA, fp32 accumulate
__device__ __forceinline__ void mma16816h(float* d, const uint32_t* a, const uint32_t* b) {
    asm volatile("mma.sync.aligned.m16n8k16.row.col.f32.f16.f16.f32 "
                 "{%0,%1,%2,%3}, {%4,%5,%6,%7}, {%8,%9}, {%0,%1,%2,%3};"
                 : "+f"(d[0]), "+f"(d[1]), "+f"(d[2]), "+f"(d[3])
                 : "r"(a[0]), "r"(a[1]), "r"(a[2]), "r"(a[3]), "r"(b[0]), "r"(b[1]));
}
__device__ __forceinline__ uint32_t pack_bf2(__nv_bfloat16 lo, __nv_bfloat16 hi) {
    __nv_bfloat162 t; t.x = lo; t.y = hi;
    uint32_t r; memcpy(&r, &t, 4); return r;
}
__device__ __forceinline__ uint32_t pack_h2(__half lo, __half hi) {
    __half2 t; t.x = lo; t.y = hi;
    uint32_t r; memcpy(&r, &t, 4); return r;
}
__device__ __forceinline__ void split_bf(float x, __nv_bfloat16& h, __nv_bfloat16& l) {
    h = __float2bfloat16_rn(x);
    l = __float2bfloat16_rn(x - __bfloat162float(h));
}
__device__ __forceinline__ void split_h(float x, __half& h, __half& l) {
    h = __float2half_rn(x);
    l = __float2half_rn(x - __half2float(h));
}
__device__ __forceinline__ void cp_async16(uint32_t smem, const void* g) {
    asm volatile("cp.async.cg.shared.global [%0], [%1], 16;" :: "r"(smem), "l"(g));
}
#define CP_COMMIT() asm volatile("cp.async.commit_group;" ::: "memory")
#define CP_WAIT0()  asm volatile("cp.async.wait_group 0;" ::: "memory")
#define CP_WAIT1()  asm volatile("cp.async.wait_group 1;" ::: "memory")
__device__ __forceinline__ uint32_t mapa_u32(uint32_t a, uint32_t r) {
    uint32_t d;
    asm("mapa.shared::cluster.u32 %0, %1, %2;" : "=r"(d) : "r"(a), "r"(r));
    return d;
}
__device__ __forceinline__ float ld_cluster_f32(uint32_t a) {
    float v;
    asm volatile("ld.shared::cluster.b32 %0, [%1];" : "=f"(v) : "r"(a));
    return v;
}
#define CLUSTER_SYNC() do { \
    asm volatile("barrier.cluster.arrive.aligned;" ::: "memory"); \
    asm volatile("barrier.cluster.wait.aligned;"   ::: "memory"); \
} while (0)

// ---------------- setup ----------------
__global__ void k_proto(const float* __restrict__ p_rgb, const float* __restrict__ p_sn) {
    int gt = blockIdx.x * blockDim.x + threadIdx.x;
    if (gt < 8192) g_csum2[gt] = 0.f;
    if (gt < 32)   g_bs[gt] = 0.f;

    int warp = gt >> 5;
    int lane = threadIdx.x & 31;
    int mod = warp >> 8, row = warp & 255;
    const float* src = (mod ? p_sn : p_rgb) + row * 256;
    float v[8], s = 0.f;
#pragma unroll
    for (int j = 0; j < 8; j++) { v[j] = src[lane + 32 * j]; s += v[j] * v[j]; }
#pragma unroll
    for (int o = 16; o; o >>= 1) s += __shfl_xor_sync(0xffffffffu, s, o);
    float inv = 1.0f / (sqrtf(s) + EPS);
    int base = mod * 65536;
#pragma unroll
    for (int j = 0; j < 8; j++) {
        int col = lane + 32 * j;
        __half h = __float2half_rn(v[j] * inv);
        g_pb[base + row * 256 + col] = h;
        g_pt[base + col * 256 + row] = h;
    }
}

// ---------------- 2-term fp16 GEMM machinery ----------------
// stage: Ah 10240 | Al 10240 | Bh 10240 = 30720
#define STG   30720
#define GSMEM 61440

#define DO_MMA(sb) do { \
    _Pragma("unroll") \
    for (int ks = 0; ks < 2; ks++) { \
        uint32_t kb = ks * 32; \
        uint32_t aH[2][4], aL[2][4]; \
        ldmx4(aH[0], (sb) + a_off + kb); \
        ldmx4(aH[1], (sb) + a_off + 16 * 80 + kb); \
        ldmx4(aL[0], (sb) + 10240 + a_off + kb); \
        ldmx4(aL[1], (sb) + 10240 + a_off + 16 * 80 + kb); \
        _Pragma("unroll") \
        for (int np = 0; np < 4; np++) { \
            uint32_t bo = b_off + (uint32_t)np * 16 * 80 + kb; \
            uint32_t bH[4]; \
            ldmx4(bH, (sb) + 20480 + bo); \
            _Pragma("unroll") \
            for (int tm = 0; tm < 2; tm++) { \
                mma16816h(acc[tm][2 * np],     aH[tm], bH); \
                mma16816h(acc[tm][2 * np],     aL[tm], bH); \
                mma16816h(acc[tm][2 * np + 1], aH[tm], bH + 2); \
                mma16816h(acc[tm][2 * np + 1], aL[tm], bH + 2); \
            } \
        } \
    } \
} while (0)

// B (single fp16 part, 128 rows x 32 cols = 64B/row): 512 x 16B -> 2/thread
#define B_CPASYNC(dd, stg_off) do { \
    _Pragma("unroll") \
    for (int i = 0; i < 2; i++) { \
        int idx = t + 256 * i; \
        int row = idx >> 2, c16 = idx & 3; \
        cp_async16(smb + (stg_off) + 20480 + row * 80 + c16 * 16, \
                   Bhp + (size_t)row * 256 + (dd) + c16 * 8); \
    } \
    CP_COMMIT(); \
} while (0)

// ---------------- GEMM1: sim = Xn @ Pn^T (fp16 2-term) ; Mh/Ml bf16 split ----------------
__global__ __launch_bounds__(256, 2)
void k_gemm_sim(const float* __restrict__ f_rgb, const float* __restrict__ f_sn,
                float* __restrict__ out) {
    extern __shared__ char dsm[];
    __shared__ float sSq[128];
    int t = threadIdx.x, l = t & 31, w = t >> 5;
    int wm = w >> 1, wn = w & 1;
    int bx = blockIdx.x;
    int row0 = (bx >> 1) * 128;
    int col0 = (bx & 1) * 128;
    int mod = row0 >> 14, lrow0 = row0 & 16383;
    const float* X = (mod ? f_sn : f_rgb) + (size_t)lrow0 * 256;
    const __half* Bhp = g_pb + mod * 65536 + (size_t)col0 * 256;

    uint32_t smb = smem_u32(dsm);
    uint32_t a_off = (uint32_t)(wm * 32 + (l & 7) + 8 * ((l >> 3) & 1)) * 80
                   + ((l >> 4) & 1) * 16;
    uint32_t b_off = (uint32_t)(wn * 64 + (l & 7) + 8 * ((l >> 4) & 1)) * 80
                   + ((l >> 3) & 1) * 16;

    float acc[2][8][4];
#pragma unroll
    for (int a = 0; a < 2; a++)
#pragma unroll
        for (int b = 0; b < 8; b++)
#pragma unroll
            for (int d = 0; d < 4; d++) acc[a][b][d] = 0.f;
    float ss[4] = {0.f, 0.f, 0.f, 0.f};
    float4 aReg[4];

#pragma unroll
    for (int i = 0; i < 4; i++) {
        int idx = t + 256 * i;
        aReg[i] = *(const float4*)(X + (size_t)(idx >> 3) * 256 + 4 * (idx & 7));
    }
    B_CPASYNC(0, 0);
#pragma unroll
    for (int i = 0; i < 4; i++) {
        int idx = t + 256 * i;
        int row = idx >> 3, c4 = idx & 7;
        float4 v = aReg[i];
        ss[i] += v.x * v.x + v.y * v.y + v.z * v.z + v.w * v.w;
        __half hx, lx, hy, ly, hz, lz, hw, lw;
        split_h(v.x, hx, lx); split_h(v.y, hy, ly);
        split_h(v.z, hz, lz); split_h(v.w, hw, lw);
        uint2 ph, pl;
        ph.x = pack_h2(hx, hy); ph.y = pack_h2(hz, hw);
        pl.x = pack_h2(lx, ly); pl.y = pack_h2(lz, lw);
        int sob = row * 80 + c4 * 8;
        *(uint2*)(dsm + sob) = ph;
        *(uint2*)(dsm + 10240 + sob) = pl;
    }
    CP_WAIT0();
    __syncthreads();

#pragma unroll 2
    for (int c = 0; c < 8; c++) {
        int buf = c & 1, nbuf = buf ^ 1;
        if (c < 7) {
            int dd = (c + 1) * 32;
#pragma unroll
            for (int i = 0; i < 4; i++) {
                int idx = t + 256 * i;
                aReg[i] = *(const float4*)(X + (size_t)(idx >> 3) * 256 + dd + 4 * (idx & 7));
            }
            B_CPASYNC(dd, nbuf * STG);
        }
        uint32_t sb = smb + buf * STG;
        DO_MMA(sb);
        if (c < 7) {
            char* stg = dsm + nbuf * STG;
#pragma unroll
            for (int i = 0; i < 4; i++) {
                int idx = t + 256 * i;
                int row = idx >> 3, c4 = idx & 7;
                float4 v = aReg[i];
                ss[i] += v.x * v.x + v.y * v.y + v.z * v.z + v.w * v.w;
                __half hx, lx, hy, ly, hz, lz, hw, lw;
                split_h(v.x, hx, lx); split_h(v.y, hy, ly);
                split_h(v.z, hz, lz); split_h(v.w, hw, lw);
                uint2 ph, pl;
                ph.x = pack_h2(hx, hy); ph.y = pack_h2(hz, hw);
                pl.x = pack_h2(lx, ly); pl.y = pack_h2(lz, lw);
                int sob = row * 80 + c4 * 8;
                *(uint2*)(stg + sob) = ph;
                *(uint2*)(stg + 10240 + sob) = pl;
            }
            CP_WAIT0();
        }
        __syncthreads();
    }

#pragma unroll
    for (int i = 0; i < 4; i++) {
        ss[i] += __shfl_xor_sync(0xffffffffu, ss[i], 1);
        ss[i] += __shfl_xor_sync(0xffffffffu, ss[i], 2);
        ss[i] += __shfl_xor_sync(0xffffffffu, ss[i], 4);
    }
    if ((t & 7) == 0) {
#pragma unroll
        for (int i = 0; i < 4; i++)
            sSq[(t >> 3) + 32 * i] = ss[i];
    }
    __syncthreads();

    float* simb = out + (size_t)(4 + mod) * SEG;
    float psum = 0.f;
#pragma unroll
    for (int tm = 0; tm < 2; tm++) {
        int tr0 = wm * 32 + tm * 16 + (l >> 2);
        int r0 = row0 + tr0, r1 = r0 + 8;
        float xi0 = 1.0f / (sqrtf(sSq[tr0]) + EPS);
        float xi1 = 1.0f / (sqrtf(sSq[tr0 + 8]) + EPS);
        size_t lr0 = (size_t)(r0 & 16383) * 256, lr1 = (size_t)(r1 & 16383) * 256;
        size_t gr0 = (size_t)r0 * 256, gr1 = (size_t)r1 * 256;
#pragma unroll
        for (int nt = 0; nt < 8; nt++) {
            int col = col0 + wn * 64 + nt * 8 + 2 * (l & 3);
            float* d = acc[tm][nt];
            float2 s0 = {d[0] * xi0, d[1] * xi0};
            float2 s1 = {d[2] * xi1, d[3] * xi1};
            *(float2*)(simb + lr0 + col) = s0;
            *(float2*)(simb + lr1 + col) = s1;
            float2 e0 = {exp20(s0.x), exp20(s0.y)};
            float2 e1 = {exp20(s1.x), exp20(s1.y)};
            __nv_bfloat16 h0x, l0x, h0y, l0y, h1x, l1x, h1y, l1y;
            split_bf(e0.x, h0x, l0x); split_bf(e0.y, h0y, l0y);
            split_bf(e1.x, h1x, l1x); split_bf(e1.y, h1y, l1y);
            *(uint32_t*)(g_Mh + gr0 + col) = pack_bf2(h0x, h0y);
            *(uint32_t*)(g_Ml + gr0 + col) = pack_bf2(l0x, l0y);
            *(uint32_t*)(g_Mh + gr1 + col) = pack_bf2(h1x, h1y);
            *(uint32_t*)(g_Ml + gr1 + col) = pack_bf2(l1x, l1y);
            psum += (e0.x + e0.y) + (e1.x + e1.y);
        }
    }
#pragma unroll
    for (int o = 16; o; o >>= 1) psum += __shfl_xor_sync(0xffffffffu, psum, o);
    if (l == 0) atomicAdd(&g_bs[row0 >> 10], psum);
}

// ---------------- fused sinkhorn + final (round-13 proven; fp16 assign splits) ----------------
#define SINK_SMEM 151552

__global__ void __launch_bounds__(512, 1) __cluster_dims__(4, 1, 1)
k_sinkfinal(float* __restrict__ out) {
    extern __shared__ char smraw[];
    __nv_bfloat16* sM = (__nv_bfloat16*)smraw;
    float* su    = (float*)(smraw + 131072);
    float* sv    = (float*)(smraw + 132096);
    float* scolb = (float*)(smraw + 133120);
    float* wbuf  = (float*)(smraw + 135168);
    int t = threadIdx.x, lane = t & 31, w = t >> 5;
    uint32_t rank;
    asm("mov.u32 %0, %%cluster_ctarank;" : "=r"(rank));
    int bm = blockIdx.x >> 2;
    int mod = bm >> 4;
    uint32_t smb = smem_u32(smraw);
    size_t gbase = ((size_t)bm * 1024 + (size_t)rank * 256) * 256;

    const uint4* src = (const uint4*)(g_Mh + gbase);
#pragma unroll
    for (int i = 0; i < 16; i++)
        cp_async16(smb + (t + 512 * i) * 16, src + t + 512 * i);
    CP_COMMIT();

    float u0 = 1.0f / (g_bs[bm] + EPS);
    if (t < 256) { su[t] = u0; sv[t] = 1.0f; }
    CP_WAIT0();
    __syncthreads();

    for (int it = 0; it < 5; it++) {
        float* scol = scolb + (it & 1) * 256;
        float vr[8];
#pragma unroll
        for (int j = 0; j < 8; j++) vr[j] = sv[8 * lane + j];
        float c[8] = {0, 0, 0, 0, 0, 0, 0, 0};
        for (int rr = 0; rr < 16; rr += 2) {
            int row = w * 16 + rr;
            uint4 mv0 = *(const uint4*)(sM + row * 256 + 8 * lane);
            uint4 mv1 = *(const uint4*)(sM + (row + 1) * 256 + 8 * lane);
            float m0[8], m1[8];
            {
                float2 f;
                f = __bfloat1622float2(*(__nv_bfloat162*)&mv0.x); m0[0]=f.x; m0[1]=f.y;
                f = __bfloat1622float2(*(__nv_bfloat162*)&mv0.y); m0[2]=f.x; m0[3]=f.y;
                f = __bfloat1622float2(*(__nv_bfloat162*)&mv0.z); m0[4]=f.x; m0[5]=f.y;
                f = __bfloat1622float2(*(__nv_bfloat162*)&mv0.w); m0[6]=f.x; m0[7]=f.y;
                f = __bfloat1622float2(*(__nv_bfloat162*)&mv1.x); m1[0]=f.x; m1[1]=f.y;
                f = __bfloat1622float2(*(__nv_bfloat162*)&mv1.y); m1[2]=f.x; m1[3]=f.y;
                f = __bfloat1622float2(*(__nv_bfloat162*)&mv1.z); m1[4]=f.x; m1[5]=f.y;
                f = __bfloat1622float2(*(__nv_bfloat162*)&mv1.w); m1[6]=f.x; m1[7]=f.y;
            }
            float d0 = 0.f, d1 = 0.f;
#pragma unroll
            for (int j = 0; j < 8; j++) { d0 = fmaf(m0[j], vr[j], d0); d1 = fmaf(m1[j], vr[j], d1); }
#pragma unroll
            for (int o = 16; o; o >>= 1) {
                d0 += __shfl_xor_sync(0xffffffffu, d0, o);
                d1 += __shfl_xor_sync(0xffffffffu, d1, o);
            }
            float uu0 = su[row], uu1 = su[row + 1];
            float un0 = uu0 * TR / (uu0 * d0 + EPS);
            float un1 = uu1 * TR / (uu1 * d1 + EPS);
            if (lane == 0) { su[row] = un0; su[row + 1] = un1; }
#pragma unroll
            for (int j = 0; j < 8; j++)
                c[j] = fmaf(m0[j], un0, fmaf(m1[j], un1, c[j]));
        }
        *(float4*)&wbuf[w * 256 + 8 * lane]     = *(float4*)&c[0];
        *(float4*)&wbuf[w * 256 + 8 * lane + 4] = *(float4*)&c[4];
        __syncthreads();
        if (t < 256) {
            float tot = 0.f;
#pragma unroll
            for (int ww = 0; ww < 16; ww++) tot += wbuf[ww * 256 + t];
            scol[t] = tot;
        }
        CLUSTER_SYNC();
        if (t < 256) {
            float tot = 0.f;
#pragma unroll
            for (uint32_t r = 0; r < 4; r++)
                tot += ld_cluster_f32(mapa_u32(smem_u32(scol) + 4 * t, r));
            float v = sv[t];
            sv[t] = v * TC / (v * tot + EPS);
        }
        __syncthreads();
    }

    {
        float vr[8];
#pragma unroll
        for (int j = 0; j < 8; j++) vr[j] = sv[8 * lane + j];
        float c[8] = {0, 0, 0, 0, 0, 0, 0, 0};
        int lrow0 = (bm & 15) * 1024 + rank * 256;
        float* aout = out + (size_t)(2 + mod) * SEG + (size_t)lrow0 * 256;
        for (int rr = 0; rr < 16; rr += 2) {
            int row = w * 16 + rr;
            size_t g0 = gbase + (size_t)row * 256 + 8 * lane;
            size_t g1 = g0 + 256;
            uint4 mv0 = *(const uint4*)(sM + row * 256 + 8 * lane);
            uint4 mv1 = *(const uint4*)(sM + (row + 1) * 256 + 8 * lane);
            uint4 lv0 = *(const uint4*)(g_Ml + g0);
            uint4 lv1 = *(const uint4*)(g_Ml + g1);
            float m0[8], m1[8];
            {
                float2 fh, fl;
                fh = __bfloat1622float2(*(__nv_bfloat162*)&mv0.x);
                fl = __bfloat1622float2(*(__nv_bfloat162*)&lv0.x);
                m0[0] = fh.x + fl.x; m0[1] = fh.y + fl.y;
                fh = __bfloat1622float2(*(__nv_bfloat162*)&mv0.y);
                fl = __bfloat1622float2(*(__nv_bfloat162*)&lv0.y);
                m0[2] = fh.x + fl.x; m0[3] = fh.y + fl.y;
                fh = __bfloat1622float2(*(__nv_bfloat162*)&mv0.z);
                fl = __bfloat1622float2(*(__nv_bfloat162*)&lv0.z);
                m0[4] = fh.x + fl.x; m0[5] = fh.y + fl.y;
                fh = __bfloat1622float2(*(__nv_bfloat162*)&mv0.w);
                fl = __bfloat1622float2(*(__nv_bfloat162*)&lv0.w);
                m0[6] = fh.x + fl.x; m0[7] = fh.y + fl.y;
                fh = __bfloat1622float2(*(__nv_bfloat162*)&mv1.x);
                fl = __bfloat1622float2(*(__nv_bfloat162*)&lv1.x);
                m1[0] = fh.x + fl.x; m1[1] = fh.y + fl.y;
                fh = __bfloat1622float2(*(__nv_bfloat162*)&mv1.y);
                fl = __bfloat1622float2(*(__nv_bfloat162*)&lv1.y);
                m1[2] = fh.x + fl.x; m1[3] = fh.y + fl.y;
                fh = __bfloat1622float2(*(__nv_bfloat162*)&mv1.z);
                fl = __bfloat1622float2(*(__nv_bfloat162*)&lv1.z);
                m1[4] = fh.x + fl.x; m1[5] = fh.y + fl.y;
                fh = __bfloat1622float2(*(__nv_bfloat162*)&mv1.w);
                fl = __bfloat1622float2(*(__nv_bfloat162*)&lv1.w);
                m1[6] = fh.x + fl.x; m1[7] = fh.y + fl.y;
            }
            float d0 = 0.f, d1 = 0.f;
#pragma unroll
            for (int j = 0; j < 8; j++) { d0 = fmaf(m0[j], vr[j], d0); d1 = fmaf(m1[j], vr[j], d1); }
#pragma unroll
            for (int o = 16; o; o >>= 1) {
                d0 += __shfl_xor_sync(0xffffffffu, d0, o);
                d1 += __shfl_xor_sync(0xffffffffu, d1, o);
            }
            float uu0 = su[row], uu1 = su[row + 1];
            float un0 = uu0 / (uu0 * d0 + EPS);
            float un1 = uu1 / (uu1 * d1 + EPS);
            float a0[8], a1[8];
            uint4 ah0, al0, ah1, al1;
            uint32_t* ah0p = (uint32_t*)&ah0; uint32_t* al0p = (uint32_t*)&al0;
            uint32_t* ah1p = (uint32_t*)&ah1; uint32_t* al1p = (uint32_t*)&al1;
#pragma unroll
            for (int j = 0; j < 8; j += 2) {
                a0[j] = m0[j] * un0 * vr[j];
                a0[j + 1] = m0[j + 1] * un0 * vr[j + 1];
                a1[j] = m1[j] * un1 * vr[j];
                a1[j + 1] = m1[j + 1] * un1 * vr[j + 1];
                c[j] += a0[j] + a1[j];
                c[j + 1] += a0[j + 1] + a1[j + 1];
                __half h0, l0, h1, l1;
                split_h(a0[j], h0, l0); split_h(a0[j + 1], h1, l1);
                ah0p[j >> 1] = pack_h2(h0, h1);
                al0p[j >> 1] = pack_h2(l0, l1);
                split_h(a1[j], h0, l0); split_h(a1[j + 1], h1, l1);
                ah1p[j >> 1] = pack_h2(h0, h1);
                al1p[j >> 1] = pack_h2(l0, l1);
            }
            *(float4*)(aout + (size_t)row * 256 + 8 * lane)           = *(float4*)&a0[0];
            *(float4*)(aout + (size_t)row * 256 + 8 * lane + 4)       = *(float4*)&a0[4];
            *(float4*)(aout + (size_t)(row + 1) * 256 + 8 * lane)     = *(float4*)&a1[0];
            *(float4*)(aout + (size_t)(row + 1) * 256 + 8 * lane + 4) = *(float4*)&a1[4];
            *(uint4*)(g_Ah + g0) = ah0;
            *(uint4*)(g_Al + g0) = al0;
            *(uint4*)(g_Ah + g1) = ah1;
            *(uint4*)(g_Al + g1) = al1;
        }
        *(float4*)&wbuf[w * 256 + 8 * lane]     = *(float4*)&c[0];
        *(float4*)&wbuf[w * 256 + 8 * lane + 4] = *(float4*)&c[4];
        __syncthreads();
        if (t < 256) {
            float tot = 0.f;
#pragma unroll
            for (int ww = 0; ww < 16; ww++) tot += wbuf[ww * 256 + t];
            atomicAdd(&g_csum2[bm * 256 + t], tot);
        }
    }
}

// ---------------- k_z: z = assign @ Phat (fp16 2-term), pure-load ----------------
#define LOAD_CHUNK(dd, stg) do { \
    _Pragma("unroll") \
    for (int i = 0; i < 4; i++) { \
        int part = i >> 1; \
        int rem = t + 256 * (i & 1); \
        int row = rem >> 2, c16 = rem & 3; \
        cp_async16(smb + (stg) + part * 10240 + row * 80 + c16 * 16, \
                   partsA[part] + (size_t)row * 256 + (dd) + c16 * 8); \
    } \
    _Pragma("unroll") \
    for (int i = 0; i < 2; i++) { \
        int rem = t + 256 * i; \
        int row = rem >> 2, c16 = rem & 3; \
        cp_async16(smb + (stg) + 20480 + row * 80 + c16 * 16, \
                   Bhp + (size_t)row * 256 + (dd) + c16 * 8); \
    } \
    CP_COMMIT(); \
} while (0)

__global__ __launch_bounds__(256, 2)
void k_z(float* __restrict__ out) {
    extern __shared__ char dsm[];
    int t = threadIdx.x, l = t & 31, w = t >> 5;
    int wm = w >> 1, wn = w & 1;
    int bx = blockIdx.x;
    int row0 = (bx >> 1) * 128;
    int col0 = (bx & 1) * 128;
    int mod = row0 >> 14;

    const __half* partsA[2] = {
        g_Ah + (size_t)row0 * 256,
        g_Al + (size_t)row0 * 256
    };
    const __half* Bhp = g_pt + mod * 65536 + (size_t)col0 * 256;
    uint32_t smb = smem_u32(dsm);
    uint32_t a_off = (uint32_t)(wm * 32 + (l & 7) + 8 * ((l >> 3) & 1)) * 80
                   + ((l >> 4) & 1) * 16;
    uint32_t b_off = (uint32_t)(wn * 64 + (l & 7) + 8 * ((l >> 4) & 1)) * 80
                   + ((l >> 3) & 1) * 16;

    float acc[2][8][4];
#pragma unroll
    for (int a = 0; a < 2; a++)
#pragma unroll
        for (int b = 0; b < 8; b++)
#pragma unroll
            for (int d = 0; d < 4; d++) acc[a][b][d] = 0.f;

    LOAD_CHUNK(0, 0);
    for (int c = 0; c < 8; c++) {
        int buf = c & 1;
        if (c < 7) { LOAD_CHUNK((c + 1) * 32, (buf ^ 1) * STG); CP_WAIT1(); }
        else       { CP_WAIT0(); }
        __syncthreads();
        uint32_t sb = smb + buf * STG;
        DO_MMA(sb);
        __syncthreads();
    }

    float* zb = out + (size_t)mod * SEG;
#pragma unroll
    for (int tm = 0; tm < 2; tm++) {
        int r0 = row0 + wm * 32 + tm * 16 + (l >> 2);
        size_t lr0 = (size_t)(r0 & 16383) * 256, lr1 = lr0 + 8 * 256;
#pragma unroll
        for (int nt = 0; nt < 8; nt++) {
            int col = col0 + wn * 64 + nt * 8 + 2 * (l & 3);
            float* d = acc[tm][nt];
            float2 v0 = {d[0], d[1]}, v1 = {d[2], d[3]};
            *(float2*)(zb + lr0 + col) = v0;
            *(float2*)(zb + lr1 + col) = v1;
        }
    }

    if (bx == 0) {
        __shared__ float red[8];
        float accs = 0.f;
#pragma unroll
        for (int b = 0; b < 16; b++)
            accs += g_csum2[b * 256 + t] * g_csum2[4096 + b * 256 + t];
#pragma unroll
        for (int o = 16; o; o >>= 1) accs += __shfl_xor_sync(0xffffffffu, accs, o);
        if (l == 0) red[w] = accs;
        __syncthreads();
        if (t == 0) {
            float tot = 0.f;
            for (int i = 0; i < 8; i++) tot += red[i];
            float m = tot * (1.0f / 16777216.0f);
            m = fminf(fmaxf(m, 0.f), 1.f);
            out[(size_t)6 * SEG] = 1.0f - m;
        }
    }
}

// ---------------- launch ----------------
extern "C" void kernel_launch(void* const* d_in, const int* in_sizes, int n_in,
                              void* d_out, int out_size) {
    const float* f_rgb = (const float*)d_in[0];
    const float* f_sn  = (const float*)d_in[1];
    const float* p_rgb = (const float*)d_in[2];
    const float* p_sn  = (const float*)d_in[3];
    float* out = (float*)d_out;

    cudaFuncSetAttribute(k_sinkfinal, cudaFuncAttributeMaxDynamicSharedMemorySize, SINK_SMEM);
    cudaFuncSetAttribute(k_gemm_sim,  cudaFuncAttributeMaxDynamicSharedMemorySize, GSMEM);
    cudaFuncSetAttribute(k_z,         cudaFuncAttributeMaxDynamicSharedMemorySize, GSMEM);

    k_proto<<<64, 256>>>(p_rgb, p_sn);
    k_gemm_sim<<<512, 256, GSMEM>>>(f_rgb, f_sn, out);
    k_sinkfinal<<<128, 512, SINK_SMEM>>>(out);
    k_z<<<512, 256, GSMEM>>>(out);
}

// round 16
// speedup vs baseline: 1.6925x; 1.0061x over previous
#include <cuda_runtime.h>
#include <cuda_bf16.h>
#include <cuda_fp16.h>
#include <math.h>
#include <stdint.h>

#define EPS 1e-8f
#define TR  (1.0f/1024.0f)
#define TC  (1.0f/256.0f)
#define SEG 4194304            // 16*1024*256

// ---------------- scratch (device globals; no allocation) ----------------
__device__ __align__(16) __nv_bfloat16 g_Mh[8388608];   // M = exp(sim/tau) hi (bf16: range)
__device__ __align__(16) __nv_bfloat16 g_Ml[8388608];   // M lo
__device__ __align__(16) __half g_Ah[8388608];          // assign hi (fp16)
__device__ __align__(16) __half g_Al[8388608];          // assign lo
__device__ __align__(16) __half g_pb[131072];           // proto normalized fp16 [2][k][d]
__device__ __align__(16) __half g_pt[131072];           // proto^T fp16 [2][d][k]
__device__ float g_csum2[8192];
__device__ float g_bs[32];

// exp(20*s) via 2^y, FFMA-only
__device__ __forceinline__ float exp20(float s) {
    float y  = s * 28.853900817779268f;
    float fl = floorf(y);
    float f  = y - fl;
    float p = 1.5252733804059840e-05f;
    p = fmaf(p, f, 1.5403530393381609e-04f);
    p = fmaf(p, f, 1.3333558146428443e-03f);
    p = fmaf(p, f, 9.6181291076284772e-03f);
    p = fmaf(p, f, 5.5504108664821580e-02f);
    p = fmaf(p, f, 2.4022650695910071e-01f);
    p = fmaf(p, f, 6.9314718055994531e-01f);
    p = fmaf(p, f, 1.0f);
    int e = (int)fl + 127;
    return p * __int_as_float(e << 23);
}

__device__ __forceinline__ uint32_t smem_u32(const void* p) {
    uint32_t a;
    asm("{ .reg .u64 t; cvta.to.shared.u64 t, %1; cvt.u32.u64 %0, t; }" : "=r"(a) : "l"(p));
    return a;
}
__device__ __forceinline__ void ldmx4(uint32_t* r, uint32_t addr) {
    asm volatile("ldmatrix.sync.aligned.m8n8.x4.shared.b16 {%0,%1,%2,%3}, [%4];"
                 : "=r"(r[0]), "=r"(r[1]), "=r"(r[2]), "=r"(r[3]) : "r"(addr));
}
// fp16 MMA, fp32 accumulate
__device__ __forceinline__ void mma16816h(float* d, const uint32_t* a, const uint32_t* b) {
    asm volatile("mma.sync.aligned.m16n8k16.row.col.f32.f16.f16.f32 "
                 "{%0,%1,%2,%3}, {%4,%5,%6,%7}, {%8,%9}, {%0,%1,%2,%3};"
                 : "+f"(d[0]), "+f"(d[1]), "+f"(d[2]), "+f"(d[3])
                 : "r"(a[0]), "r"(a[1]), "r"(a[2]), "r"(a[3]), "r"(b[0]), "r"(b[1]));
}
__device__ __forceinline__ uint32_t pack_bf2(__nv_bfloat16 lo, __nv_bfloat16 hi) {
    __nv_bfloat162 t; t.x = lo; t.y = hi;
    uint32_t r; memcpy(&r, &t, 4); return r;
}
__device__ __forceinline__ uint32_t pack_h2(__half lo, __half hi) {
    __half2 t; t.x = lo; t.y = hi;
    uint32_t r; memcpy(&r, &t, 4); return r;
}
__device__ __forceinline__ void split_bf(float x, __nv_bfloat16& h, __nv_bfloat16& l) {
    h = __float2bfloat16_rn(x);
    l = __float2bfloat16_rn(x - __bfloat162float(h));
}
__device__ __forceinline__ void split_h(float x, __half& h, __half& l) {
    h = __float2half_rn(x);
    l = __float2half_rn(x - __half2float(h));
}
__device__ __forceinline__ void cp_async16(uint32_t smem, const void* g) {
    asm volatile("cp.async.cg.shared.global [%0], [%1], 16;" :: "r"(smem), "l"(g));
}
#define CP_COMMIT() asm volatile("cp.async.commit_group;" ::: "memory")
#define CP_WAIT0()  asm volatile("cp.async.wait_group 0;" ::: "memory")
#define CP_WAIT1()  asm volatile("cp.async.wait_group 1;" ::: "memory")
__device__ __forceinline__ uint32_t mapa_u32(uint32_t a, uint32_t r) {
    uint32_t d;
    asm("mapa.shared::cluster.u32 %0, %1, %2;" : "=r"(d) : "r"(a), "r"(r));
    return d;
}
__device__ __forceinline__ float ld_cluster_f32(uint32_t a) {
    float v;
    asm volatile("ld.shared::cluster.b32 %0, [%1];" : "=f"(v) : "r"(a));
    return v;
}
#define CLUSTER_SYNC() do { \
    asm volatile("barrier.cluster.arrive.aligned;" ::: "memory"); \
    asm volatile("barrier.cluster.wait.aligned;"   ::: "memory"); \
} while (0)

// ---------------- setup ----------------
__global__ void k_proto(const float* __restrict__ p_rgb, const float* __restrict__ p_sn) {
    int gt = blockIdx.x * blockDim.x + threadIdx.x;
    if (gt < 8192) g_csum2[gt] = 0.f;
    if (gt < 32)   g_bs[gt] = 0.f;

    int warp = gt >> 5;
    int lane = threadIdx.x & 31;
    int mod = warp >> 8, row = warp & 255;
    const float* src = (mod ? p_sn : p_rgb) + row * 256;
    float v[8], s = 0.f;
#pragma unroll
    for (int j = 0; j < 8; j++) { v[j] = src[lane + 32 * j]; s += v[j] * v[j]; }
#pragma unroll
    for (int o = 16; o; o >>= 1) s += __shfl_xor_sync(0xffffffffu, s, o);
    float inv = 1.0f / (sqrtf(s) + EPS);
    int base = mod * 65536;
#pragma unroll
    for (int j = 0; j < 8; j++) {
        int col = lane + 32 * j;
        __half h = __float2half_rn(v[j] * inv);
        g_pb[base + row * 256 + col] = h;
        g_pt[base + col * 256 + row] = h;
    }
}

// ---------------- 2-term fp16 GEMM machinery ----------------
// stage: Ah 10240 | Al 10240 | Bh 10240 = 30720
#define STG   30720
#define GSMEM 61440

#define DO_MMA(sb) do { \
    _Pragma("unroll") \
    for (int ks = 0; ks < 2; ks++) { \
        uint32_t kb = ks * 32; \
        uint32_t aH[2][4], aL[2][4]; \
        ldmx4(aH[0], (sb) + a_off + kb); \
        ldmx4(aH[1], (sb) + a_off + 16 * 80 + kb); \
        ldmx4(aL[0], (sb) + 10240 + a_off + kb); \
        ldmx4(aL[1], (sb) + 10240 + a_off + 16 * 80 + kb); \
        _Pragma("unroll") \
        for (int np = 0; np < 4; np++) { \
            uint32_t bo = b_off + (uint32_t)np * 16 * 80 + kb; \
            uint32_t bH[4]; \
            ldmx4(bH, (sb) + 20480 + bo); \
            _Pragma("unroll") \
            for (int tm = 0; tm < 2; tm++) { \
                mma16816h(acc[tm][2 * np],     aH[tm], bH); \
                mma16816h(acc[tm][2 * np],     aL[tm], bH); \
                mma16816h(acc[tm][2 * np + 1], aH[tm], bH + 2); \
                mma16816h(acc[tm][2 * np + 1], aL[tm], bH + 2); \
            } \
        } \
    } \
} while (0)

// B (single fp16 part, 128 rows x 32 cols = 64B/row): 512 x 16B -> 2/thread
#define B_CPASYNC(dd, stg_off) do { \
    _Pragma("unroll") \
    for (int i = 0; i < 2; i++) { \
        int idx = t + 256 * i; \
        int row = idx >> 2, c16 = idx & 3; \
        cp_async16(smb + (stg_off) + 20480 + row * 80 + c16 * 16, \
                   Bhp + (size_t)row * 256 + (dd) + c16 * 8); \
    } \
    CP_COMMIT(); \
} while (0)

// ---------------- GEMM1: sim = Xn @ Pn^T (fp16 2-term) ; Mh/Ml bf16 split ----------------
__global__ __launch_bounds__(256, 2)
void k_gemm_sim(const float* __restrict__ f_rgb, const float* __restrict__ f_sn,
                float* __restrict__ out) {
    extern __shared__ char dsm[];
    __shared__ float sSq[128];
    int t = threadIdx.x, l = t & 31, w = t >> 5;
    int wm = w >> 1, wn = w & 1;
    int bx = blockIdx.x;
    int row0 = (bx >> 1) * 128;
    int col0 = (bx & 1) * 128;
    int mod = row0 >> 14, lrow0 = row0 & 16383;
    const float* X = (mod ? f_sn : f_rgb) + (size_t)lrow0 * 256;
    const __half* Bhp = g_pb + mod * 65536 + (size_t)col0 * 256;

    uint32_t smb = smem_u32(dsm);
    uint32_t a_off = (uint32_t)(wm * 32 + (l & 7) + 8 * ((l >> 3) & 1)) * 80
                   + ((l >> 4) & 1) * 16;
    uint32_t b_off = (uint32_t)(wn * 64 + (l & 7) + 8 * ((l >> 4) & 1)) * 80
                   + ((l >> 3) & 1) * 16;

    float acc[2][8][4];
#pragma unroll
    for (int a = 0; a < 2; a++)
#pragma unroll
        for (int b = 0; b < 8; b++)
#pragma unroll
            for (int d = 0; d < 4; d++) acc[a][b][d] = 0.f;
    float ss[4] = {0.f, 0.f, 0.f, 0.f};
    float4 aReg[4];

#pragma unroll
    for (int i = 0; i < 4; i++) {
        int idx = t + 256 * i;
        aReg[i] = *(const float4*)(X + (size_t)(idx >> 3) * 256 + 4 * (idx & 7));
    }
    B_CPASYNC(0, 0);
#pragma unroll
    for (int i = 0; i < 4; i++) {
        int idx = t + 256 * i;
        int row = idx >> 3, c4 = idx & 7;
        float4 v = aReg[i];
        ss[i] += v.x * v.x + v.y * v.y + v.z * v.z + v.w * v.w;
        __half hx, lx, hy, ly, hz, lz, hw, lw;
        split_h(v.x, hx, lx); split_h(v.y, hy, ly);
        split_h(v.z, hz, lz); split_h(v.w, hw, lw);
        uint2 ph, pl;
        ph.x = pack_h2(hx, hy); ph.y = pack_h2(hz, hw);
        pl.x = pack_h2(lx, ly); pl.y = pack_h2(lz, lw);
        int sob = row * 80 + c4 * 8;
        *(uint2*)(dsm + sob) = ph;
        *(uint2*)(dsm + 10240 + sob) = pl;
    }
    CP_WAIT0();
    __syncthreads();

#pragma unroll 2
    for (int c = 0; c < 8; c++) {
        int buf = c & 1, nbuf = buf ^ 1;
        if (c < 7) {
            int dd = (c + 1) * 32;
#pragma unroll
            for (int i = 0; i < 4; i++) {
                int idx = t + 256 * i;
                aReg[i] = *(const float4*)(X + (size_t)(idx >> 3) * 256 + dd + 4 * (idx & 7));
            }
            B_CPASYNC(dd, nbuf * STG);
        }
        uint32_t sb = smb + buf * STG;
        DO_MMA(sb);
        if (c < 7) {
            char* stg = dsm + nbuf * STG;
#pragma unroll
            for (int i = 0; i < 4; i++) {
                int idx = t + 256 * i;
                int row = idx >> 3, c4 = idx & 7;
                float4 v = aReg[i];
                ss[i] += v.x * v.x + v.y * v.y + v.z * v.z + v.w * v.w;
                __half hx, lx, hy, ly, hz, lz, hw, lw;
                split_h(v.x, hx, lx); split_h(v.y, hy, ly);
                split_h(v.z, hz, lz); split_h(v.w, hw, lw);
                uint2 ph, pl;
                ph.x = pack_h2(hx, hy); ph.y = pack_h2(hz, hw);
                pl.x = pack_h2(lx, ly); pl.y = pack_h2(lz, lw);
                int sob = row * 80 + c4 * 8;
                *(uint2*)(stg + sob) = ph;
                *(uint2*)(stg + 10240 + sob) = pl;
            }
            CP_WAIT0();
        }
        __syncthreads();
    }

#pragma unroll
    for (int i = 0; i < 4; i++) {
        ss[i] += __shfl_xor_sync(0xffffffffu, ss[i], 1);
        ss[i] += __shfl_xor_sync(0xffffffffu, ss[i], 2);
        ss[i] += __shfl_xor_sync(0xffffffffu, ss[i], 4);
    }
    if ((t & 7) == 0) {
#pragma unroll
        for (int i = 0; i < 4; i++)
            sSq[(t >> 3) + 32 * i] = ss[i];
    }
    __syncthreads();

    float* simb = out + (size_t)(4 + mod) * SEG;
    float psum = 0.f;
#pragma unroll
    for (int tm = 0; tm < 2; tm++) {
        int tr0 = wm * 32 + tm * 16 + (l >> 2);
        int r0 = row0 + tr0, r1 = r0 + 8;
        float xi0 = 1.0f / (sqrtf(sSq[tr0]) + EPS);
        float xi1 = 1.0f / (sqrtf(sSq[tr0 + 8]) + EPS);
        size_t lr0 = (size_t)(r0 & 16383) * 256, lr1 = (size_t)(r1 & 16383) * 256;
        size_t gr0 = (size_t)r0 * 256, gr1 = (size_t)r1 * 256;
#pragma unroll
        for (int nt = 0; nt < 8; nt++) {
            int col = col0 + wn * 64 + nt * 8 + 2 * (l & 3);
            float* d = acc[tm][nt];
            float2 s0 = {d[0] * xi0, d[1] * xi0};
            float2 s1 = {d[2] * xi1, d[3] * xi1};
            *(float2*)(simb + lr0 + col) = s0;
            *(float2*)(simb + lr1 + col) = s1;
            float2 e0 = {exp20(s0.x), exp20(s0.y)};
            float2 e1 = {exp20(s1.x), exp20(s1.y)};
            __nv_bfloat16 h0x, l0x, h0y, l0y, h1x, l1x, h1y, l1y;
            split_bf(e0.x, h0x, l0x); split_bf(e0.y, h0y, l0y);
            split_bf(e1.x, h1x, l1x); split_bf(e1.y, h1y, l1y);
            *(uint32_t*)(g_Mh + gr0 + col) = pack_bf2(h0x, h0y);
            *(uint32_t*)(g_Ml + gr0 + col) = pack_bf2(l0x, l0y);
            *(uint32_t*)(g_Mh + gr1 + col) = pack_bf2(h1x, h1y);
            *(uint32_t*)(g_Ml + gr1 + col) = pack_bf2(l1x, l1y);
            psum += (e0.x + e0.y) + (e1.x + e1.y);
        }
    }
#pragma unroll
    for (int o = 16; o; o >>= 1) psum += __shfl_xor_sync(0xffffffffu, psum, o);
    if (l == 0) atomicAdd(&g_bs[row0 >> 10], psum);
}

// ---------------- fused sinkhorn + final (round-13 proven; fp16 assign splits) ----------------
#define SINK_SMEM 151552

__global__ void __launch_bounds__(512, 1) __cluster_dims__(4, 1, 1)
k_sinkfinal(float* __restrict__ out) {
    extern __shared__ char smraw[];
    __nv_bfloat16* sM = (__nv_bfloat16*)smraw;
    float* su    = (float*)(smraw + 131072);
    float* sv    = (float*)(smraw + 132096);
    float* scolb = (float*)(smraw + 133120);
    float* wbuf  = (float*)(smraw + 135168);
    int t = threadIdx.x, lane = t & 31, w = t >> 5;
    uint32_t rank;
    asm("mov.u32 %0, %%cluster_ctarank;" : "=r"(rank));
    int bm = blockIdx.x >> 2;
    int mod = bm >> 4;
    uint32_t smb = smem_u32(smraw);
    size_t gbase = ((size_t)bm * 1024 + (size_t)rank * 256) * 256;

    const uint4* src = (const uint4*)(g_Mh + gbase);
#pragma unroll
    for (int i = 0; i < 16; i++)
        cp_async16(smb + (t + 512 * i) * 16, src + t + 512 * i);
    CP_COMMIT();

    float u0 = 1.0f / (g_bs[bm] + EPS);
    if (t < 256) { su[t] = u0; sv[t] = 1.0f; }
    CP_WAIT0();
    __syncthreads();

    for (int it = 0; it < 5; it++) {
        float* scol = scolb + (it & 1) * 256;
        float vr[8];
#pragma unroll
        for (int j = 0; j < 8; j++) vr[j] = sv[8 * lane + j];
        float c[8] = {0, 0, 0, 0, 0, 0, 0, 0};
        for (int rr = 0; rr < 16; rr += 2) {
            int row = w * 16 + rr;
            uint4 mv0 = *(const uint4*)(sM + row * 256 + 8 * lane);
            uint4 mv1 = *(const uint4*)(sM + (row + 1) * 256 + 8 * lane);
            float m0[8], m1[8];
            {
                float2 f;
                f = __bfloat1622float2(*(__nv_bfloat162*)&mv0.x); m0[0]=f.x; m0[1]=f.y;
                f = __bfloat1622float2(*(__nv_bfloat162*)&mv0.y); m0[2]=f.x; m0[3]=f.y;
                f = __bfloat1622float2(*(__nv_bfloat162*)&mv0.z); m0[4]=f.x; m0[5]=f.y;
                f = __bfloat1622float2(*(__nv_bfloat162*)&mv0.w); m0[6]=f.x; m0[7]=f.y;
                f = __bfloat1622float2(*(__nv_bfloat162*)&mv1.x); m1[0]=f.x; m1[1]=f.y;
                f = __bfloat1622float2(*(__nv_bfloat162*)&mv1.y); m1[2]=f.x; m1[3]=f.y;
                f = __bfloat1622float2(*(__nv_bfloat162*)&mv1.z); m1[4]=f.x; m1[5]=f.y;
                f = __bfloat1622float2(*(__nv_bfloat162*)&mv1.w); m1[6]=f.x; m1[7]=f.y;
            }
            float d0 = 0.f, d1 = 0.f;
#pragma unroll
            for (int j = 0; j < 8; j++) { d0 = fmaf(m0[j], vr[j], d0); d1 = fmaf(m1[j], vr[j], d1); }
#pragma unroll
            for (int o = 16; o; o >>= 1) {
                d0 += __shfl_xor_sync(0xffffffffu, d0, o);
                d1 += __shfl_xor_sync(0xffffffffu, d1, o);
            }
            float uu0 = su[row], uu1 = su[row + 1];
            float un0 = uu0 * TR / (uu0 * d0 + EPS);
            float un1 = uu1 * TR / (uu1 * d1 + EPS);
            if (lane == 0) { su[row] = un0; su[row + 1] = un1; }
#pragma unroll
            for (int j = 0; j < 8; j++)
                c[j] = fmaf(m0[j], un0, fmaf(m1[j], un1, c[j]));
        }
        *(float4*)&wbuf[w * 256 + 8 * lane]     = *(float4*)&c[0];
        *(float4*)&wbuf[w * 256 + 8 * lane + 4] = *(float4*)&c[4];
        __syncthreads();
        if (t < 256) {
            float tot = 0.f;
#pragma unroll
            for (int ww = 0; ww < 16; ww++) tot += wbuf[ww * 256 + t];
            scol[t] = tot;
        }
        CLUSTER_SYNC();
        if (t < 256) {
            float tot = 0.f;
#pragma unroll
            for (uint32_t r = 0; r < 4; r++)
                tot += ld_cluster_f32(mapa_u32(smem_u32(scol) + 4 * t, r));
            float v = sv[t];
            sv[t] = v * TC / (v * tot + EPS);
        }
        __syncthreads();
    }

    {
        float vr[8];
#pragma unroll
        for (int j = 0; j < 8; j++) vr[j] = sv[8 * lane + j];
        float c[8] = {0, 0, 0, 0, 0, 0, 0, 0};
        int lrow0 = (bm & 15) * 1024 + rank * 256;
        float* aout = out + (size_t)(2 + mod) * SEG + (size_t)lrow0 * 256;
        for (int rr = 0; rr < 16; rr += 2) {
            int row = w * 16 + rr;
            size_t g0 = gbase + (size_t)row * 256 + 8 * lane;
            size_t g1 = g0 + 256;
            uint4 mv0 = *(const uint4*)(sM + row * 256 + 8 * lane);
            uint4 mv1 = *(const uint4*)(sM + (row + 1) * 256 + 8 * lane);
            uint4 lv0 = *(const uint4*)(g_Ml + g0);
            uint4 lv1 = *(const uint4*)(g_Ml + g1);
            float m0[8], m1[8];
            {
                float2 fh, fl;
                fh = __bfloat1622float2(*(__nv_bfloat162*)&mv0.x);
                fl = __bfloat1622float2(*(__nv_bfloat162*)&lv0.x);
                m0[0] = fh.x + fl.x; m0[1] = fh.y + fl.y;
                fh = __bfloat1622float2(*(__nv_bfloat162*)&mv0.y);
                fl = __bfloat1622float2(*(__nv_bfloat162*)&lv0.y);
                m0[2] = fh.x + fl.x; m0[3] = fh.y + fl.y;
                fh = __bfloat1622float2(*(__nv_bfloat162*)&mv0.z);
                fl = __bfloat1622float2(*(__nv_bfloat162*)&lv0.z);
                m0[4] = fh.x + fl.x; m0[5] = fh.y + fl.y;
                fh = __bfloat1622float2(*(__nv_bfloat162*)&mv0.w);
                fl = __bfloat1622float2(*(__nv_bfloat162*)&lv0.w);
                m0[6] = fh.x + fl.x; m0[7] = fh.y + fl.y;
                fh = __bfloat1622float2(*(__nv_bfloat162*)&mv1.x);
                fl = __bfloat1622float2(*(__nv_bfloat162*)&lv1.x);
                m1[0] = fh.x + fl.x; m1[1] = fh.y + fl.y;
                fh = __bfloat1622float2(*(__nv_bfloat162*)&mv1.y);
                fl = __bfloat1622float2(*(__nv_bfloat162*)&lv1.y);
                m1[2] = fh.x + fl.x; m1[3] = fh.y + fl.y;
                fh = __bfloat1622float2(*(__nv_bfloat162*)&mv1.z);
                fl = __bfloat1622float2(*(__nv_bfloat162*)&lv1.z);
                m1[4] = fh.x + fl.x; m1[5] = fh.y + fl.y;
                fh = __bfloat1622float2(*(__nv_bfloat162*)&mv1.w);
                fl = __bfloat1622float2(*(__nv_bfloat162*)&lv1.w);
                m1[6] = fh.x + fl.x; m1[7] = fh.y + fl.y;
            }
            float d0 = 0.f, d1 = 0.f;
#pragma unroll
            for (int j = 0; j < 8; j++) { d0 = fmaf(m0[j], vr[j], d0); d1 = fmaf(m1[j], vr[j], d1); }
#pragma unroll
            for (int o = 16; o; o >>= 1) {
                d0 += __shfl_xor_sync(0xffffffffu, d0, o);
                d1 += __shfl_xor_sync(0xffffffffu, d1, o);
            }
            float uu0 = su[row], uu1 = su[row + 1];
            float un0 = uu0 / (uu0 * d0 + EPS);
            float un1 = uu1 / (uu1 * d1 + EPS);
            float a0[8], a1[8];
            uint4 ah0, al0, ah1, al1;
            uint32_t* ah0p = (uint32_t*)&ah0; uint32_t* al0p = (uint32_t*)&al0;
            uint32_t* ah1p = (uint32_t*)&ah1; uint32_t* al1p = (uint32_t*)&al1;
#pragma unroll
            for (int j = 0; j < 8; j += 2) {
                a0[j] = m0[j] * un0 * vr[j];
                a0[j + 1] = m0[j + 1] * un0 * vr[j + 1];
                a1[j] = m1[j] * un1 * vr[j];
                a1[j + 1] = m1[j + 1] * un1 * vr[j + 1];
                c[j] += a0[j] + a1[j];
                c[j + 1] += a0[j + 1] + a1[j + 1];
                __half h0, l0, h1, l1;
                split_h(a0[j], h0, l0); split_h(a0[j + 1], h1, l1);
                ah0p[j >> 1] = pack_h2(h0, h1);
                al0p[j >> 1] = pack_h2(l0, l1);
                split_h(a1[j], h0, l0); split_h(a1[j + 1], h1, l1);
                ah1p[j >> 1] = pack_h2(h0, h1);
                al1p[j >> 1] = pack_h2(l0, l1);
            }
            *(float4*)(aout + (size_t)row * 256 + 8 * lane)           = *(float4*)&a0[0];
            *(float4*)(aout + (size_t)row * 256 + 8 * lane + 4)       = *(float4*)&a0[4];
            *(float4*)(aout + (size_t)(row + 1) * 256 + 8 * lane)     = *(float4*)&a1[0];
            *(float4*)(aout + (size_t)(row + 1) * 256 + 8 * lane + 4) = *(float4*)&a1[4];
            *(uint4*)(g_Ah + g0) = ah0;
            *(uint4*)(g_Al + g0) = al0;
            *(uint4*)(g_Ah + g1) = ah1;
            *(uint4*)(g_Al + g1) = al1;
        }
        *(float4*)&wbuf[w * 256 + 8 * lane]     = *(float4*)&c[0];
        *(float4*)&wbuf[w * 256 + 8 * lane + 4] = *(float4*)&c[4];
        __syncthreads();
        if (t < 256) {
            float tot = 0.f;
#pragma unroll
            for (int ww = 0; ww < 16; ww++) tot += wbuf[ww * 256 + t];
            atomicAdd(&g_csum2[bm * 256 + t], tot);
        }
    }
}

// ---------------- k_z: z = assign @ Phat (fp16 2-term), pure-load ----------------
#define LOAD_CHUNK(dd, stg) do { \
    _Pragma("unroll") \
    for (int i = 0; i < 4; i++) { \
        int part = i >> 1; \
        int rem = t + 256 * (i & 1); \
        int row = rem >> 2, c16 = rem & 3; \
        cp_async16(smb + (stg) + part * 10240 + row * 80 + c16 * 16, \
                   partsA[part] + (size_t)row * 256 + (dd) + c16 * 8); \
    } \
    _Pragma("unroll") \
    for (int i = 0; i < 2; i++) { \
        int rem = t + 256 * i; \
        int row = rem >> 2, c16 = rem & 3; \
        cp_async16(smb + (stg) + 20480 + row * 80 + c16 * 16, \
                   Bhp + (size_t)row * 256 + (dd) + c16 * 8); \
    } \
    CP_COMMIT(); \
} while (0)

__global__ __launch_bounds__(256, 2)
void k_z(float* __restrict__ out) {
    extern __shared__ char dsm[];
    int t = threadIdx.x, l = t & 31, w = t >> 5;
    int wm = w >> 1, wn = w & 1;
    int bx = blockIdx.x;
    int row0 = (bx >> 1) * 128;
    int col0 = (bx & 1) * 128;
    int mod = row0 >> 14;

    const __half* partsA[2] = {
        g_Ah + (size_t)row0 * 256,
        g_Al + (size_t)row0 * 256
    };
    const __half* Bhp = g_pt + mod * 65536 + (size_t)col0 * 256;
    uint32_t smb = smem_u32(dsm);
    uint32_t a_off = (uint32_t)(wm * 32 + (l & 7) + 8 * ((l >> 3) & 1)) * 80
                   + ((l >> 4) & 1) * 16;
    uint32_t b_off = (uint32_t)(wn * 64 + (l & 7) + 8 * ((l >> 4) & 1)) * 80
                   + ((l >> 3) & 1) * 16;

    float acc[2][8][4];
#pragma unroll
    for (int a = 0; a < 2; a++)
#pragma unroll
        for (int b = 0; b < 8; b++)
#pragma unroll
            for (int d = 0; d < 4; d++) acc[a][b][d] = 0.f;

    LOAD_CHUNK(0, 0);
    for (int c = 0; c < 8; c++) {
        int buf = c & 1;
        if (c < 7) { LOAD_CHUNK((c + 1) * 32, (buf ^ 1) * STG); CP_WAIT1(); }
        else       { CP_WAIT0(); }
        __syncthreads();
        uint32_t sb = smb + buf * STG;
        DO_MMA(sb);
        __syncthreads();
    }

    float* zb = out + (size_t)mod * SEG;
#pragma unroll
    for (int tm = 0; tm < 2; tm++) {
        int r0 = row0 + wm * 32 + tm * 16 + (l >> 2);
        size_t lr0 = (size_t)(r0 & 16383) * 256, lr1 = lr0 + 8 * 256;
#pragma unroll
        for (int nt = 0; nt < 8; nt++) {
            int col = col0 + wn * 64 + nt * 8 + 2 * (l & 3);
            float* d = acc[tm][nt];
            float2 v0 = {d[0], d[1]}, v1 = {d[2], d[3]};
            *(float2*)(zb + lr0 + col) = v0;
            *(float2*)(zb + lr1 + col) = v1;
        }
    }

    if (bx == 0) {
        __shared__ float red[8];
        float accs = 0.f;
#pragma unroll
        for (int b = 0; b < 16; b++)
            accs += g_csum2[b * 256 + t] * g_csum2[4096 + b * 256 + t];
#pragma unroll
        for (int o = 16; o; o >>= 1) accs += __shfl_xor_sync(0xffffffffu, accs, o);
        if (l == 0) red[w] = accs;
        __syncthreads();
        if (t == 0) {
            float tot = 0.f;
            for (int i = 0; i < 8; i++) tot += red[i];
            float m = tot * (1.0f / 16777216.0f);
            m = fminf(fmaxf(m, 0.f), 1.f);
            out[(size_t)6 * SEG] = 1.0f - m;
        }
    }
}

// ---------------- launch ----------------
extern "C" void kernel_launch(void* const* d_in, const int* in_sizes, int n_in,
                              void* d_out, int out_size) {
    const float* f_rgb = (const float*)d_in[0];
    const float* f_sn  = (const float*)d_in[1];
    const float* p_rgb = (const float*)d_in[2];
    const float* p_sn  = (const float*)d_in[3];
    float* out = (float*)d_out;

    cudaFuncSetAttribute(k_sinkfinal, cudaFuncAttributeMaxDynamicSharedMemorySize, SINK_SMEM);
    cudaFuncSetAttribute(k_gemm_sim,  cudaFuncAttributeMaxDynamicSharedMemorySize, GSMEM);
    cudaFuncSetAttribute(k_z,         cudaFuncAttributeMaxDynamicSharedMemorySize, GSMEM);

    k_proto<<<64, 256>>>(p_rgb, p_sn);
    k_gemm_sim<<<512, 256, GSMEM>>>(f_rgb, f_sn, out);
    k_sinkfinal<<<128, 512, SINK_SMEM>>>(out);
    k_z<<<512, 256, GSMEM>>>(out);
}